// round 11
// baseline (speedup 1.0000x reference)
#include <cuda_runtime.h>
#include <cuda.h>
#include <cuda_bf16.h>
#include <math.h>
#include <stdint.h>

#define N_TOK   4096
#define D_MODEL 512
#define N_HEADS 8
#define HEAD_DIM 64
#define NBINS_C 512
#define CAND_C  64
#define QCAP    512
#define IN_ELEMS (N_TOK * D_MODEL)
#define W_ELEMS  (D_MODEL * D_MODEL)
#define EPI_STRIDE 132   // multiple of 4 -> float4-aligned rows

// Compile-time feature gate: tcgen05 is only legal in arch-specific passes.
#if defined(__CUDA_ARCH__)
#if defined(__CUDA_ARCH_FEAT_SM103_ALL) || defined(__CUDA_ARCH_FEAT_SM100_ALL)
#define HAS_TCGEN05 1
#elif defined(__CUDA_ARCH_SPECIFIC__) && (__CUDA_ARCH__ >= 1000)
#define HAS_TCGEN05 1
#elif defined(__CUDA_ARCH_FAMILY_SPECIFIC__) && (__CUDA_ARCH__ >= 1000)
#define HAS_TCGEN05 1
#else
#define HAS_TCGEN05 0
#endif
#else
#define HAS_TCGEN05 0
#endif

// ---------------- scratch (device globals: allocation-free) ----------------
static __device__ float g_Q[N_HEADS * N_TOK * HEAD_DIM];   // [h][n][d], projected
static __device__ float g_K[N_HEADS * N_TOK * HEAD_DIM];
static __device__ float g_V[N_HEADS * N_TOK * HEAD_DIM];
static __device__ int   g_qb[N_HEADS * N_TOK];
static __device__ int   g_kb[N_HEADS * N_TOK];
static __device__ short g_cand[N_HEADS * NBINS_C * CAND_C];
static __device__ int   g_cnt[N_HEADS * NBINS_C];

// query buckets per (head, bin)
static __device__ int   g_qcnt[N_HEADS * NBINS_C];
static __device__ short g_qlist[N_HEADS * NBINS_C * QCAP];

// bf16 split operands
static __device__ __align__(1024) __nv_bfloat16 g_INhi[3 * IN_ELEMS];
static __device__ __align__(1024) __nv_bfloat16 g_INlo[3 * IN_ELEMS];
static __device__ __align__(1024) __nv_bfloat16 g_Whi[4 * W_ELEMS];
static __device__ __align__(1024) __nv_bfloat16 g_Wlo[4 * W_ELEMS];
static __device__ __align__(1024) __nv_bfloat16 g_AOhi[IN_ELEMS];
static __device__ __align__(1024) __nv_bfloat16 g_AOlo[IN_ELEMS];

// exact fp32 bin coordinates: [token][2*h + {0,1}]
static __device__ float g_Cq[N_TOK * 16];
static __device__ float g_Ck[N_TOK * 16];

// ---------------- PTX helpers ------------------------------------------------
__device__ __forceinline__ uint32_t smem_u32(const void* p) {
    uint32_t a;
    asm("{ .reg .u64 t; cvta.to.shared.u64 t, %1; cvt.u32.u64 %0, t; }"
        : "=r"(a) : "l"(p));
    return a;
}

#define SW128(x) ((x) ^ (((x) >> 3) & 0x70))

#if HAS_TCGEN05
__device__ __forceinline__ uint32_t elect_one() {
    uint32_t pred;
    asm volatile("{\n\t.reg .pred p;\n\telect.sync _|p, 0xFFFFFFFF;\n\t"
                 "selp.b32 %0, 1, 0, p;\n\t}" : "=r"(pred));
    return pred;
}

#define MBAR_INIT(a, c) \
    asm volatile("mbarrier.init.shared.b64 [%0], %1;" :: "r"(a), "r"(c) : "memory")

#define MBAR_EXPECT_TX(a, bytes) \
    asm volatile("mbarrier.arrive.expect_tx.shared.b64 _, [%0], %1;" \
                 :: "r"(a), "r"(bytes) : "memory")

#define MBAR_WAIT(a, ph) do {                                                   \
    asm volatile("{\n\t.reg .pred P1;\n\t"                                      \
        "WL_%=:\n\t"                                                            \
        "mbarrier.try_wait.parity.acquire.cta.shared::cta.b64 P1, [%0], %1, 0x989680;\n\t" \
        "@P1 bra.uni WD_%=;\n\t"                                                \
        "bra.uni WL_%=;\n\t"                                                    \
        "WD_%=:\n\t}"                                                           \
        :: "r"(a), "r"(ph) : "memory");                                         \
} while (0)

#define TMA3(smem, mapref, x, y, z, mb) \
    asm volatile("cp.async.bulk.tensor.3d.shared::cta.global.tile.mbarrier::complete_tx::bytes " \
        "[%0], [%1, {%2, %3, %4}], [%5];" \
        :: "r"(smem), "l"(&(mapref)), "r"(x), "r"(y), "r"(z), "r"(mb) : "memory")

__device__ __forceinline__ void mma_f16_ss(uint32_t d, uint64_t a, uint64_t b,
                                           uint32_t idesc, uint32_t en) {
    asm volatile("{\n\t.reg .pred p;\n\tsetp.ne.u32 p, %5, 0;\n\t"
        "tcgen05.mma.cta_group::1.kind::f16 [%0], %1, %2, %3, {%4,%4,%4,%4}, p;\n\t}"
        :: "r"(d), "l"(a), "l"(b), "r"(idesc), "r"(0u), "r"(en) : "memory");
}

// SW128 K-major smem descriptor (layout=2, version=1, SBO=64, LBO=1)
__device__ __forceinline__ uint64_t mk_desc(uint32_t addr) {
    const uint64_t base = (uint64_t(2) << 61) | (uint64_t(1) << 46)
                        | (uint64_t(64) << 32) | (uint64_t(1) << 16);
    return base | ((uint64_t)(addr >> 4) & 0x3FFF);
}

// idesc: f32 accum, bf16 a/b, M=128, N=128
#define IDESC_F16_128x128 0x8200490u
#else
// ---- legacy mma.sync helpers (fallback path) ----
#define LDSM4(R, ptr) do {                                                     \
    unsigned _a = (unsigned)__cvta_generic_to_shared(ptr);                     \
    asm volatile("ldmatrix.sync.aligned.m8n8.x4.shared.b16 {%0,%1,%2,%3}, [%4];" \
        : "=r"((R)[0]), "=r"((R)[1]), "=r"((R)[2]), "=r"((R)[3]) : "r"(_a));   \
} while (0)

#define MMA16816(C, A, B0, B1)                                                 \
    asm volatile("mma.sync.aligned.m16n8k16.row.col.f32.bf16.bf16.f32 "       \
        "{%0,%1,%2,%3},{%4,%5,%6,%7},{%8,%9},{%0,%1,%2,%3};"                  \
        : "+f"((C)[0]), "+f"((C)[1]), "+f"((C)[2]), "+f"((C)[3])              \
        : "r"((A)[0]), "r"((A)[1]), "r"((A)[2]), "r"((A)[3]),                 \
          "r"(B0), "r"(B1))
#endif

// ---------------- merged split fp32 -> bf16 hi/lo (+ qcnt zeroing) -----------
__global__ __launch_bounds__(256)
void split_all(const float* __restrict__ q, const float* __restrict__ k,
               const float* __restrict__ v, const float* __restrict__ wq,
               const float* __restrict__ wk, const float* __restrict__ wv,
               const float* __restrict__ wo)
{
    const int bid = blockIdx.x;
    if (bid < 16) g_qcnt[bid * 256 + threadIdx.x] = 0;   // fused zero_qcnt
    const float* src;
    __nv_bfloat16 *hi, *lo;
    int i4;
    if (bid < 6144) {
        const int z = bid >> 11;
        src = (z == 0) ? q : (z == 1) ? k : v;
        hi = g_INhi + (size_t)z * IN_ELEMS;
        lo = g_INlo + (size_t)z * IN_ELEMS;
        i4 = (bid & 2047) * 256 + threadIdx.x;
    } else {
        const int z = (bid - 6144) >> 8;
        src = (z == 0) ? wq : (z == 1) ? wk : (z == 2) ? wv : wo;
        hi = g_Whi + (size_t)z * W_ELEMS;
        lo = g_Wlo + (size_t)z * W_ELEMS;
        i4 = ((bid - 6144) & 255) * 256 + threadIdx.x;
    }
    float4 val = ((const float4*)src)[i4];
    __nv_bfloat16 h0 = __float2bfloat16(val.x);
    __nv_bfloat16 h1 = __float2bfloat16(val.y);
    __nv_bfloat16 h2 = __float2bfloat16(val.z);
    __nv_bfloat16 h3 = __float2bfloat16(val.w);
    __nv_bfloat16 l0 = __float2bfloat16(val.x - __bfloat162float(h0));
    __nv_bfloat16 l1 = __float2bfloat16(val.y - __bfloat162float(h1));
    __nv_bfloat16 l2 = __float2bfloat16(val.z - __bfloat162float(h2));
    __nv_bfloat16 l3 = __float2bfloat16(val.w - __bfloat162float(h3));
    uint2 hp, lp;
    hp.x = (unsigned)__bfloat16_as_ushort(h0) | ((unsigned)__bfloat16_as_ushort(h1) << 16);
    hp.y = (unsigned)__bfloat16_as_ushort(h2) | ((unsigned)__bfloat16_as_ushort(h3) << 16);
    lp.x = (unsigned)__bfloat16_as_ushort(l0) | ((unsigned)__bfloat16_as_ushort(l1) << 16);
    lp.y = (unsigned)__bfloat16_as_ushort(l2) | ((unsigned)__bfloat16_as_ushort(l3) << 16);
    *(uint2*)(hi + 4 * (size_t)i4) = hp;
    *(uint2*)(lo + 4 * (size_t)i4) = lp;
}

// ---------------- exact fp32 bin-coordinate GEMM -----------------------------
__global__ __launch_bounds__(256)
void bincoord_kernel(const float* __restrict__ q, const float* __restrict__ k,
                     const float* __restrict__ Wq, const float* __restrict__ Wk,
                     const float* __restrict__ bq, const float* __restrict__ bk)
{
    __shared__ float Ws[16][512];
    __shared__ float bs[16];
    const int z = blockIdx.y;
    const float* A = z ? k : q;
    const float* W = z ? Wk : Wq;
    const float* bias = z ? bk : bq;
    float* out = z ? g_Ck : g_Cq;

    for (int i = threadIdx.x; i < 16 * 512; i += 256) {
        int j = i >> 9, kk = i & 511;
        int wrow = (j >> 1) * 64 + (j & 1);
        Ws[j][kk] = W[(size_t)wrow * 512 + kk];
    }
    if (threadIdx.x < 16) {
        int j = threadIdx.x;
        bs[j] = bias[(j >> 1) * 64 + (j & 1)];
    }
    __syncthreads();

    const int token = blockIdx.x * 256 + threadIdx.x;
    float acc[16];
#pragma unroll
    for (int j = 0; j < 16; j++) acc[j] = 0.f;
    const float4* Ar = (const float4*)(A + (size_t)token * 512);
    for (int kk = 0; kk < 128; kk++) {
        float4 a = Ar[kk];
#pragma unroll
        for (int j = 0; j < 16; j++) {
            acc[j] = fmaf(a.x, Ws[j][4 * kk + 0], acc[j]);
            acc[j] = fmaf(a.y, Ws[j][4 * kk + 1], acc[j]);
            acc[j] = fmaf(a.z, Ws[j][4 * kk + 2], acc[j]);
            acc[j] = fmaf(a.w, Ws[j][4 * kk + 3], acc[j]);
        }
    }
#pragma unroll
    for (int j = 0; j < 16; j++) out[(size_t)token * 16 + j] = acc[j] + bs[j];
}

// ---------------- GEMM: C = A*W^T + bias (3-term bf16 split) ----------------
// tcgen05 + TMA. Tiles: M=256 (two M=128 TMEM accumulators), N=128,
// K chunks of 64, depth-2 pipeline (A 64KB + W 32KB per stage).
template <int MODE>
__global__ __launch_bounds__(256)
void tc_gemm(const __grid_constant__ CUtensorMap tAhi,
             const __grid_constant__ CUtensorMap tAlo,
             const __grid_constant__ CUtensorMap tWhi,
             const __grid_constant__ CUtensorMap tWlo,
             const float* __restrict__ b0, const float* __restrict__ b1,
             const float* __restrict__ b2, float* __restrict__ outp)
{
    extern __shared__ __align__(1024) char smem[];
    const int tid = threadIdx.x;
    const int wid = tid >> 5;
    const int lid = tid & 31;

    const int z = blockIdx.z;
    const float* bias;
    float* outQ;
    if (MODE == 0) {
        bias = (z == 0) ? b0 : (z == 1) ? b1 : b2;
        outQ = (z == 0) ? g_Q : (z == 1) ? g_K : g_V;
    } else {
        bias = b0;
        outQ = outp;
    }
    const int m0 = blockIdx.x * 256;
    const int n0 = blockIdx.y * 128;

#if HAS_TCGEN05
    const int zA = (MODE == 0) ? z : 0;
    const int zW = (MODE == 0) ? z : 3;
    const uint32_t sb = smem_u32(smem);
    // smem: [0] tmem ptr, [8..40) 4 mbars, 2 buffers of 96KB at 1024
    const uint32_t bufB = sb + 1024;

    if (wid == 0) {
        asm volatile("tcgen05.alloc.cta_group::1.sync.aligned.shared::cta.b32 [%0], %1;"
                     :: "r"(sb), "r"(256u) : "memory");
        asm volatile("tcgen05.relinquish_alloc_permit.cta_group::1.sync.aligned;");
    }
    if (tid == 0) {
        MBAR_INIT(sb + 8, 1);  MBAR_INIT(sb + 16, 1);   // data mbars
        MBAR_INIT(sb + 24, 1); MBAR_INIT(sb + 32, 1);   // mma mbars
    }
    __syncthreads();
    uint32_t tmem;
    asm volatile("ld.shared.b32 %0, [%1];" : "=r"(tmem) : "r"(sb));

    if (wid == 0 && elect_one()) {
        const uint32_t dmb[2] = { sb + 8, sb + 16 };
        const uint32_t mmb[2] = { sb + 24, sb + 32 };

        auto stage = [&](int b, int chunk) {
            const uint32_t bb = bufB + (uint32_t)b * 98304;
            MBAR_EXPECT_TX(dmb[b], 98304u);
            TMA3(bb,         tAhi, chunk * 64, m0, zA, dmb[b]);   // 32KB (256 rows)
            TMA3(bb + 32768, tAlo, chunk * 64, m0, zA, dmb[b]);   // 32KB
            TMA3(bb + 65536, tWhi, chunk * 64, n0, zW, dmb[b]);   // 16KB
            TMA3(bb + 81920, tWlo, chunk * 64, n0, zW, dmb[b]);   // 16KB
        };

        stage(0, 0);
        stage(1, 1);
        int dph[2] = {0, 0}, mph[2] = {0, 0};

        for (int c = 0; c < 8; c++) {
            const int b = c & 1;
            MBAR_WAIT(dmb[b], dph[b]); dph[b] ^= 1;
            const uint32_t bb = bufB + (uint32_t)b * 98304;
            const uint64_t dAh = mk_desc(bb);
            const uint64_t dAl = mk_desc(bb + 32768);
            const uint64_t dBh = mk_desc(bb + 65536);
            const uint64_t dBl = mk_desc(bb + 81920);
#pragma unroll
            for (int k16 = 0; k16 < 4; k16++) {
                const uint64_t o = k16 * 2;
#pragma unroll
                for (int half = 0; half < 2; half++) {
                    const uint32_t d = tmem + half * 128;
                    const uint64_t ao = (uint64_t)half * 1024 + o;  // +16KB A rows 128..255
                    mma_f16_ss(d, dAh + ao, dBh + o, IDESC_F16_128x128,
                               (c == 0 && k16 == 0) ? 0u : 1u);
                    mma_f16_ss(d, dAh + ao, dBl + o, IDESC_F16_128x128, 1u);
                    mma_f16_ss(d, dAl + ao, dBh + o, IDESC_F16_128x128, 1u);
                }
            }
            asm volatile(
                "tcgen05.commit.cta_group::1.mbarrier::arrive::one.shared::cluster.b64 [%0];"
                :: "r"(mmb[b]) : "memory");
            if (c + 2 < 8) {
                MBAR_WAIT(mmb[b], mph[b]); mph[b] ^= 1;   // this chunk's MMAs done
                stage(b, c + 2);
            }
        }
        MBAR_WAIT(mmb[0], mph[0]); mph[0] ^= 1;   // chunk 6
        MBAR_WAIT(mmb[1], mph[1]); mph[1] ^= 1;   // chunk 7
    }
    __syncthreads();
    asm volatile("tcgen05.fence::after_thread_sync;" ::: "memory");

    // ---- epilogue: two 128-row halves, TMEM -> smem tile -> coalesced stores
    float* sT = (float*)(smem + 1024);
    for (int half = 0; half < 2; half++) {
        {
            const int trow = (wid & 3) * 32 + lid;
            const int cbase = (wid >> 2) * 64;
#pragma unroll
            for (int cb = 0; cb < 64; cb += 32) {
                uint32_t r[32];
                asm volatile(
                    "tcgen05.ld.sync.aligned.32x32b.x32.b32 "
                    "{%0,%1,%2,%3,%4,%5,%6,%7,%8,%9,%10,%11,%12,%13,%14,%15,"
                    "%16,%17,%18,%19,%20,%21,%22,%23,%24,%25,%26,%27,%28,%29,%30,%31}, [%32];"
                    : "=r"(r[0]), "=r"(r[1]), "=r"(r[2]), "=r"(r[3]),
                      "=r"(r[4]), "=r"(r[5]), "=r"(r[6]), "=r"(r[7]),
                      "=r"(r[8]), "=r"(r[9]), "=r"(r[10]), "=r"(r[11]),
                      "=r"(r[12]), "=r"(r[13]), "=r"(r[14]), "=r"(r[15]),
                      "=r"(r[16]), "=r"(r[17]), "=r"(r[18]), "=r"(r[19]),
                      "=r"(r[20]), "=r"(r[21]), "=r"(r[22]), "=r"(r[23]),
                      "=r"(r[24]), "=r"(r[25]), "=r"(r[26]), "=r"(r[27]),
                      "=r"(r[28]), "=r"(r[29]), "=r"(r[30]), "=r"(r[31])
                    : "r"(tmem + half * 128 + cbase + cb));
                asm volatile("tcgen05.wait::ld.sync.aligned;" ::: "memory");
#pragma unroll
                for (int j = 0; j < 32; j++)
                    sT[trow * EPI_STRIDE + cbase + cb + j] = __uint_as_float(r[j]);
            }
        }
        __syncthreads();
        const int mbase = m0 + half * 128;
        for (int i = tid; i < 128 * 32; i += 256) {
            const int row = i >> 5;
            const int col = (i & 31) * 4;
            float4 v = *(float4*)&sT[row * EPI_STRIDE + col];
            const int gcol = n0 + col;
            const float4 bb4 = *(const float4*)&bias[gcol];
            v.x += bb4.x; v.y += bb4.y; v.z += bb4.z; v.w += bb4.w;
            if (MODE == 0) {
                const int h = gcol >> 6, dd = gcol & 63;
                *(float4*)&outQ[((size_t)((h << 12) + mbase + row)) * 64 + dd] = v;
            } else {
                *(float4*)&outQ[(size_t)(mbase + row) * 512 + gcol] = v;
            }
        }
        __syncthreads();
    }
    if (wid == 0) {
        asm volatile("tcgen05.dealloc.cta_group::1.sync.aligned.b32 %0, %1;"
                     :: "r"(tmem), "r"(256u));
    }
#else
    // ---- fallback: mma.sync m16n8k16 bf16 (Round-2 layout), two 128-row halves
    const __nv_bfloat16 *Ahi, *Alo, *Whi, *Wlo;
    if (MODE == 0) {
        Ahi = g_INhi + (size_t)z * IN_ELEMS;
        Alo = g_INlo + (size_t)z * IN_ELEMS;
        Whi = g_Whi + (size_t)z * W_ELEMS;
        Wlo = g_Wlo + (size_t)z * W_ELEMS;
    } else {
        Ahi = g_AOhi; Alo = g_AOlo;
        Whi = g_Whi + (size_t)3 * W_ELEMS;
        Wlo = g_Wlo + (size_t)3 * W_ELEMS;
    }
    unsigned short* As = (unsigned short*)smem;             // [128][64]
    unsigned short* Bs = (unsigned short*)(smem + 16384);   // [128][64]
    const int wm = wid >> 1;
    const int wn = wid & 1;

    for (int mh = 0; mh < 2; mh++) {
        const int m0h = m0 + mh * 128;
        float acc[2][8][4];
#pragma unroll
        for (int a = 0; a < 2; a++)
#pragma unroll
            for (int b = 0; b < 8; b++)
#pragma unroll
                for (int c = 0; c < 4; c++) acc[a][b][c] = 0.f;

        for (int kt = 0; kt < D_MODEL; kt += 32) {
#pragma unroll
            for (int i = 0; i < 8; i++) {
                const int cid = tid + i * 256;
                const int which = cid >> 9;
                const int r = (cid >> 2) & 127;
                const int kc = cid & 3;
                const __nv_bfloat16* base =
                    (which == 0) ? Ahi : (which == 1) ? Alo : (which == 2) ? Whi : Wlo;
                const int grow = ((which < 2) ? m0h : n0) + r;
                uint4 v = *(const uint4*)(base + (size_t)grow * 512 + kt + kc * 8);
                unsigned short* db = (which < 2) ? As : Bs;
                const int sc = (kc + ((which & 1) << 2)) ^ (r & 7);
                *(uint4*)(db + r * 64 + sc * 8) = v;
            }
            __syncthreads();

#pragma unroll
            for (int k16 = 0; k16 < 2; k16++) {
                unsigned ah[2][4], al[2][4], bh[4][4], bl[4][4];
#pragma unroll
                for (int mi = 0; mi < 2; mi++) {
                    const int r = wm * 32 + mi * 16 + (lid & 15);
                    const int kc = 2 * k16 + (lid >> 4);
                    LDSM4(ah[mi], As + r * 64 + ((kc) ^ (r & 7)) * 8);
                    LDSM4(al[mi], As + r * 64 + ((kc + 4) ^ (r & 7)) * 8);
                }
#pragma unroll
                for (int p = 0; p < 4; p++) {
                    const int r = wn * 64 + p * 16 + ((lid >> 4) << 3) + (lid & 7);
                    const int kc = 2 * k16 + ((lid >> 3) & 1);
                    LDSM4(bh[p], Bs + r * 64 + ((kc) ^ (r & 7)) * 8);
                    LDSM4(bl[p], Bs + r * 64 + ((kc + 4) ^ (r & 7)) * 8);
                }
#pragma unroll
                for (int mi = 0; mi < 2; mi++)
#pragma unroll
                    for (int nj = 0; nj < 8; nj++) {
                        const int p = nj >> 1, o = (nj & 1) * 2;
                        MMA16816(acc[mi][nj], ah[mi], bh[p][o], bh[p][o + 1]);
                        MMA16816(acc[mi][nj], ah[mi], bl[p][o], bl[p][o + 1]);
                        MMA16816(acc[mi][nj], al[mi], bh[p][o], bh[p][o + 1]);
                    }
            }
            __syncthreads();
        }

#pragma unroll
        for (int mi = 0; mi < 2; mi++)
#pragma unroll
            for (int nj = 0; nj < 8; nj++) {
                const int row = m0h + wm * 32 + mi * 16 + (lid >> 2);
                const int col = n0 + wn * 64 + nj * 8 + (lid & 3) * 2;
                const float bx = bias[col], by = bias[col + 1];
                float2 v0 = make_float2(acc[mi][nj][0] + bx, acc[mi][nj][1] + by);
                float2 v1 = make_float2(acc[mi][nj][2] + bx, acc[mi][nj][3] + by);
                if (MODE == 0) {
                    const int h = col >> 6, d = col & 63;
                    *(float2*)&outQ[((size_t)((h << 12) + row)) * 64 + d] = v0;
                    *(float2*)&outQ[((size_t)((h << 12) + row + 8)) * 64 + d] = v1;
                } else {
                    *(float2*)&outQ[(size_t)row * 512 + col] = v0;
                    *(float2*)&outQ[(size_t)(row + 8) * 512 + col] = v1;
                }
            }
    }
#endif
}

// ---------------- projection (Poincare clip) + geometric binning -------------
__global__ __launch_bounds__(256)
void projbin_kernel()
{
    const int lane = threadIdx.x & 31;
    const int w    = blockIdx.x * 8 + (threadIdx.x >> 5);  // h*N_TOK + n
    float* X = (blockIdx.y == 0) ? g_Q : g_K;
    const float* C = (blockIdx.y == 0) ? g_Cq : g_Ck;
    int* bins = (blockIdx.y == 0) ? g_qb : g_kb;

    float* row = X + (size_t)w * HEAD_DIM;
    const float x0 = row[lane];
    const float x1 = row[lane + 32];
    float ss = x0 * x0 + x1 * x1;
#pragma unroll
    for (int o = 16; o; o >>= 1) ss += __shfl_xor_sync(0xffffffffu, ss, o);
    const float nrm = sqrtf(ss);
    const float s = fminf(1.0f, 0.99999f / fmaxf(nrm, 1e-12f));
    row[lane] = x0 * s;
    row[lane + 32] = x1 * s;

    if (lane == 0) {
        const int n = w & (N_TOK - 1);
        const int h = w >> 12;
        const float c0 = C[(size_t)n * 16 + 2 * h];
        const float c1 = C[(size_t)n * 16 + 2 * h + 1];
        float ang = atan2f(c1, c0);
        float t = (ang / 6.28318530717958647692f + 0.5f) * 512.0f;
        if (fabsf(t - rintf(t)) < 4e-3f) {
            ang = (float)atan2((double)c1, (double)c0);
            t = (ang / 6.28318530717958647692f + 0.5f) * 512.0f;
        }
        int b = (int)floorf(t);
        b = (b < 0) ? 0 : ((b > NBINS_C - 1) ? NBINS_C - 1 : b);
        bins[w] = b;
        if (blockIdx.y == 0) {
            const int hb = (h << 9) + b;
            const int idx = atomicAdd(&g_qcnt[hb], 1);
            if (idx < QCAP) g_qlist[(size_t)hb * QCAP + idx] = (short)n;
        }
    }
}

// ---------------- candidate lists per (head, bin) ---------------------------
__global__ __launch_bounds__(256)
void cand_kernel()
{
    __shared__ short kbs[N_TOK];
    const int h    = blockIdx.x >> 6;
    const int bin0 = (blockIdx.x & 63) * 8;
    for (int i = threadIdx.x; i < N_TOK; i += 256)
        kbs[i] = (short)g_kb[h * N_TOK + i];
    __syncthreads();

    const int warp = threadIdx.x >> 5;
    const int lane = threadIdx.x & 31;
    const int b = bin0 + warp;
    short* dst = g_cand + ((size_t)h * NBINS_C + b) * CAND_C;

    int cnt = 0;
    for (int k0 = 0; k0 < N_TOK; k0 += 32) {
        const int kv = (int)kbs[k0 + lane];
        const int d = kv - b;
        const bool pred = (d >= -1) && (d <= 1);
        const unsigned bal = __ballot_sync(0xffffffffu, pred);
        const int rank = __popc(bal & ((1u << lane) - 1u));
        if (pred && (cnt + rank) < CAND_C) dst[cnt + rank] = (short)(k0 + lane);
        cnt += __popc(bal);
        if (cnt >= CAND_C) { cnt = CAND_C; break; }
    }
    if (lane == 0) g_cnt[h * NBINS_C + b] = cnt;
}

// ---------------- bucketed sparse attention ----------------------------------
__global__ __launch_bounds__(256)
void attn_kernel()
{
    __shared__ float Ks[CAND_C * 68];
    __shared__ float Vs[CAND_C * 68];
    __shared__ float qs[8][64];
    __shared__ float ws[8][64];
    __shared__ short cl[CAND_C];

    const int hb = blockIdx.x;
    int nq = g_qcnt[hb];
    if (nq == 0) return;
    if (nq > QCAP) nq = QCAP;

    const int h = hb >> 9;
    const int tid = threadIdx.x;
    const int wid = tid >> 5;
    const int lane = tid & 31;

    const int cnt = g_cnt[hb];
    const int c = (cnt == 0) ? CAND_C : cnt;
    if (tid < CAND_C) {
        short v = (short)tid;
        if (cnt > 0) v = (tid < cnt) ? g_cand[(size_t)hb * CAND_C + tid] : (short)0;
        cl[tid] = v;
    }
    __syncthreads();

    for (int i = tid; i < c * 16; i += 256) {
        const int r = i >> 4, seg = i & 15;
        const size_t gro = ((size_t)(h << 12) + cl[r]) * 64 + seg * 4;
        *(float4*)&Ks[r * 68 + seg * 4] = *(const float4*)&g_K[gro];
        *(float4*)&Vs[r * 68 + seg * 4] = *(const float4*)&g_V[gro];
    }
    __syncthreads();

    for (int qi = wid; qi < nq; qi += 8) {
        const int q = (int)g_qlist[(size_t)hb * QCAP + qi];
        const float* qrow = g_Q + ((size_t)(h << 12) + q) * 64;
        qs[wid][lane] = qrow[lane];
        qs[wid][lane + 32] = qrow[lane + 32];
        __syncwarp();

        float s0 = -INFINITY, s1 = -INFINITY;
        {
            float a0 = 0.f, a1 = 0.f;
            const bool v0 = (lane < c), v1 = (lane + 32 < c);
#pragma unroll
            for (int d4 = 0; d4 < 16; d4++) {
                const float4 qv = *(const float4*)&qs[wid][d4 * 4];
                if (v0) {
                    const float4 kv = *(const float4*)&Ks[lane * 68 + d4 * 4];
                    a0 = fmaf(qv.x, kv.x, a0); a0 = fmaf(qv.y, kv.y, a0);
                    a0 = fmaf(qv.z, kv.z, a0); a0 = fmaf(qv.w, kv.w, a0);
                }
                if (v1) {
                    const float4 kv = *(const float4*)&Ks[(lane + 32) * 68 + d4 * 4];
                    a1 = fmaf(qv.x, kv.x, a1); a1 = fmaf(qv.y, kv.y, a1);
                    a1 = fmaf(qv.z, kv.z, a1); a1 = fmaf(qv.w, kv.w, a1);
                }
            }
            if (v0) s0 = a0 * 0.125f;
            if (v1) s1 = a1 * 0.125f;
        }

        float m = fmaxf(s0, s1);
#pragma unroll
        for (int o = 16; o; o >>= 1) m = fmaxf(m, __shfl_xor_sync(0xffffffffu, m, o));
        const float e0 = expf(s0 - m);
        const float e1 = expf(s1 - m);
        float ssum = e0 + e1;
#pragma unroll
        for (int o = 16; o; o >>= 1) ssum += __shfl_xor_sync(0xffffffffu, ssum, o);
        const float inv = 1.0f / ssum;
        ws[wid][lane] = e0 * inv;
        ws[wid][lane + 32] = e1 * inv;
        __syncwarp();

        float a0 = 0.f, a1 = 0.f;
        for (int c2 = 0; c2 < c; c2++) {
            const float wv = ws[wid][c2];
            a0 = fmaf(wv, Vs[c2 * 68 + lane], a0);
            a1 = fmaf(wv, Vs[c2 * 68 + lane + 32], a1);
        }

        const int ch = (h << 6) + lane;
        __nv_bfloat16 h0 = __float2bfloat16(a0);
        __nv_bfloat16 h1 = __float2bfloat16(a1);
        g_AOhi[(size_t)q * 512 + ch]      = h0;
        g_AOhi[(size_t)q * 512 + ch + 32] = h1;
        g_AOlo[(size_t)q * 512 + ch]      = __float2bfloat16(a0 - __bfloat162float(h0));
        g_AOlo[(size_t)q * 512 + ch + 32] = __float2bfloat16(a1 - __bfloat162float(h1));
    }
}

// ---------------- host: tensor-map construction ------------------------------
typedef CUresult (*PFN_encodeTiled)(
    CUtensorMap*, CUtensorMapDataType, cuuint32_t, void*,
    const cuuint64_t*, const cuuint64_t*, const cuuint32_t*, const cuuint32_t*,
    CUtensorMapInterleave, CUtensorMapSwizzle, CUtensorMapL2promotion,
    CUtensorMapFloatOOBfill);

static PFN_encodeTiled get_encoder()
{
    static PFN_encodeTiled fn = nullptr;
    if (!fn) {
        void* p = nullptr;
        cudaDriverEntryPointQueryResult st;
        cudaGetDriverEntryPoint("cuTensorMapEncodeTiled", &p,
                                cudaEnableDefault, &st);
        fn = (PFN_encodeTiled)p;
    }
    return fn;
}

static void make_map(CUtensorMap* m, void* ptr, uint64_t d0, uint64_t d1,
                     uint64_t d2, uint32_t bx, uint32_t by)
{
    cuuint64_t dims[3] = { d0, d1, d2 };
    cuuint64_t strides[2] = { d0 * 2, d0 * d1 * 2 };
    cuuint32_t box[3] = { bx, by, 1 };
    cuuint32_t es[3] = { 1, 1, 1 };
    get_encoder()(m, CU_TENSOR_MAP_DATA_TYPE_BFLOAT16, 3, ptr,
                  dims, strides, box, es,
                  CU_TENSOR_MAP_INTERLEAVE_NONE, CU_TENSOR_MAP_SWIZZLE_128B,
                  CU_TENSOR_MAP_L2_PROMOTION_L2_128B,
                  CU_TENSOR_MAP_FLOAT_OOB_FILL_NONE);
}

// ---------------- launch -----------------------------------------------------
extern "C" void kernel_launch(void* const* d_in, const int* in_sizes, int n_in,
                              void* d_out, int out_size)
{
    const float* query = (const float*)d_in[0];
    const float* key   = (const float*)d_in[1];
    const float* value = (const float*)d_in[2];
    const float* Wq    = (const float*)d_in[3];
    const float* bq    = (const float*)d_in[4];
    const float* Wk    = (const float*)d_in[5];
    const float* bk    = (const float*)d_in[6];
    const float* Wv    = (const float*)d_in[7];
    const float* bv    = (const float*)d_in[8];
    const float* Wo    = (const float*)d_in[9];
    const float* bo    = (const float*)d_in[10];
    float* out = (float*)d_out;

    const int SMEM_GEMM = 1024 + 2 * 98304;   // 197632 bytes
    static int attr_done = 0;
    if (!attr_done) {
        cudaFuncSetAttribute(tc_gemm<0>, cudaFuncAttributeMaxDynamicSharedMemorySize, SMEM_GEMM);
        cudaFuncSetAttribute(tc_gemm<1>, cudaFuncAttributeMaxDynamicSharedMemorySize, SMEM_GEMM);
        attr_done = 1;
    }

    void *p_inhi, *p_inlo, *p_whi, *p_wlo, *p_aohi, *p_aolo;
    cudaGetSymbolAddress(&p_inhi, g_INhi);
    cudaGetSymbolAddress(&p_inlo, g_INlo);
    cudaGetSymbolAddress(&p_whi,  g_Whi);
    cudaGetSymbolAddress(&p_wlo,  g_Wlo);
    cudaGetSymbolAddress(&p_aohi, g_AOhi);
    cudaGetSymbolAddress(&p_aolo, g_AOlo);

    CUtensorMap tInHi, tInLo, tWHi, tWLo, tAoHi, tAoLo;
    make_map(&tInHi, p_inhi, 512, 4096, 3, 64, 256);
    make_map(&tInLo, p_inlo, 512, 4096, 3, 64, 256);
    make_map(&tWHi,  p_whi,  512, 512,  4, 64, 128);
    make_map(&tWLo,  p_wlo,  512, 512,  4, 64, 128);
    make_map(&tAoHi, p_aohi, 512, 4096, 1, 64, 256);
    make_map(&tAoLo, p_aolo, 512, 4096, 1, 64, 256);

    split_all<<<7168, 256>>>(query, key, value, Wq, Wk, Wv, Wo);
    bincoord_kernel<<<dim3(16, 2), 256>>>(query, key, Wq, Wk, bq, bk);
    tc_gemm<0><<<dim3(16, 4, 3), 256, SMEM_GEMM>>>(tInHi, tInLo, tWHi, tWLo,
                                                   bq, bk, bv, nullptr);
    projbin_kernel<<<dim3(4096, 2), 256>>>();
    cand_kernel<<<512, 256>>>();
    attn_kernel<<<4096, 256>>>();
    tc_gemm<1><<<dim3(16, 4, 1), 256, SMEM_GEMM>>>(tAoHi, tAoLo, tWHi, tWLo,
                                                   bo, nullptr, nullptr, out);
}

// round 12
// speedup vs baseline: 1.0832x; 1.0832x over previous
#include <cuda_runtime.h>
#include <cuda.h>
#include <cuda_bf16.h>
#include <math.h>
#include <stdint.h>

#define N_TOK   4096
#define D_MODEL 512
#define N_HEADS 8
#define HEAD_DIM 64
#define NBINS_C 512
#define CAND_C  64
#define QCAP    512
#define IN_ELEMS (N_TOK * D_MODEL)
#define W_ELEMS  (D_MODEL * D_MODEL)
#define EPI_STRIDE 132   // multiple of 4 -> float4-aligned rows

// Compile-time feature gate: tcgen05 is only legal in arch-specific passes.
#if defined(__CUDA_ARCH__)
#if defined(__CUDA_ARCH_FEAT_SM103_ALL) || defined(__CUDA_ARCH_FEAT_SM100_ALL)
#define HAS_TCGEN05 1
#elif defined(__CUDA_ARCH_SPECIFIC__) && (__CUDA_ARCH__ >= 1000)
#define HAS_TCGEN05 1
#elif defined(__CUDA_ARCH_FAMILY_SPECIFIC__) && (__CUDA_ARCH__ >= 1000)
#define HAS_TCGEN05 1
#else
#define HAS_TCGEN05 0
#endif
#else
#define HAS_TCGEN05 0
#endif

// ---------------- scratch (device globals: allocation-free) ----------------
static __device__ float g_Q[N_HEADS * N_TOK * HEAD_DIM];   // [h][n][d], projected
static __device__ float g_K[N_HEADS * N_TOK * HEAD_DIM];
static __device__ float g_V[N_HEADS * N_TOK * HEAD_DIM];
static __device__ int   g_kb[N_HEADS * N_TOK];
static __device__ short g_cand[N_HEADS * NBINS_C * CAND_C];
static __device__ int   g_cnt[N_HEADS * NBINS_C];

// query buckets per (head, bin)
static __device__ int   g_qcnt[N_HEADS * NBINS_C];
static __device__ short g_qlist[N_HEADS * NBINS_C * QCAP];

// bf16 split operands
static __device__ __align__(1024) __nv_bfloat16 g_INhi[3 * IN_ELEMS];
static __device__ __align__(1024) __nv_bfloat16 g_INlo[3 * IN_ELEMS];
static __device__ __align__(1024) __nv_bfloat16 g_Whi[4 * W_ELEMS];
static __device__ __align__(1024) __nv_bfloat16 g_Wlo[4 * W_ELEMS];
static __device__ __align__(1024) __nv_bfloat16 g_AOhi[IN_ELEMS];
static __device__ __align__(1024) __nv_bfloat16 g_AOlo[IN_ELEMS];

// exact fp32 bin coordinates: [token][2*h + {0,1}]
static __device__ float g_Cq[N_TOK * 16];
static __device__ float g_Ck[N_TOK * 16];

// ---------------- PTX helpers ------------------------------------------------
__device__ __forceinline__ uint32_t smem_u32(const void* p) {
    uint32_t a;
    asm("{ .reg .u64 t; cvta.to.shared.u64 t, %1; cvt.u32.u64 %0, t; }"
        : "=r"(a) : "l"(p));
    return a;
}

#define SW128(x) ((x) ^ (((x) >> 3) & 0x70))

#if HAS_TCGEN05
__device__ __forceinline__ uint32_t elect_one() {
    uint32_t pred;
    asm volatile("{\n\t.reg .pred p;\n\telect.sync _|p, 0xFFFFFFFF;\n\t"
                 "selp.b32 %0, 1, 0, p;\n\t}" : "=r"(pred));
    return pred;
}

#define MBAR_INIT(a, c) \
    asm volatile("mbarrier.init.shared.b64 [%0], %1;" :: "r"(a), "r"(c) : "memory")

#define MBAR_EXPECT_TX(a, bytes) \
    asm volatile("mbarrier.arrive.expect_tx.shared.b64 _, [%0], %1;" \
                 :: "r"(a), "r"(bytes) : "memory")

#define MBAR_WAIT(a, ph) do {                                                   \
    asm volatile("{\n\t.reg .pred P1;\n\t"                                      \
        "WL_%=:\n\t"                                                            \
        "mbarrier.try_wait.parity.acquire.cta.shared::cta.b64 P1, [%0], %1, 0x989680;\n\t" \
        "@P1 bra.uni WD_%=;\n\t"                                                \
        "bra.uni WL_%=;\n\t"                                                    \
        "WD_%=:\n\t}"                                                           \
        :: "r"(a), "r"(ph) : "memory");                                         \
} while (0)

#define TMA3(smem, mapref, x, y, z, mb) \
    asm volatile("cp.async.bulk.tensor.3d.shared::cta.global.tile.mbarrier::complete_tx::bytes " \
        "[%0], [%1, {%2, %3, %4}], [%5];" \
        :: "r"(smem), "l"(&(mapref)), "r"(x), "r"(y), "r"(z), "r"(mb) : "memory")

__device__ __forceinline__ void mma_f16_ss(uint32_t d, uint64_t a, uint64_t b,
                                           uint32_t idesc, uint32_t en) {
    asm volatile("{\n\t.reg .pred p;\n\tsetp.ne.u32 p, %5, 0;\n\t"
        "tcgen05.mma.cta_group::1.kind::f16 [%0], %1, %2, %3, {%4,%4,%4,%4}, p;\n\t}"
        :: "r"(d), "l"(a), "l"(b), "r"(idesc), "r"(0u), "r"(en) : "memory");
}

// SW128 K-major smem descriptor (layout=2, version=1, SBO=64, LBO=1)
__device__ __forceinline__ uint64_t mk_desc(uint32_t addr) {
    const uint64_t base = (uint64_t(2) << 61) | (uint64_t(1) << 46)
                        | (uint64_t(64) << 32) | (uint64_t(1) << 16);
    return base | ((uint64_t)(addr >> 4) & 0x3FFF);
}

// idesc: f32 accum, bf16 a/b, M=128, N=128
#define IDESC_F16_128x128 0x8200490u
#else
// ---- legacy mma.sync helpers (fallback path) ----
#define LDSM4(R, ptr) do {                                                     \
    unsigned _a = (unsigned)__cvta_generic_to_shared(ptr);                     \
    asm volatile("ldmatrix.sync.aligned.m8n8.x4.shared.b16 {%0,%1,%2,%3}, [%4];" \
        : "=r"((R)[0]), "=r"((R)[1]), "=r"((R)[2]), "=r"((R)[3]) : "r"(_a));   \
} while (0)

#define MMA16816(C, A, B0, B1)                                                 \
    asm volatile("mma.sync.aligned.m16n8k16.row.col.f32.bf16.bf16.f32 "       \
        "{%0,%1,%2,%3},{%4,%5,%6,%7},{%8,%9},{%0,%1,%2,%3};"                  \
        : "+f"((C)[0]), "+f"((C)[1]), "+f"((C)[2]), "+f"((C)[3])              \
        : "r"((A)[0]), "r"((A)[1]), "r"((A)[2]), "r"((A)[3]),                 \
          "r"(B0), "r"(B1))
#endif

// ---------------- merged split fp32 -> bf16 hi/lo (+ qcnt zeroing) -----------
__global__ __launch_bounds__(256)
void split_all(const float* __restrict__ q, const float* __restrict__ k,
               const float* __restrict__ v, const float* __restrict__ wq,
               const float* __restrict__ wk, const float* __restrict__ wv,
               const float* __restrict__ wo)
{
    const int bid = blockIdx.x;
    if (bid < 16) g_qcnt[bid * 256 + threadIdx.x] = 0;   // fused zero_qcnt
    const float* src;
    __nv_bfloat16 *hi, *lo;
    int i4;
    if (bid < 6144) {
        const int z = bid >> 11;
        src = (z == 0) ? q : (z == 1) ? k : v;
        hi = g_INhi + (size_t)z * IN_ELEMS;
        lo = g_INlo + (size_t)z * IN_ELEMS;
        i4 = (bid & 2047) * 256 + threadIdx.x;
    } else {
        const int z = (bid - 6144) >> 8;
        src = (z == 0) ? wq : (z == 1) ? wk : (z == 2) ? wv : wo;
        hi = g_Whi + (size_t)z * W_ELEMS;
        lo = g_Wlo + (size_t)z * W_ELEMS;
        i4 = ((bid - 6144) & 255) * 256 + threadIdx.x;
    }
    float4 val = ((const float4*)src)[i4];
    __nv_bfloat16 h0 = __float2bfloat16(val.x);
    __nv_bfloat16 h1 = __float2bfloat16(val.y);
    __nv_bfloat16 h2 = __float2bfloat16(val.z);
    __nv_bfloat16 h3 = __float2bfloat16(val.w);
    __nv_bfloat16 l0 = __float2bfloat16(val.x - __bfloat162float(h0));
    __nv_bfloat16 l1 = __float2bfloat16(val.y - __bfloat162float(h1));
    __nv_bfloat16 l2 = __float2bfloat16(val.z - __bfloat162float(h2));
    __nv_bfloat16 l3 = __float2bfloat16(val.w - __bfloat162float(h3));
    uint2 hp, lp;
    hp.x = (unsigned)__bfloat16_as_ushort(h0) | ((unsigned)__bfloat16_as_ushort(h1) << 16);
    hp.y = (unsigned)__bfloat16_as_ushort(h2) | ((unsigned)__bfloat16_as_ushort(h3) << 16);
    lp.x = (unsigned)__bfloat16_as_ushort(l0) | ((unsigned)__bfloat16_as_ushort(l1) << 16);
    lp.y = (unsigned)__bfloat16_as_ushort(l2) | ((unsigned)__bfloat16_as_ushort(l3) << 16);
    *(uint2*)(hi + 4 * (size_t)i4) = hp;
    *(uint2*)(lo + 4 * (size_t)i4) = lp;
}

// ---------------- exact fp32 bin-coordinate GEMM -----------------------------
__global__ __launch_bounds__(256)
void bincoord_kernel(const float* __restrict__ q, const float* __restrict__ k,
                     const float* __restrict__ Wq, const float* __restrict__ Wk,
                     const float* __restrict__ bq, const float* __restrict__ bk)
{
    __shared__ float Ws[16][512];
    __shared__ float bs[16];
    const int z = blockIdx.y;
    const float* A = z ? k : q;
    const float* W = z ? Wk : Wq;
    const float* bias = z ? bk : bq;
    float* out = z ? g_Ck : g_Cq;

    for (int i = threadIdx.x; i < 16 * 512; i += 256) {
        int j = i >> 9, kk = i & 511;
        int wrow = (j >> 1) * 64 + (j & 1);
        Ws[j][kk] = W[(size_t)wrow * 512 + kk];
    }
    if (threadIdx.x < 16) {
        int j = threadIdx.x;
        bs[j] = bias[(j >> 1) * 64 + (j & 1)];
    }
    __syncthreads();

    const int token = blockIdx.x * 256 + threadIdx.x;
    float acc[16];
#pragma unroll
    for (int j = 0; j < 16; j++) acc[j] = 0.f;
    const float4* Ar = (const float4*)(A + (size_t)token * 512);
    for (int kk = 0; kk < 128; kk++) {
        float4 a = Ar[kk];
#pragma unroll
        for (int j = 0; j < 16; j++) {
            acc[j] = fmaf(a.x, Ws[j][4 * kk + 0], acc[j]);
            acc[j] = fmaf(a.y, Ws[j][4 * kk + 1], acc[j]);
            acc[j] = fmaf(a.z, Ws[j][4 * kk + 2], acc[j]);
            acc[j] = fmaf(a.w, Ws[j][4 * kk + 3], acc[j]);
        }
    }
#pragma unroll
    for (int j = 0; j < 16; j++) out[(size_t)token * 16 + j] = acc[j] + bs[j];
}

// ---------------- GEMM: C = A*W^T + bias (3-term bf16 split) ----------------
// tcgen05 + TMA, depth-3 pipeline (R10 config: M=128, N=128, K chunks of 64).
// MODE 0 fuses the Poincare projection + binning + query bucketing into the
// epilogue (the 128x128 tile covers 128 tokens x 2 complete heads).
template <int MODE>
__global__ __launch_bounds__(256)
void tc_gemm(const __grid_constant__ CUtensorMap tAhi,
             const __grid_constant__ CUtensorMap tAlo,
             const __grid_constant__ CUtensorMap tWhi,
             const __grid_constant__ CUtensorMap tWlo,
             const float* __restrict__ b0, const float* __restrict__ b1,
             const float* __restrict__ b2, float* __restrict__ outp)
{
    extern __shared__ __align__(1024) char smem[];
    const int tid = threadIdx.x;
    const int wid = tid >> 5;
    const int lid = tid & 31;

    const int z = blockIdx.z;
    const float* bias;
    float* outQ;
    if (MODE == 0) {
        bias = (z == 0) ? b0 : (z == 1) ? b1 : b2;
        outQ = (z == 0) ? g_Q : (z == 1) ? g_K : g_V;
    } else {
        bias = b0;
        outQ = outp;
    }
    const int m0 = blockIdx.x * 128;
    const int n0 = blockIdx.y * 128;

#if HAS_TCGEN05
    const int zA = (MODE == 0) ? z : 0;
    const int zW = (MODE == 0) ? z : 3;
    const uint32_t sb = smem_u32(smem);
    const uint32_t bufB = sb + 1024;

    if (wid == 0) {
        asm volatile("tcgen05.alloc.cta_group::1.sync.aligned.shared::cta.b32 [%0], %1;"
                     :: "r"(sb), "r"(128u) : "memory");
        asm volatile("tcgen05.relinquish_alloc_permit.cta_group::1.sync.aligned;");
    }
    if (tid == 0) {
        MBAR_INIT(sb + 8, 1);  MBAR_INIT(sb + 16, 1); MBAR_INIT(sb + 24, 1); // data
        MBAR_INIT(sb + 32, 1); MBAR_INIT(sb + 40, 1); MBAR_INIT(sb + 48, 1); // mma
    }
    __syncthreads();
    uint32_t tmem;
    asm volatile("ld.shared.b32 %0, [%1];" : "=r"(tmem) : "r"(sb));

    if (wid == 0 && elect_one()) {
        const uint32_t dmb[3] = { sb + 8, sb + 16, sb + 24 };
        const uint32_t mmb[3] = { sb + 32, sb + 40, sb + 48 };

        auto stage = [&](int b, int chunk) {
            const uint32_t bb = bufB + (uint32_t)b * 65536;
            MBAR_EXPECT_TX(dmb[b], 65536u);
            TMA3(bb,         tAhi, chunk * 64, m0, zA, dmb[b]);
            TMA3(bb + 16384, tAlo, chunk * 64, m0, zA, dmb[b]);
            TMA3(bb + 32768, tWhi, chunk * 64, n0, zW, dmb[b]);
            TMA3(bb + 49152, tWlo, chunk * 64, n0, zW, dmb[b]);
        };

        stage(0, 0);
        stage(1, 1);
        stage(2, 2);
        int dph[3] = {0, 0, 0}, mph[3] = {0, 0, 0};

        for (int c = 0; c < 8; c++) {
            const int b = c % 3;
            MBAR_WAIT(dmb[b], dph[b]); dph[b] ^= 1;
            const uint32_t bb = bufB + (uint32_t)b * 65536;
            const uint64_t dAh = mk_desc(bb);
            const uint64_t dAl = mk_desc(bb + 16384);
            const uint64_t dBh = mk_desc(bb + 32768);
            const uint64_t dBl = mk_desc(bb + 49152);
#pragma unroll
            for (int k16 = 0; k16 < 4; k16++) {
                const uint64_t o = k16 * 2;
                mma_f16_ss(tmem, dAh + o, dBh + o, IDESC_F16_128x128,
                           (c == 0 && k16 == 0) ? 0u : 1u);
                mma_f16_ss(tmem, dAh + o, dBl + o, IDESC_F16_128x128, 1u);
                mma_f16_ss(tmem, dAl + o, dBh + o, IDESC_F16_128x128, 1u);
            }
            asm volatile(
                "tcgen05.commit.cta_group::1.mbarrier::arrive::one.shared::cluster.b64 [%0];"
                :: "r"(mmb[b]) : "memory");
            if (c >= 1 && c + 2 < 8) {
                const int pb = (c - 1) % 3;
                MBAR_WAIT(mmb[pb], mph[pb]); mph[pb] ^= 1;
                stage(pb, c + 2);
            }
        }
        MBAR_WAIT(mmb[2], mph[2]); mph[2] ^= 1;
        MBAR_WAIT(mmb[0], mph[0]); mph[0] ^= 1;
        MBAR_WAIT(mmb[1], mph[1]); mph[1] ^= 1;
    }
    __syncthreads();
    asm volatile("tcgen05.fence::after_thread_sync;" ::: "memory");

    // ---- pass 1: TMEM -> smem tile (raw accumulators) ----
    float* sT = (float*)(smem + 1024);
    {
        const int trow = (wid & 3) * 32 + lid;
        const int cbase = (wid >> 2) * 64;
#pragma unroll
        for (int cb = 0; cb < 64; cb += 32) {
            uint32_t r[32];
            asm volatile(
                "tcgen05.ld.sync.aligned.32x32b.x32.b32 "
                "{%0,%1,%2,%3,%4,%5,%6,%7,%8,%9,%10,%11,%12,%13,%14,%15,"
                "%16,%17,%18,%19,%20,%21,%22,%23,%24,%25,%26,%27,%28,%29,%30,%31}, [%32];"
                : "=r"(r[0]), "=r"(r[1]), "=r"(r[2]), "=r"(r[3]),
                  "=r"(r[4]), "=r"(r[5]), "=r"(r[6]), "=r"(r[7]),
                  "=r"(r[8]), "=r"(r[9]), "=r"(r[10]), "=r"(r[11]),
                  "=r"(r[12]), "=r"(r[13]), "=r"(r[14]), "=r"(r[15]),
                  "=r"(r[16]), "=r"(r[17]), "=r"(r[18]), "=r"(r[19]),
                  "=r"(r[20]), "=r"(r[21]), "=r"(r[22]), "=r"(r[23]),
                  "=r"(r[24]), "=r"(r[25]), "=r"(r[26]), "=r"(r[27]),
                  "=r"(r[28]), "=r"(r[29]), "=r"(r[30]), "=r"(r[31])
                : "r"(tmem + cbase + cb));
            asm volatile("tcgen05.wait::ld.sync.aligned;" ::: "memory");
#pragma unroll
            for (int j = 0; j < 32; j++)
                sT[trow * EPI_STRIDE + cbase + cb + j] = __uint_as_float(r[j]);
        }
    }
    __syncthreads();

    // ---- pass 2 (MODE 0): bias + Poincare scale + bin + bucket, in smem ----
    if (MODE == 0) {
        const int r = tid >> 1;            // token row within tile
        const int hh = tid & 1;            // which head half of the tile
        const int gh = (n0 >> 6) + hh;     // global head
        const int token = m0 + r;
        float* rowp = &sT[r * EPI_STRIDE + hh * 64];
        const float* bp = &bias[hh * 64];  // n0 offset folded: bias[n0+hh*64+..]

        float ss = 0.f;
#pragma unroll
        for (int j4 = 0; j4 < 16; j4++) {
            float4 v = *(float4*)&rowp[j4 * 4];
            const float4 b4 = *(const float4*)&bp[n0 + j4 * 4];
            v.x += b4.x; v.y += b4.y; v.z += b4.z; v.w += b4.w;
            if (z < 2) {
                ss = fmaf(v.x, v.x, ss); ss = fmaf(v.y, v.y, ss);
                ss = fmaf(v.z, v.z, ss); ss = fmaf(v.w, v.w, ss);
            }
            *(float4*)&rowp[j4 * 4] = v;
        }
        if (z < 2) {
            const float nrm = sqrtf(ss);
            const float s = fminf(1.0f, 0.99999f / fmaxf(nrm, 1e-12f));
#pragma unroll
            for (int j4 = 0; j4 < 16; j4++) {
                float4 v = *(float4*)&rowp[j4 * 4];
                v.x *= s; v.y *= s; v.z *= s; v.w *= s;
                *(float4*)&rowp[j4 * 4] = v;
            }
            // exact bin from precomputed fp32 coordinates
            const float* C = (z == 0) ? g_Cq : g_Ck;
            const float c0 = C[(size_t)token * 16 + 2 * gh];
            const float c1 = C[(size_t)token * 16 + 2 * gh + 1];
            float ang = atan2f(c1, c0);
            float t = (ang / 6.28318530717958647692f + 0.5f) * 512.0f;
            if (fabsf(t - rintf(t)) < 4e-3f) {
                ang = (float)atan2((double)c1, (double)c0);
                t = (ang / 6.28318530717958647692f + 0.5f) * 512.0f;
            }
            int b = (int)floorf(t);
            b = (b < 0) ? 0 : ((b > NBINS_C - 1) ? NBINS_C - 1 : b);
            if (z == 0) {
                const int hb = (gh << 9) + b;
                const int idx = atomicAdd(&g_qcnt[hb], 1);
                if (idx < QCAP) g_qlist[(size_t)hb * QCAP + idx] = (short)token;
            } else {
                g_kb[gh * N_TOK + token] = b;
            }
        }
    }
    __syncthreads();

    // ---- pass 3: coalesced float4 stores (bias already applied for MODE 0) --
    for (int i = tid; i < 128 * 32; i += 256) {
        const int row = i >> 5;
        const int col = (i & 31) * 4;
        float4 v = *(float4*)&sT[row * EPI_STRIDE + col];
        const int gcol = n0 + col;
        if (MODE == 1) {
            const float4 bb4 = *(const float4*)&bias[gcol];
            v.x += bb4.x; v.y += bb4.y; v.z += bb4.z; v.w += bb4.w;
            *(float4*)&outQ[(size_t)(m0 + row) * 512 + gcol] = v;
        } else {
            const int h = gcol >> 6, dd = gcol & 63;
            *(float4*)&outQ[((size_t)((h << 12) + m0 + row)) * 64 + dd] = v;
        }
    }
    __syncthreads();
    if (wid == 0) {
        asm volatile("tcgen05.dealloc.cta_group::1.sync.aligned.b32 %0, %1;"
                     :: "r"(tmem), "r"(128u));
    }
#else
    // ---- fallback: mma.sync path (NOTE: arch-specific pass is confirmed
    // present on this harness; this branch is compile-completeness only) ----
    const __nv_bfloat16 *Ahi, *Alo, *Whi, *Wlo;
    if (MODE == 0) {
        Ahi = g_INhi + (size_t)z * IN_ELEMS;
        Alo = g_INlo + (size_t)z * IN_ELEMS;
        Whi = g_Whi + (size_t)z * W_ELEMS;
        Wlo = g_Wlo + (size_t)z * W_ELEMS;
    } else {
        Ahi = g_AOhi; Alo = g_AOlo;
        Whi = g_Whi + (size_t)3 * W_ELEMS;
        Wlo = g_Wlo + (size_t)3 * W_ELEMS;
    }
    unsigned short* As = (unsigned short*)smem;
    unsigned short* Bs = (unsigned short*)(smem + 16384);
    const int wm = wid >> 1;
    const int wn = wid & 1;

    float acc[2][8][4];
#pragma unroll
    for (int a = 0; a < 2; a++)
#pragma unroll
        for (int b = 0; b < 8; b++)
#pragma unroll
            for (int c = 0; c < 4; c++) acc[a][b][c] = 0.f;

    for (int kt = 0; kt < D_MODEL; kt += 32) {
#pragma unroll
        for (int i = 0; i < 8; i++) {
            const int cid = tid + i * 256;
            const int which = cid >> 9;
            const int r = (cid >> 2) & 127;
            const int kc = cid & 3;
            const __nv_bfloat16* base =
                (which == 0) ? Ahi : (which == 1) ? Alo : (which == 2) ? Whi : Wlo;
            const int grow = ((which < 2) ? m0 : n0) + r;
            uint4 v = *(const uint4*)(base + (size_t)grow * 512 + kt + kc * 8);
            unsigned short* db = (which < 2) ? As : Bs;
            const int sc = (kc + ((which & 1) << 2)) ^ (r & 7);
            *(uint4*)(db + r * 64 + sc * 8) = v;
        }
        __syncthreads();

#pragma unroll
        for (int k16 = 0; k16 < 2; k16++) {
            unsigned ah[2][4], al[2][4], bh[4][4], bl[4][4];
#pragma unroll
            for (int mi = 0; mi < 2; mi++) {
                const int r = wm * 32 + mi * 16 + (lid & 15);
                const int kc = 2 * k16 + (lid >> 4);
                LDSM4(ah[mi], As + r * 64 + ((kc) ^ (r & 7)) * 8);
                LDSM4(al[mi], As + r * 64 + ((kc + 4) ^ (r & 7)) * 8);
            }
#pragma unroll
            for (int p = 0; p < 4; p++) {
                const int r = wn * 64 + p * 16 + ((lid >> 4) << 3) + (lid & 7);
                const int kc = 2 * k16 + ((lid >> 3) & 1);
                LDSM4(bh[p], Bs + r * 64 + ((kc) ^ (r & 7)) * 8);
                LDSM4(bl[p], Bs + r * 64 + ((kc + 4) ^ (r & 7)) * 8);
            }
#pragma unroll
            for (int mi = 0; mi < 2; mi++)
#pragma unroll
                for (int nj = 0; nj < 8; nj++) {
                    const int p = nj >> 1, o = (nj & 1) * 2;
                    MMA16816(acc[mi][nj], ah[mi], bh[p][o], bh[p][o + 1]);
                    MMA16816(acc[mi][nj], ah[mi], bl[p][o], bl[p][o + 1]);
                    MMA16816(acc[mi][nj], al[mi], bh[p][o], bh[p][o + 1]);
                }
        }
        __syncthreads();
    }

#pragma unroll
    for (int mi = 0; mi < 2; mi++)
#pragma unroll
        for (int nj = 0; nj < 8; nj++) {
            const int row = m0 + wm * 32 + mi * 16 + (lid >> 2);
            const int col = n0 + wn * 64 + nj * 8 + (lid & 3) * 2;
            const float bx = bias[col], by = bias[col + 1];
            float2 v0 = make_float2(acc[mi][nj][0] + bx, acc[mi][nj][1] + by);
            float2 v1 = make_float2(acc[mi][nj][2] + bx, acc[mi][nj][3] + by);
            if (MODE == 0) {
                const int h = col >> 6, d = col & 63;
                *(float2*)&outQ[((size_t)((h << 12) + row)) * 64 + d] = v0;
                *(float2*)&outQ[((size_t)((h << 12) + row + 8)) * 64 + d] = v1;
            } else {
                *(float2*)&outQ[(size_t)row * 512 + col] = v0;
                *(float2*)&outQ[(size_t)(row + 8) * 512 + col] = v1;
            }
        }
#endif
}

// ---------------- candidate lists per (head, bin) ---------------------------
__global__ __launch_bounds__(256)
void cand_kernel()
{
    __shared__ short kbs[N_TOK];
    const int h    = blockIdx.x >> 6;
    const int bin0 = (blockIdx.x & 63) * 8;
    for (int i = threadIdx.x; i < N_TOK; i += 256)
        kbs[i] = (short)g_kb[h * N_TOK + i];
    __syncthreads();

    const int warp = threadIdx.x >> 5;
    const int lane = threadIdx.x & 31;
    const int b = bin0 + warp;
    short* dst = g_cand + ((size_t)h * NBINS_C + b) * CAND_C;

    int cnt = 0;
    for (int k0 = 0; k0 < N_TOK; k0 += 32) {
        const int kv = (int)kbs[k0 + lane];
        const int d = kv - b;
        const bool pred = (d >= -1) && (d <= 1);
        const unsigned bal = __ballot_sync(0xffffffffu, pred);
        const int rank = __popc(bal & ((1u << lane) - 1u));
        if (pred && (cnt + rank) < CAND_C) dst[cnt + rank] = (short)(k0 + lane);
        cnt += __popc(bal);
        if (cnt >= CAND_C) { cnt = CAND_C; break; }
    }
    if (lane == 0) g_cnt[h * NBINS_C + b] = cnt;
}

// ---------------- bucketed sparse attention ----------------------------------
__global__ __launch_bounds__(256)
void attn_kernel()
{
    __shared__ float Ks[CAND_C * 68];
    __shared__ float Vs[CAND_C * 68];
    __shared__ float qs[8][64];
    __shared__ float ws[8][64];
    __shared__ short cl[CAND_C];

    const int hb = blockIdx.x;
    int nq = g_qcnt[hb];
    if (nq == 0) return;
    if (nq > QCAP) nq = QCAP;

    const int h = hb >> 9;
    const int tid = threadIdx.x;
    const int wid = tid >> 5;
    const int lane = tid & 31;

    const int cnt = g_cnt[hb];
    const int c = (cnt == 0) ? CAND_C : cnt;
    if (tid < CAND_C) {
        short v = (short)tid;
        if (cnt > 0) v = (tid < cnt) ? g_cand[(size_t)hb * CAND_C + tid] : (short)0;
        cl[tid] = v;
    }
    __syncthreads();

    for (int i = tid; i < c * 16; i += 256) {
        const int r = i >> 4, seg = i & 15;
        const size_t gro = ((size_t)(h << 12) + cl[r]) * 64 + seg * 4;
        *(float4*)&Ks[r * 68 + seg * 4] = *(const float4*)&g_K[gro];
        *(float4*)&Vs[r * 68 + seg * 4] = *(const float4*)&g_V[gro];
    }
    __syncthreads();

    for (int qi = wid; qi < nq; qi += 8) {
        const int q = (int)g_qlist[(size_t)hb * QCAP + qi];
        const float* qrow = g_Q + ((size_t)(h << 12) + q) * 64;
        qs[wid][lane] = qrow[lane];
        qs[wid][lane + 32] = qrow[lane + 32];
        __syncwarp();

        float s0 = -INFINITY, s1 = -INFINITY;
        {
            float a0 = 0.f, a1 = 0.f;
            const bool v0 = (lane < c), v1 = (lane + 32 < c);
#pragma unroll
            for (int d4 = 0; d4 < 16; d4++) {
                const float4 qv = *(const float4*)&qs[wid][d4 * 4];
                if (v0) {
                    const float4 kv = *(const float4*)&Ks[lane * 68 + d4 * 4];
                    a0 = fmaf(qv.x, kv.x, a0); a0 = fmaf(qv.y, kv.y, a0);
                    a0 = fmaf(qv.z, kv.z, a0); a0 = fmaf(qv.w, kv.w, a0);
                }
                if (v1) {
                    const float4 kv = *(const float4*)&Ks[(lane + 32) * 68 + d4 * 4];
                    a1 = fmaf(qv.x, kv.x, a1); a1 = fmaf(qv.y, kv.y, a1);
                    a1 = fmaf(qv.z, kv.z, a1); a1 = fmaf(qv.w, kv.w, a1);
                }
            }
            if (v0) s0 = a0 * 0.125f;
            if (v1) s1 = a1 * 0.125f;
        }

        float m = fmaxf(s0, s1);
#pragma unroll
        for (int o = 16; o; o >>= 1) m = fmaxf(m, __shfl_xor_sync(0xffffffffu, m, o));
        const float e0 = expf(s0 - m);
        const float e1 = expf(s1 - m);
        float ssum = e0 + e1;
#pragma unroll
        for (int o = 16; o; o >>= 1) ssum += __shfl_xor_sync(0xffffffffu, ssum, o);
        const float inv = 1.0f / ssum;
        ws[wid][lane] = e0 * inv;
        ws[wid][lane + 32] = e1 * inv;
        __syncwarp();

        float a0 = 0.f, a1 = 0.f;
        for (int c2 = 0; c2 < c; c2++) {
            const float wv = ws[wid][c2];
            a0 = fmaf(wv, Vs[c2 * 68 + lane], a0);
            a1 = fmaf(wv, Vs[c2 * 68 + lane + 32], a1);
        }

        const int ch = (h << 6) + lane;
        __nv_bfloat16 h0 = __float2bfloat16(a0);
        __nv_bfloat16 h1 = __float2bfloat16(a1);
        g_AOhi[(size_t)q * 512 + ch]      = h0;
        g_AOhi[(size_t)q * 512 + ch + 32] = h1;
        g_AOlo[(size_t)q * 512 + ch]      = __float2bfloat16(a0 - __bfloat162float(h0));
        g_AOlo[(size_t)q * 512 + ch + 32] = __float2bfloat16(a1 - __bfloat162float(h1));
    }
}

// ---------------- host: tensor-map construction ------------------------------
typedef CUresult (*PFN_encodeTiled)(
    CUtensorMap*, CUtensorMapDataType, cuuint32_t, void*,
    const cuuint64_t*, const cuuint64_t*, const cuuint32_t*, const cuuint32_t*,
    CUtensorMapInterleave, CUtensorMapSwizzle, CUtensorMapL2promotion,
    CUtensorMapFloatOOBfill);

static PFN_encodeTiled get_encoder()
{
    static PFN_encodeTiled fn = nullptr;
    if (!fn) {
        void* p = nullptr;
        cudaDriverEntryPointQueryResult st;
        cudaGetDriverEntryPoint("cuTensorMapEncodeTiled", &p,
                                cudaEnableDefault, &st);
        fn = (PFN_encodeTiled)p;
    }
    return fn;
}

static void make_map(CUtensorMap* m, void* ptr, uint64_t d0, uint64_t d1,
                     uint64_t d2, uint32_t bx, uint32_t by)
{
    cuuint64_t dims[3] = { d0, d1, d2 };
    cuuint64_t strides[2] = { d0 * 2, d0 * d1 * 2 };
    cuuint32_t box[3] = { bx, by, 1 };
    cuuint32_t es[3] = { 1, 1, 1 };
    get_encoder()(m, CU_TENSOR_MAP_DATA_TYPE_BFLOAT16, 3, ptr,
                  dims, strides, box, es,
                  CU_TENSOR_MAP_INTERLEAVE_NONE, CU_TENSOR_MAP_SWIZZLE_128B,
                  CU_TENSOR_MAP_L2_PROMOTION_L2_128B,
                  CU_TENSOR_MAP_FLOAT_OOB_FILL_NONE);
}

// ---------------- launch -----------------------------------------------------
extern "C" void kernel_launch(void* const* d_in, const int* in_sizes, int n_in,
                              void* d_out, int out_size)
{
    const float* query = (const float*)d_in[0];
    const float* key   = (const float*)d_in[1];
    const float* value = (const float*)d_in[2];
    const float* Wq    = (const float*)d_in[3];
    const float* bq    = (const float*)d_in[4];
    const float* Wk    = (const float*)d_in[5];
    const float* bk    = (const float*)d_in[6];
    const float* Wv    = (const float*)d_in[7];
    const float* bv    = (const float*)d_in[8];
    const float* Wo    = (const float*)d_in[9];
    const float* bo    = (const float*)d_in[10];
    float* out = (float*)d_out;

    const int SMEM_GEMM = 1024 + 3 * 65536;   // 197632 bytes
    static int attr_done = 0;
    if (!attr_done) {
        cudaFuncSetAttribute(tc_gemm<0>, cudaFuncAttributeMaxDynamicSharedMemorySize, SMEM_GEMM);
        cudaFuncSetAttribute(tc_gemm<1>, cudaFuncAttributeMaxDynamicSharedMemorySize, SMEM_GEMM);
        attr_done = 1;
    }

    void *p_inhi, *p_inlo, *p_whi, *p_wlo, *p_aohi, *p_aolo;
    cudaGetSymbolAddress(&p_inhi, g_INhi);
    cudaGetSymbolAddress(&p_inlo, g_INlo);
    cudaGetSymbolAddress(&p_whi,  g_Whi);
    cudaGetSymbolAddress(&p_wlo,  g_Wlo);
    cudaGetSymbolAddress(&p_aohi, g_AOhi);
    cudaGetSymbolAddress(&p_aolo, g_AOlo);

    CUtensorMap tInHi, tInLo, tWHi, tWLo, tAoHi, tAoLo;
    make_map(&tInHi, p_inhi, 512, 4096, 3, 64, 128);
    make_map(&tInLo, p_inlo, 512, 4096, 3, 64, 128);
    make_map(&tWHi,  p_whi,  512, 512,  4, 64, 128);
    make_map(&tWLo,  p_wlo,  512, 512,  4, 64, 128);
    make_map(&tAoHi, p_aohi, 512, 4096, 1, 64, 128);
    make_map(&tAoLo, p_aolo, 512, 4096, 1, 64, 128);

    split_all<<<7168, 256>>>(query, key, value, Wq, Wk, Wv, Wo);
    bincoord_kernel<<<dim3(16, 2), 256>>>(query, key, Wq, Wk, bq, bk);
    // QKV projections with fused Poincare projection + binning + bucketing
    tc_gemm<0><<<dim3(32, 4, 3), 256, SMEM_GEMM>>>(tInHi, tInLo, tWHi, tWLo,
                                                   bq, bk, bv, nullptr);
    cand_kernel<<<512, 256>>>();
    attn_kernel<<<4096, 256>>>();
    tc_gemm<1><<<dim3(32, 4, 1), 256, SMEM_GEMM>>>(tAoHi, tAoLo, tWHi, tWLo,
                                                   bo, nullptr, nullptr, out);
}

// round 13
// speedup vs baseline: 1.1314x; 1.0444x over previous
#include <cuda_runtime.h>
#include <cuda.h>
#include <cuda_bf16.h>
#include <math.h>
#include <stdint.h>

#define N_TOK   4096
#define D_MODEL 512
#define N_HEADS 8
#define HEAD_DIM 64
#define NBINS_C 512
#define CAND_C  64
#define QCAP    512
#define IN_ELEMS (N_TOK * D_MODEL)
#define W_ELEMS  (D_MODEL * D_MODEL)
#define EPI_STRIDE 132   // multiple of 4 -> float4-aligned rows

// Compile-time feature gate: tcgen05 is only legal in arch-specific passes.
#if defined(__CUDA_ARCH__)
#if defined(__CUDA_ARCH_FEAT_SM103_ALL) || defined(__CUDA_ARCH_FEAT_SM100_ALL)
#define HAS_TCGEN05 1
#elif defined(__CUDA_ARCH_SPECIFIC__) && (__CUDA_ARCH__ >= 1000)
#define HAS_TCGEN05 1
#elif defined(__CUDA_ARCH_FAMILY_SPECIFIC__) && (__CUDA_ARCH__ >= 1000)
#define HAS_TCGEN05 1
#else
#define HAS_TCGEN05 0
#endif
#else
#define HAS_TCGEN05 0
#endif

// ---------------- scratch (device globals: allocation-free) ----------------
static __device__ float g_Q[N_HEADS * N_TOK * HEAD_DIM];   // [h][n][d], projected
static __device__ float g_K[N_HEADS * N_TOK * HEAD_DIM];
static __device__ float g_V[N_HEADS * N_TOK * HEAD_DIM];
static __device__ int   g_kb[N_HEADS * N_TOK];
static __device__ short g_cand[N_HEADS * NBINS_C * CAND_C];
static __device__ int   g_cnt[N_HEADS * NBINS_C];

// query buckets per (head, bin)
static __device__ int   g_qcnt[N_HEADS * NBINS_C];
static __device__ short g_qlist[N_HEADS * NBINS_C * QCAP];

// bf16 split operands
static __device__ __align__(1024) __nv_bfloat16 g_INhi[3 * IN_ELEMS];
static __device__ __align__(1024) __nv_bfloat16 g_INlo[3 * IN_ELEMS];
static __device__ __align__(1024) __nv_bfloat16 g_Whi[4 * W_ELEMS];
static __device__ __align__(1024) __nv_bfloat16 g_Wlo[4 * W_ELEMS];
static __device__ __align__(1024) __nv_bfloat16 g_AOhi[IN_ELEMS];
static __device__ __align__(1024) __nv_bfloat16 g_AOlo[IN_ELEMS];

// exact fp32 bin coordinates: [token][2*h + {0,1}]
static __device__ float g_Cq[N_TOK * 16];
static __device__ float g_Ck[N_TOK * 16];

// ---------------- PTX helpers ------------------------------------------------
__device__ __forceinline__ uint32_t smem_u32(const void* p) {
    uint32_t a;
    asm("{ .reg .u64 t; cvta.to.shared.u64 t, %1; cvt.u32.u64 %0, t; }"
        : "=r"(a) : "l"(p));
    return a;
}

#define SW128(x) ((x) ^ (((x) >> 3) & 0x70))

#if HAS_TCGEN05
__device__ __forceinline__ uint32_t elect_one() {
    uint32_t pred;
    asm volatile("{\n\t.reg .pred p;\n\telect.sync _|p, 0xFFFFFFFF;\n\t"
                 "selp.b32 %0, 1, 0, p;\n\t}" : "=r"(pred));
    return pred;
}

#define MBAR_INIT(a, c) \
    asm volatile("mbarrier.init.shared.b64 [%0], %1;" :: "r"(a), "r"(c) : "memory")

#define MBAR_EXPECT_TX(a, bytes) \
    asm volatile("mbarrier.arrive.expect_tx.shared.b64 _, [%0], %1;" \
                 :: "r"(a), "r"(bytes) : "memory")

#define MBAR_WAIT(a, ph) do {                                                   \
    asm volatile("{\n\t.reg .pred P1;\n\t"                                      \
        "WL_%=:\n\t"                                                            \
        "mbarrier.try_wait.parity.acquire.cta.shared::cta.b64 P1, [%0], %1, 0x989680;\n\t" \
        "@P1 bra.uni WD_%=;\n\t"                                                \
        "bra.uni WL_%=;\n\t"                                                    \
        "WD_%=:\n\t}"                                                           \
        :: "r"(a), "r"(ph) : "memory");                                         \
} while (0)

#define TMA3(smem, mapref, x, y, z, mb) \
    asm volatile("cp.async.bulk.tensor.3d.shared::cta.global.tile.mbarrier::complete_tx::bytes " \
        "[%0], [%1, {%2, %3, %4}], [%5];" \
        :: "r"(smem), "l"(&(mapref)), "r"(x), "r"(y), "r"(z), "r"(mb) : "memory")

__device__ __forceinline__ void mma_f16_ss(uint32_t d, uint64_t a, uint64_t b,
                                           uint32_t idesc, uint32_t en) {
    asm volatile("{\n\t.reg .pred p;\n\tsetp.ne.u32 p, %5, 0;\n\t"
        "tcgen05.mma.cta_group::1.kind::f16 [%0], %1, %2, %3, {%4,%4,%4,%4}, p;\n\t}"
        :: "r"(d), "l"(a), "l"(b), "r"(idesc), "r"(0u), "r"(en) : "memory");
}

// SW128 K-major smem descriptor (layout=2, version=1, SBO=64, LBO=1)
__device__ __forceinline__ uint64_t mk_desc(uint32_t addr) {
    const uint64_t base = (uint64_t(2) << 61) | (uint64_t(1) << 46)
                        | (uint64_t(64) << 32) | (uint64_t(1) << 16);
    return base | ((uint64_t)(addr >> 4) & 0x3FFF);
}

// idesc: f32 accum, bf16 a/b, M=128, N=128
#define IDESC_F16_128x128 0x8200490u
#else
// ---- legacy mma.sync helpers (fallback path) ----
#define LDSM4(R, ptr) do {                                                     \
    unsigned _a = (unsigned)__cvta_generic_to_shared(ptr);                     \
    asm volatile("ldmatrix.sync.aligned.m8n8.x4.shared.b16 {%0,%1,%2,%3}, [%4];" \
        : "=r"((R)[0]), "=r"((R)[1]), "=r"((R)[2]), "=r"((R)[3]) : "r"(_a));   \
} while (0)

#define MMA16816(C, A, B0, B1)                                                 \
    asm volatile("mma.sync.aligned.m16n8k16.row.col.f32.bf16.bf16.f32 "       \
        "{%0,%1,%2,%3},{%4,%5,%6,%7},{%8,%9},{%0,%1,%2,%3};"                  \
        : "+f"((C)[0]), "+f"((C)[1]), "+f"((C)[2]), "+f"((C)[3])              \
        : "r"((A)[0]), "r"((A)[1]), "r"((A)[2]), "r"((A)[3]),                 \
          "r"(B0), "r"(B1))
#endif

// ---------------- merged split fp32 -> bf16 hi/lo (+ qcnt zeroing) -----------
__global__ __launch_bounds__(256)
void split_all(const float* __restrict__ q, const float* __restrict__ k,
               const float* __restrict__ v, const float* __restrict__ wq,
               const float* __restrict__ wk, const float* __restrict__ wv,
               const float* __restrict__ wo)
{
    const int bid = blockIdx.x;
    if (bid < 16) g_qcnt[bid * 256 + threadIdx.x] = 0;   // fused zero_qcnt
    const float* src;
    __nv_bfloat16 *hi, *lo;
    int i4;
    if (bid < 6144) {
        const int z = bid >> 11;
        src = (z == 0) ? q : (z == 1) ? k : v;
        hi = g_INhi + (size_t)z * IN_ELEMS;
        lo = g_INlo + (size_t)z * IN_ELEMS;
        i4 = (bid & 2047) * 256 + threadIdx.x;
    } else {
        const int z = (bid - 6144) >> 8;
        src = (z == 0) ? wq : (z == 1) ? wk : (z == 2) ? wv : wo;
        hi = g_Whi + (size_t)z * W_ELEMS;
        lo = g_Wlo + (size_t)z * W_ELEMS;
        i4 = ((bid - 6144) & 255) * 256 + threadIdx.x;
    }
    float4 val = ((const float4*)src)[i4];
    __nv_bfloat16 h0 = __float2bfloat16(val.x);
    __nv_bfloat16 h1 = __float2bfloat16(val.y);
    __nv_bfloat16 h2 = __float2bfloat16(val.z);
    __nv_bfloat16 h3 = __float2bfloat16(val.w);
    __nv_bfloat16 l0 = __float2bfloat16(val.x - __bfloat162float(h0));
    __nv_bfloat16 l1 = __float2bfloat16(val.y - __bfloat162float(h1));
    __nv_bfloat16 l2 = __float2bfloat16(val.z - __bfloat162float(h2));
    __nv_bfloat16 l3 = __float2bfloat16(val.w - __bfloat162float(h3));
    uint2 hp, lp;
    hp.x = (unsigned)__bfloat16_as_ushort(h0) | ((unsigned)__bfloat16_as_ushort(h1) << 16);
    hp.y = (unsigned)__bfloat16_as_ushort(h2) | ((unsigned)__bfloat16_as_ushort(h3) << 16);
    lp.x = (unsigned)__bfloat16_as_ushort(l0) | ((unsigned)__bfloat16_as_ushort(l1) << 16);
    lp.y = (unsigned)__bfloat16_as_ushort(l2) | ((unsigned)__bfloat16_as_ushort(l3) << 16);
    *(uint2*)(hi + 4 * (size_t)i4) = hp;
    *(uint2*)(lo + 4 * (size_t)i4) = lp;
}

// ---------------- exact fp32 bin-coordinate GEMM -----------------------------
__global__ __launch_bounds__(256)
void bincoord_kernel(const float* __restrict__ q, const float* __restrict__ k,
                     const float* __restrict__ Wq, const float* __restrict__ Wk,
                     const float* __restrict__ bq, const float* __restrict__ bk)
{
    __shared__ float Ws[16][512];
    __shared__ float bs[16];
    const int z = blockIdx.y;
    const float* A = z ? k : q;
    const float* W = z ? Wk : Wq;
    const float* bias = z ? bk : bq;
    float* out = z ? g_Ck : g_Cq;

    for (int i = threadIdx.x; i < 16 * 512; i += 256) {
        int j = i >> 9, kk = i & 511;
        int wrow = (j >> 1) * 64 + (j & 1);
        Ws[j][kk] = W[(size_t)wrow * 512 + kk];
    }
    if (threadIdx.x < 16) {
        int j = threadIdx.x;
        bs[j] = bias[(j >> 1) * 64 + (j & 1)];
    }
    __syncthreads();

    const int token = blockIdx.x * 256 + threadIdx.x;
    float acc[16];
#pragma unroll
    for (int j = 0; j < 16; j++) acc[j] = 0.f;
    const float4* Ar = (const float4*)(A + (size_t)token * 512);
    for (int kk = 0; kk < 128; kk++) {
        float4 a = Ar[kk];
#pragma unroll
        for (int j = 0; j < 16; j++) {
            acc[j] = fmaf(a.x, Ws[j][4 * kk + 0], acc[j]);
            acc[j] = fmaf(a.y, Ws[j][4 * kk + 1], acc[j]);
            acc[j] = fmaf(a.z, Ws[j][4 * kk + 2], acc[j]);
            acc[j] = fmaf(a.w, Ws[j][4 * kk + 3], acc[j]);
        }
    }
#pragma unroll
    for (int j = 0; j < 16; j++) out[(size_t)token * 16 + j] = acc[j] + bs[j];
}

// ---------------- GEMM: C = A*W^T + bias (3-term bf16 split) ----------------
// tcgen05 + TMA, depth-3 pipeline (M=128, N=128, K chunks of 64).
// MODE 0 fuses the Poincare projection + binning + query bucketing into the
// epilogue (the 128x128 tile covers 128 tokens x 2 complete heads).
template <int MODE>
__global__ __launch_bounds__(256)
void tc_gemm(const __grid_constant__ CUtensorMap tAhi,
             const __grid_constant__ CUtensorMap tAlo,
             const __grid_constant__ CUtensorMap tWhi,
             const __grid_constant__ CUtensorMap tWlo,
             const float* __restrict__ b0, const float* __restrict__ b1,
             const float* __restrict__ b2, float* __restrict__ outp)
{
    extern __shared__ __align__(1024) char smem[];
    const int tid = threadIdx.x;
    const int wid = tid >> 5;
    const int lid = tid & 31;

    const int z = blockIdx.z;
    const float* bias;
    float* outQ;
    if (MODE == 0) {
        bias = (z == 0) ? b0 : (z == 1) ? b1 : b2;
        outQ = (z == 0) ? g_Q : (z == 1) ? g_K : g_V;
    } else {
        bias = b0;
        outQ = outp;
    }
    const int m0 = blockIdx.x * 128;
    const int n0 = blockIdx.y * 128;

#if HAS_TCGEN05
    const int zA = (MODE == 0) ? z : 0;
    const int zW = (MODE == 0) ? z : 3;
    const uint32_t sb = smem_u32(smem);
    const uint32_t bufB = sb + 1024;

    if (wid == 0) {
        asm volatile("tcgen05.alloc.cta_group::1.sync.aligned.shared::cta.b32 [%0], %1;"
                     :: "r"(sb), "r"(128u) : "memory");
        asm volatile("tcgen05.relinquish_alloc_permit.cta_group::1.sync.aligned;");
    }
    if (tid == 0) {
        MBAR_INIT(sb + 8, 1);  MBAR_INIT(sb + 16, 1); MBAR_INIT(sb + 24, 1); // data
        MBAR_INIT(sb + 32, 1); MBAR_INIT(sb + 40, 1); MBAR_INIT(sb + 48, 1); // mma
    }
    __syncthreads();
    uint32_t tmem;
    asm volatile("ld.shared.b32 %0, [%1];" : "=r"(tmem) : "r"(sb));

    if (wid == 0 && elect_one()) {
        const uint32_t dmb[3] = { sb + 8, sb + 16, sb + 24 };
        const uint32_t mmb[3] = { sb + 32, sb + 40, sb + 48 };

        auto stage = [&](int b, int chunk) {
            const uint32_t bb = bufB + (uint32_t)b * 65536;
            MBAR_EXPECT_TX(dmb[b], 65536u);
            TMA3(bb,         tAhi, chunk * 64, m0, zA, dmb[b]);
            TMA3(bb + 16384, tAlo, chunk * 64, m0, zA, dmb[b]);
            TMA3(bb + 32768, tWhi, chunk * 64, n0, zW, dmb[b]);
            TMA3(bb + 49152, tWlo, chunk * 64, n0, zW, dmb[b]);
        };

        stage(0, 0);
        stage(1, 1);
        stage(2, 2);
        int dph[3] = {0, 0, 0}, mph[3] = {0, 0, 0};

        for (int c = 0; c < 8; c++) {
            const int b = c % 3;
            MBAR_WAIT(dmb[b], dph[b]); dph[b] ^= 1;
            const uint32_t bb = bufB + (uint32_t)b * 65536;
            const uint64_t dAh = mk_desc(bb);
            const uint64_t dAl = mk_desc(bb + 16384);
            const uint64_t dBh = mk_desc(bb + 32768);
            const uint64_t dBl = mk_desc(bb + 49152);
#pragma unroll
            for (int k16 = 0; k16 < 4; k16++) {
                const uint64_t o = k16 * 2;
                mma_f16_ss(tmem, dAh + o, dBh + o, IDESC_F16_128x128,
                           (c == 0 && k16 == 0) ? 0u : 1u);
                mma_f16_ss(tmem, dAh + o, dBl + o, IDESC_F16_128x128, 1u);
                mma_f16_ss(tmem, dAl + o, dBh + o, IDESC_F16_128x128, 1u);
            }
            asm volatile(
                "tcgen05.commit.cta_group::1.mbarrier::arrive::one.shared::cluster.b64 [%0];"
                :: "r"(mmb[b]) : "memory");
            if (c >= 1 && c + 2 < 8) {
                const int pb = (c - 1) % 3;
                MBAR_WAIT(mmb[pb], mph[pb]); mph[pb] ^= 1;
                stage(pb, c + 2);
            }
        }
        MBAR_WAIT(mmb[2], mph[2]); mph[2] ^= 1;
        MBAR_WAIT(mmb[0], mph[0]); mph[0] ^= 1;
        MBAR_WAIT(mmb[1], mph[1]); mph[1] ^= 1;
    }
    __syncthreads();
    asm volatile("tcgen05.fence::after_thread_sync;" ::: "memory");

    // ---- pass 1: TMEM -> smem tile (raw accumulators) ----
    float* sT = (float*)(smem + 1024);
    {
        const int trow = (wid & 3) * 32 + lid;
        const int cbase = (wid >> 2) * 64;
#pragma unroll
        for (int cb = 0; cb < 64; cb += 32) {
            uint32_t r[32];
            asm volatile(
                "tcgen05.ld.sync.aligned.32x32b.x32.b32 "
                "{%0,%1,%2,%3,%4,%5,%6,%7,%8,%9,%10,%11,%12,%13,%14,%15,"
                "%16,%17,%18,%19,%20,%21,%22,%23,%24,%25,%26,%27,%28,%29,%30,%31}, [%32];"
                : "=r"(r[0]), "=r"(r[1]), "=r"(r[2]), "=r"(r[3]),
                  "=r"(r[4]), "=r"(r[5]), "=r"(r[6]), "=r"(r[7]),
                  "=r"(r[8]), "=r"(r[9]), "=r"(r[10]), "=r"(r[11]),
                  "=r"(r[12]), "=r"(r[13]), "=r"(r[14]), "=r"(r[15]),
                  "=r"(r[16]), "=r"(r[17]), "=r"(r[18]), "=r"(r[19]),
                  "=r"(r[20]), "=r"(r[21]), "=r"(r[22]), "=r"(r[23]),
                  "=r"(r[24]), "=r"(r[25]), "=r"(r[26]), "=r"(r[27]),
                  "=r"(r[28]), "=r"(r[29]), "=r"(r[30]), "=r"(r[31])
                : "r"(tmem + cbase + cb));
            asm volatile("tcgen05.wait::ld.sync.aligned;" ::: "memory");
#pragma unroll
            for (int j = 0; j < 32; j++)
                sT[trow * EPI_STRIDE + cbase + cb + j] = __uint_as_float(r[j]);
        }
    }
    __syncthreads();

    // ---- pass 2 (MODE 0): bias + Poincare scale + bin + bucket, in smem ----
    if (MODE == 0) {
        const int r = tid >> 1;            // token row within tile
        const int hh = tid & 1;            // which head half of the tile
        const int gh = (n0 >> 6) + hh;     // global head
        const int token = m0 + r;
        float* rowp = &sT[r * EPI_STRIDE + hh * 64];
        const float* bp = &bias[hh * 64];

        float ss = 0.f;
#pragma unroll
        for (int j4 = 0; j4 < 16; j4++) {
            float4 v = *(float4*)&rowp[j4 * 4];
            const float4 b4 = *(const float4*)&bp[n0 + j4 * 4];
            v.x += b4.x; v.y += b4.y; v.z += b4.z; v.w += b4.w;
            if (z < 2) {
                ss = fmaf(v.x, v.x, ss); ss = fmaf(v.y, v.y, ss);
                ss = fmaf(v.z, v.z, ss); ss = fmaf(v.w, v.w, ss);
            }
            *(float4*)&rowp[j4 * 4] = v;
        }
        if (z < 2) {
            const float nrm = sqrtf(ss);
            const float s = fminf(1.0f, 0.99999f / fmaxf(nrm, 1e-12f));
#pragma unroll
            for (int j4 = 0; j4 < 16; j4++) {
                float4 v = *(float4*)&rowp[j4 * 4];
                v.x *= s; v.y *= s; v.z *= s; v.w *= s;
                *(float4*)&rowp[j4 * 4] = v;
            }
            const float* C = (z == 0) ? g_Cq : g_Ck;
            const float c0 = C[(size_t)token * 16 + 2 * gh];
            const float c1 = C[(size_t)token * 16 + 2 * gh + 1];
            float ang = atan2f(c1, c0);
            float t = (ang / 6.28318530717958647692f + 0.5f) * 512.0f;
            if (fabsf(t - rintf(t)) < 4e-3f) {
                ang = (float)atan2((double)c1, (double)c0);
                t = (ang / 6.28318530717958647692f + 0.5f) * 512.0f;
            }
            int b = (int)floorf(t);
            b = (b < 0) ? 0 : ((b > NBINS_C - 1) ? NBINS_C - 1 : b);
            if (z == 0) {
                const int hb = (gh << 9) + b;
                const int idx = atomicAdd(&g_qcnt[hb], 1);
                if (idx < QCAP) g_qlist[(size_t)hb * QCAP + idx] = (short)token;
            } else {
                g_kb[gh * N_TOK + token] = b;
            }
        }
    }
    __syncthreads();

    // ---- pass 3: coalesced float4 stores (bias already applied for MODE 0) --
    for (int i = tid; i < 128 * 32; i += 256) {
        const int row = i >> 5;
        const int col = (i & 31) * 4;
        float4 v = *(float4*)&sT[row * EPI_STRIDE + col];
        const int gcol = n0 + col;
        if (MODE == 1) {
            const float4 bb4 = *(const float4*)&bias[gcol];
            v.x += bb4.x; v.y += bb4.y; v.z += bb4.z; v.w += bb4.w;
            *(float4*)&outQ[(size_t)(m0 + row) * 512 + gcol] = v;
        } else {
            const int h = gcol >> 6, dd = gcol & 63;
            *(float4*)&outQ[((size_t)((h << 12) + m0 + row)) * 64 + dd] = v;
        }
    }
    __syncthreads();
    if (wid == 0) {
        asm volatile("tcgen05.dealloc.cta_group::1.sync.aligned.b32 %0, %1;"
                     :: "r"(tmem), "r"(128u));
    }
#else
    // ---- fallback: mma.sync path (compile-completeness only) ----
    const __nv_bfloat16 *Ahi, *Alo, *Whi, *Wlo;
    if (MODE == 0) {
        Ahi = g_INhi + (size_t)z * IN_ELEMS;
        Alo = g_INlo + (size_t)z * IN_ELEMS;
        Whi = g_Whi + (size_t)z * W_ELEMS;
        Wlo = g_Wlo + (size_t)z * W_ELEMS;
    } else {
        Ahi = g_AOhi; Alo = g_AOlo;
        Whi = g_Whi + (size_t)3 * W_ELEMS;
        Wlo = g_Wlo + (size_t)3 * W_ELEMS;
    }
    unsigned short* As = (unsigned short*)smem;
    unsigned short* Bs = (unsigned short*)(smem + 16384);
    const int wm = wid >> 1;
    const int wn = wid & 1;

    float acc[2][8][4];
#pragma unroll
    for (int a = 0; a < 2; a++)
#pragma unroll
        for (int b = 0; b < 8; b++)
#pragma unroll
            for (int c = 0; c < 4; c++) acc[a][b][c] = 0.f;

    for (int kt = 0; kt < D_MODEL; kt += 32) {
#pragma unroll
        for (int i = 0; i < 8; i++) {
            const int cid = tid + i * 256;
            const int which = cid >> 9;
            const int r = (cid >> 2) & 127;
            const int kc = cid & 3;
            const __nv_bfloat16* base =
                (which == 0) ? Ahi : (which == 1) ? Alo : (which == 2) ? Whi : Wlo;
            const int grow = ((which < 2) ? m0 : n0) + r;
            uint4 v = *(const uint4*)(base + (size_t)grow * 512 + kt + kc * 8);
            unsigned short* db = (which < 2) ? As : Bs;
            const int sc = (kc + ((which & 1) << 2)) ^ (r & 7);
            *(uint4*)(db + r * 64 + sc * 8) = v;
        }
        __syncthreads();

#pragma unroll
        for (int k16 = 0; k16 < 2; k16++) {
            unsigned ah[2][4], al[2][4], bh[4][4], bl[4][4];
#pragma unroll
            for (int mi = 0; mi < 2; mi++) {
                const int r = wm * 32 + mi * 16 + (lid & 15);
                const int kc = 2 * k16 + (lid >> 4);
                LDSM4(ah[mi], As + r * 64 + ((kc) ^ (r & 7)) * 8);
                LDSM4(al[mi], As + r * 64 + ((kc + 4) ^ (r & 7)) * 8);
            }
#pragma unroll
            for (int p = 0; p < 4; p++) {
                const int r = wn * 64 + p * 16 + ((lid >> 4) << 3) + (lid & 7);
                const int kc = 2 * k16 + ((lid >> 3) & 1);
                LDSM4(bh[p], Bs + r * 64 + ((kc) ^ (r & 7)) * 8);
                LDSM4(bl[p], Bs + r * 64 + ((kc + 4) ^ (r & 7)) * 8);
            }
#pragma unroll
            for (int mi = 0; mi < 2; mi++)
#pragma unroll
                for (int nj = 0; nj < 8; nj++) {
                    const int p = nj >> 1, o = (nj & 1) * 2;
                    MMA16816(acc[mi][nj], ah[mi], bh[p][o], bh[p][o + 1]);
                    MMA16816(acc[mi][nj], ah[mi], bl[p][o], bl[p][o + 1]);
                    MMA16816(acc[mi][nj], al[mi], bh[p][o], bh[p][o + 1]);
                }
        }
        __syncthreads();
    }

#pragma unroll
    for (int mi = 0; mi < 2; mi++)
#pragma unroll
        for (int nj = 0; nj < 8; nj++) {
            const int row = m0 + wm * 32 + mi * 16 + (lid >> 2);
            const int col = n0 + wn * 64 + nj * 8 + (lid & 3) * 2;
            const float bx = bias[col], by = bias[col + 1];
            float2 v0 = make_float2(acc[mi][nj][0] + bx, acc[mi][nj][1] + by);
            float2 v1 = make_float2(acc[mi][nj][2] + bx, acc[mi][nj][3] + by);
            if (MODE == 0) {
                const int h = col >> 6, d = col & 63;
                *(float2*)&outQ[((size_t)((h << 12) + row)) * 64 + d] = v0;
                *(float2*)&outQ[((size_t)((h << 12) + row + 8)) * 64 + d] = v1;
            } else {
                *(float2*)&outQ[(size_t)row * 512 + col] = v0;
                *(float2*)&outQ[(size_t)(row + 8) * 512 + col] = v1;
            }
        }
#endif
}

// ---------------- candidate lists per (head, bin) ---------------------------
// Two-phase: (1) dependence-free ballot sweep into smem words, (2) per-lane
// popc + warp exclusive scan + bit-extract emit of the first CAND_C keys.
__global__ __launch_bounds__(256)
void cand_kernel()
{
    __shared__ short kbs[N_TOK];
    __shared__ unsigned words[8][128];
    const int h    = blockIdx.x >> 6;
    const int bin0 = (blockIdx.x & 63) * 8;
    for (int i = threadIdx.x; i < N_TOK; i += 256)
        kbs[i] = (short)g_kb[h * N_TOK + i];
    __syncthreads();

    const int warp = threadIdx.x >> 5;
    const int lane = threadIdx.x & 31;
    const int b = bin0 + warp;
    short* dst = g_cand + ((size_t)h * NBINS_C + b) * CAND_C;

    // phase 1: 128 independent ballots
#pragma unroll 4
    for (int w = 0; w < 128; w++) {
        const int kv = (int)kbs[w * 32 + lane];
        const int d = kv - b;
        const unsigned bal = __ballot_sync(0xffffffffu, (d >= -1) && (d <= 1));
        if (lane == (w & 31)) words[warp][w] = bal;
    }
    __syncwarp();

    // phase 2: per-lane counts over 4 words, warp exclusive scan
    unsigned w0 = words[warp][lane * 4 + 0];
    unsigned w1 = words[warp][lane * 4 + 1];
    unsigned w2 = words[warp][lane * 4 + 2];
    unsigned w3 = words[warp][lane * 4 + 3];
    const int myc = __popc(w0) + __popc(w1) + __popc(w2) + __popc(w3);
    int ex = myc;
#pragma unroll
    for (int o = 1; o < 32; o <<= 1) {
        const int v = __shfl_up_sync(0xffffffffu, ex, o);
        if (lane >= o) ex += v;
    }
    const int total = __shfl_sync(0xffffffffu, ex, 31);
    ex -= myc;  // exclusive prefix

    // emit candidates with rank < CAND_C (ascending key index)
    if (ex < CAND_C && myc > 0) {
        int base = ex;
        const int k0 = lane * 128;
        unsigned ws[4] = { w0, w1, w2, w3 };
#pragma unroll
        for (int wi = 0; wi < 4; wi++) {
            unsigned word = ws[wi];
            while (word && base < CAND_C) {
                const int bit = __ffs(word) - 1;
                dst[base] = (short)(k0 + wi * 32 + bit);
                word &= word - 1;
                base++;
            }
        }
    }
    if (lane == 0)
        g_cnt[h * NBINS_C + b] = (total > CAND_C) ? CAND_C : total;
}

// ---------------- bucketed sparse attention ----------------------------------
__global__ __launch_bounds__(256)
void attn_kernel()
{
    __shared__ float Ks[CAND_C * 68];
    __shared__ float Vs[CAND_C * 68];
    __shared__ float qs[8][64];
    __shared__ float ws[8][64];
    __shared__ short cl[CAND_C];

    const int hb = blockIdx.x;
    int nq = g_qcnt[hb];
    if (nq == 0) return;
    if (nq > QCAP) nq = QCAP;

    const int h = hb >> 9;
    const int tid = threadIdx.x;
    const int wid = tid >> 5;
    const int lane = tid & 31;

    const int cnt = g_cnt[hb];
    const int c = (cnt == 0) ? CAND_C : cnt;
    if (tid < CAND_C) {
        short v = (short)tid;
        if (cnt > 0) v = (tid < cnt) ? g_cand[(size_t)hb * CAND_C + tid] : (short)0;
        cl[tid] = v;
    }
    __syncthreads();

    for (int i = tid; i < c * 16; i += 256) {
        const int r = i >> 4, seg = i & 15;
        const size_t gro = ((size_t)(h << 12) + cl[r]) * 64 + seg * 4;
        *(float4*)&Ks[r * 68 + seg * 4] = *(const float4*)&g_K[gro];
        *(float4*)&Vs[r * 68 + seg * 4] = *(const float4*)&g_V[gro];
    }
    __syncthreads();

    for (int qi = wid; qi < nq; qi += 8) {
        const int q = (int)g_qlist[(size_t)hb * QCAP + qi];
        const float* qrow = g_Q + ((size_t)(h << 12) + q) * 64;
        qs[wid][lane] = qrow[lane];
        qs[wid][lane + 32] = qrow[lane + 32];
        __syncwarp();

        float s0 = -INFINITY, s1 = -INFINITY;
        {
            float a0 = 0.f, a1 = 0.f;
            const bool v0 = (lane < c), v1 = (lane + 32 < c);
#pragma unroll
            for (int d4 = 0; d4 < 16; d4++) {
                const float4 qv = *(const float4*)&qs[wid][d4 * 4];
                if (v0) {
                    const float4 kv = *(const float4*)&Ks[lane * 68 + d4 * 4];
                    a0 = fmaf(qv.x, kv.x, a0); a0 = fmaf(qv.y, kv.y, a0);
                    a0 = fmaf(qv.z, kv.z, a0); a0 = fmaf(qv.w, kv.w, a0);
                }
                if (v1) {
                    const float4 kv = *(const float4*)&Ks[(lane + 32) * 68 + d4 * 4];
                    a1 = fmaf(qv.x, kv.x, a1); a1 = fmaf(qv.y, kv.y, a1);
                    a1 = fmaf(qv.z, kv.z, a1); a1 = fmaf(qv.w, kv.w, a1);
                }
            }
            if (v0) s0 = a0 * 0.125f;
            if (v1) s1 = a1 * 0.125f;
        }

        float m = fmaxf(s0, s1);
#pragma unroll
        for (int o = 16; o; o >>= 1) m = fmaxf(m, __shfl_xor_sync(0xffffffffu, m, o));
        const float e0 = expf(s0 - m);
        const float e1 = expf(s1 - m);
        float ssum = e0 + e1;
#pragma unroll
        for (int o = 16; o; o >>= 1) ssum += __shfl_xor_sync(0xffffffffu, ssum, o);
        const float inv = 1.0f / ssum;
        ws[wid][lane] = e0 * inv;
        ws[wid][lane + 32] = e1 * inv;
        __syncwarp();

        float a0 = 0.f, a1 = 0.f;
        for (int c2 = 0; c2 < c; c2++) {
            const float wv = ws[wid][c2];
            a0 = fmaf(wv, Vs[c2 * 68 + lane], a0);
            a1 = fmaf(wv, Vs[c2 * 68 + lane + 32], a1);
        }

        const int ch = (h << 6) + lane;
        __nv_bfloat16 h0 = __float2bfloat16(a0);
        __nv_bfloat16 h1 = __float2bfloat16(a1);
        g_AOhi[(size_t)q * 512 + ch]      = h0;
        g_AOhi[(size_t)q * 512 + ch + 32] = h1;
        g_AOlo[(size_t)q * 512 + ch]      = __float2bfloat16(a0 - __bfloat162float(h0));
        g_AOlo[(size_t)q * 512 + ch + 32] = __float2bfloat16(a1 - __bfloat162float(h1));
    }
}

// ---------------- host: tensor-map construction ------------------------------
typedef CUresult (*PFN_encodeTiled)(
    CUtensorMap*, CUtensorMapDataType, cuuint32_t, void*,
    const cuuint64_t*, const cuuint64_t*, const cuuint32_t*, const cuuint32_t*,
    CUtensorMapInterleave, CUtensorMapSwizzle, CUtensorMapL2promotion,
    CUtensorMapFloatOOBfill);

static PFN_encodeTiled get_encoder()
{
    static PFN_encodeTiled fn = nullptr;
    if (!fn) {
        void* p = nullptr;
        cudaDriverEntryPointQueryResult st;
        cudaGetDriverEntryPoint("cuTensorMapEncodeTiled", &p,
                                cudaEnableDefault, &st);
        fn = (PFN_encodeTiled)p;
    }
    return fn;
}

static void make_map(CUtensorMap* m, void* ptr, uint64_t d0, uint64_t d1,
                     uint64_t d2, uint32_t bx, uint32_t by)
{
    cuuint64_t dims[3] = { d0, d1, d2 };
    cuuint64_t strides[2] = { d0 * 2, d0 * d1 * 2 };
    cuuint32_t box[3] = { bx, by, 1 };
    cuuint32_t es[3] = { 1, 1, 1 };
    get_encoder()(m, CU_TENSOR_MAP_DATA_TYPE_BFLOAT16, 3, ptr,
                  dims, strides, box, es,
                  CU_TENSOR_MAP_INTERLEAVE_NONE, CU_TENSOR_MAP_SWIZZLE_128B,
                  CU_TENSOR_MAP_L2_PROMOTION_L2_128B,
                  CU_TENSOR_MAP_FLOAT_OOB_FILL_NONE);
}

// ---------------- launch -----------------------------------------------------
extern "C" void kernel_launch(void* const* d_in, const int* in_sizes, int n_in,
                              void* d_out, int out_size)
{
    const float* query = (const float*)d_in[0];
    const float* key   = (const float*)d_in[1];
    const float* value = (const float*)d_in[2];
    const float* Wq    = (const float*)d_in[3];
    const float* bq    = (const float*)d_in[4];
    const float* Wk    = (const float*)d_in[5];
    const float* bk    = (const float*)d_in[6];
    const float* Wv    = (const float*)d_in[7];
    const float* bv    = (const float*)d_in[8];
    const float* Wo    = (const float*)d_in[9];
    const float* bo    = (const float*)d_in[10];
    float* out = (float*)d_out;

    const int SMEM_GEMM = 1024 + 3 * 65536;   // 197632 bytes
    static int attr_done = 0;
    if (!attr_done) {
        cudaFuncSetAttribute(tc_gemm<0>, cudaFuncAttributeMaxDynamicSharedMemorySize, SMEM_GEMM);
        cudaFuncSetAttribute(tc_gemm<1>, cudaFuncAttributeMaxDynamicSharedMemorySize, SMEM_GEMM);
        attr_done = 1;
    }

    void *p_inhi, *p_inlo, *p_whi, *p_wlo, *p_aohi, *p_aolo;
    cudaGetSymbolAddress(&p_inhi, g_INhi);
    cudaGetSymbolAddress(&p_inlo, g_INlo);
    cudaGetSymbolAddress(&p_whi,  g_Whi);
    cudaGetSymbolAddress(&p_wlo,  g_Wlo);
    cudaGetSymbolAddress(&p_aohi, g_AOhi);
    cudaGetSymbolAddress(&p_aolo, g_AOlo);

    CUtensorMap tInHi, tInLo, tWHi, tWLo, tAoHi, tAoLo;
    make_map(&tInHi, p_inhi, 512, 4096, 3, 64, 128);
    make_map(&tInLo, p_inlo, 512, 4096, 3, 64, 128);
    make_map(&tWHi,  p_whi,  512, 512,  4, 64, 128);
    make_map(&tWLo,  p_wlo,  512, 512,  4, 64, 128);
    make_map(&tAoHi, p_aohi, 512, 4096, 1, 64, 128);
    make_map(&tAoLo, p_aolo, 512, 4096, 1, 64, 128);

    split_all<<<7168, 256>>>(query, key, value, Wq, Wk, Wv, Wo);
    bincoord_kernel<<<dim3(16, 2), 256>>>(query, key, Wq, Wk, bq, bk);
    tc_gemm<0><<<dim3(32, 4, 3), 256, SMEM_GEMM>>>(tInHi, tInLo, tWHi, tWLo,
                                                   bq, bk, bv, nullptr);
    cand_kernel<<<512, 256>>>();
    attn_kernel<<<4096, 256>>>();
    tc_gemm<1><<<dim3(32, 4, 1), 256, SMEM_GEMM>>>(tAoHi, tAoLo, tWHi, tWLo,
                                                   bo, nullptr, nullptr, out);
}

// round 14
// speedup vs baseline: 1.1933x; 1.0548x over previous
#include <cuda_runtime.h>
#include <cuda.h>
#include <cuda_bf16.h>
#include <math.h>
#include <stdint.h>

#define N_TOK   4096
#define D_MODEL 512
#define N_HEADS 8
#define HEAD_DIM 64
#define NBINS_C 512
#define CAND_C  64
#define QCAP    512
#define IN_ELEMS (N_TOK * D_MODEL)
#define W_ELEMS  (D_MODEL * D_MODEL)
#define EPI_STRIDE 132   // multiple of 4 -> float4-aligned rows

// Compile-time feature gate: tcgen05 is only legal in arch-specific passes.
#if defined(__CUDA_ARCH__)
#if defined(__CUDA_ARCH_FEAT_SM103_ALL) || defined(__CUDA_ARCH_FEAT_SM100_ALL)
#define HAS_TCGEN05 1
#elif defined(__CUDA_ARCH_SPECIFIC__) && (__CUDA_ARCH__ >= 1000)
#define HAS_TCGEN05 1
#elif defined(__CUDA_ARCH_FAMILY_SPECIFIC__) && (__CUDA_ARCH__ >= 1000)
#define HAS_TCGEN05 1
#else
#define HAS_TCGEN05 0
#endif
#else
#define HAS_TCGEN05 0
#endif

// ---------------- scratch (device globals: allocation-free) ----------------
static __device__ float g_Q[N_HEADS * N_TOK * HEAD_DIM];   // [h][n][d], projected
static __device__ float g_K[N_HEADS * N_TOK * HEAD_DIM];
static __device__ float g_V[N_HEADS * N_TOK * HEAD_DIM];
static __device__ int   g_kb[N_HEADS * N_TOK];
static __device__ short g_cand[N_HEADS * NBINS_C * CAND_C];
static __device__ int   g_cnt[N_HEADS * NBINS_C];

// query buckets per (head, bin)
static __device__ int   g_qcnt[N_HEADS * NBINS_C];
static __device__ short g_qlist[N_HEADS * NBINS_C * QCAP];

// bf16 split operands
static __device__ __align__(1024) __nv_bfloat16 g_INhi[3 * IN_ELEMS];
static __device__ __align__(1024) __nv_bfloat16 g_INlo[3 * IN_ELEMS];
static __device__ __align__(1024) __nv_bfloat16 g_Whi[4 * W_ELEMS];
static __device__ __align__(1024) __nv_bfloat16 g_Wlo[4 * W_ELEMS];
static __device__ __align__(1024) __nv_bfloat16 g_AOhi[IN_ELEMS];
static __device__ __align__(1024) __nv_bfloat16 g_AOlo[IN_ELEMS];

// exact fp32 bin coordinates: [token][2*h + {0,1}]
static __device__ float g_Cq[N_TOK * 16];
static __device__ float g_Ck[N_TOK * 16];

// ---------------- PTX helpers ------------------------------------------------
__device__ __forceinline__ uint32_t smem_u32(const void* p) {
    uint32_t a;
    asm("{ .reg .u64 t; cvta.to.shared.u64 t, %1; cvt.u32.u64 %0, t; }"
        : "=r"(a) : "l"(p));
    return a;
}

#define SW128(x) ((x) ^ (((x) >> 3) & 0x70))

#if HAS_TCGEN05
__device__ __forceinline__ uint32_t elect_one() {
    uint32_t pred;
    asm volatile("{\n\t.reg .pred p;\n\telect.sync _|p, 0xFFFFFFFF;\n\t"
                 "selp.b32 %0, 1, 0, p;\n\t}" : "=r"(pred));
    return pred;
}

#define MBAR_INIT(a, c) \
    asm volatile("mbarrier.init.shared.b64 [%0], %1;" :: "r"(a), "r"(c) : "memory")

#define MBAR_EXPECT_TX(a, bytes) \
    asm volatile("mbarrier.arrive.expect_tx.shared.b64 _, [%0], %1;" \
                 :: "r"(a), "r"(bytes) : "memory")

#define MBAR_WAIT(a, ph) do {                                                   \
    asm volatile("{\n\t.reg .pred P1;\n\t"                                      \
        "WL_%=:\n\t"                                                            \
        "mbarrier.try_wait.parity.acquire.cta.shared::cta.b64 P1, [%0], %1, 0x989680;\n\t" \
        "@P1 bra.uni WD_%=;\n\t"                                                \
        "bra.uni WL_%=;\n\t"                                                    \
        "WD_%=:\n\t}"                                                           \
        :: "r"(a), "r"(ph) : "memory");                                         \
} while (0)

#define TMA3(smem, mapref, x, y, z, mb) \
    asm volatile("cp.async.bulk.tensor.3d.shared::cta.global.tile.mbarrier::complete_tx::bytes " \
        "[%0], [%1, {%2, %3, %4}], [%5];" \
        :: "r"(smem), "l"(&(mapref)), "r"(x), "r"(y), "r"(z), "r"(mb) : "memory")

__device__ __forceinline__ void mma_f16_ss(uint32_t d, uint64_t a, uint64_t b,
                                           uint32_t idesc, uint32_t en) {
    asm volatile("{\n\t.reg .pred p;\n\tsetp.ne.u32 p, %5, 0;\n\t"
        "tcgen05.mma.cta_group::1.kind::f16 [%0], %1, %2, %3, {%4,%4,%4,%4}, p;\n\t}"
        :: "r"(d), "l"(a), "l"(b), "r"(idesc), "r"(0u), "r"(en) : "memory");
}

// SW128 K-major smem descriptor (layout=2, version=1, SBO=64, LBO=1)
__device__ __forceinline__ uint64_t mk_desc(uint32_t addr) {
    const uint64_t base = (uint64_t(2) << 61) | (uint64_t(1) << 46)
                        | (uint64_t(64) << 32) | (uint64_t(1) << 16);
    return base | ((uint64_t)(addr >> 4) & 0x3FFF);
}

// idesc: f32 accum, bf16 a/b, M=128, N=128
#define IDESC_F16_128x128 0x8200490u
#else
// ---- legacy mma.sync helpers (fallback path) ----
#define LDSM4(R, ptr) do {                                                     \
    unsigned _a = (unsigned)__cvta_generic_to_shared(ptr);                     \
    asm volatile("ldmatrix.sync.aligned.m8n8.x4.shared.b16 {%0,%1,%2,%3}, [%4];" \
        : "=r"((R)[0]), "=r"((R)[1]), "=r"((R)[2]), "=r"((R)[3]) : "r"(_a));   \
} while (0)

#define MMA16816(C, A, B0, B1)                                                 \
    asm volatile("mma.sync.aligned.m16n8k16.row.col.f32.bf16.bf16.f32 "       \
        "{%0,%1,%2,%3},{%4,%5,%6,%7},{%8,%9},{%0,%1,%2,%3};"                  \
        : "+f"((C)[0]), "+f"((C)[1]), "+f"((C)[2]), "+f"((C)[3])              \
        : "r"((A)[0]), "r"((A)[1]), "r"((A)[2]), "r"((A)[3]),                 \
          "r"(B0), "r"(B1))
#endif

// ---------------- merged split fp32 -> bf16 hi/lo (+ qcnt zeroing) -----------
__global__ __launch_bounds__(256)
void split_all(const float* __restrict__ q, const float* __restrict__ k,
               const float* __restrict__ v, const float* __restrict__ wq,
               const float* __restrict__ wk, const float* __restrict__ wv,
               const float* __restrict__ wo)
{
    const int bid = blockIdx.x;
    if (bid < 16) g_qcnt[bid * 256 + threadIdx.x] = 0;   // fused zero_qcnt
    const float* src;
    __nv_bfloat16 *hi, *lo;
    int i4;
    if (bid < 6144) {
        const int z = bid >> 11;
        src = (z == 0) ? q : (z == 1) ? k : v;
        hi = g_INhi + (size_t)z * IN_ELEMS;
        lo = g_INlo + (size_t)z * IN_ELEMS;
        i4 = (bid & 2047) * 256 + threadIdx.x;
    } else {
        const int z = (bid - 6144) >> 8;
        src = (z == 0) ? wq : (z == 1) ? wk : (z == 2) ? wv : wo;
        hi = g_Whi + (size_t)z * W_ELEMS;
        lo = g_Wlo + (size_t)z * W_ELEMS;
        i4 = ((bid - 6144) & 255) * 256 + threadIdx.x;
    }
    float4 val = ((const float4*)src)[i4];
    __nv_bfloat16 h0 = __float2bfloat16(val.x);
    __nv_bfloat16 h1 = __float2bfloat16(val.y);
    __nv_bfloat16 h2 = __float2bfloat16(val.z);
    __nv_bfloat16 h3 = __float2bfloat16(val.w);
    __nv_bfloat16 l0 = __float2bfloat16(val.x - __bfloat162float(h0));
    __nv_bfloat16 l1 = __float2bfloat16(val.y - __bfloat162float(h1));
    __nv_bfloat16 l2 = __float2bfloat16(val.z - __bfloat162float(h2));
    __nv_bfloat16 l3 = __float2bfloat16(val.w - __bfloat162float(h3));
    uint2 hp, lp;
    hp.x = (unsigned)__bfloat16_as_ushort(h0) | ((unsigned)__bfloat16_as_ushort(h1) << 16);
    hp.y = (unsigned)__bfloat16_as_ushort(h2) | ((unsigned)__bfloat16_as_ushort(h3) << 16);
    lp.x = (unsigned)__bfloat16_as_ushort(l0) | ((unsigned)__bfloat16_as_ushort(l1) << 16);
    lp.y = (unsigned)__bfloat16_as_ushort(l2) | ((unsigned)__bfloat16_as_ushort(l3) << 16);
    *(uint2*)(hi + 4 * (size_t)i4) = hp;
    *(uint2*)(lo + 4 * (size_t)i4) = lp;
}

// ---------------- exact fp32 bin-coordinate GEMM -----------------------------
// 64 tokens/block, 4 outputs/thread; per-output K order identical to the
// original (sequential k, x/y/z/w) -> bit-identical coordinates.
__global__ __launch_bounds__(256)
void bincoord_kernel(const float* __restrict__ q, const float* __restrict__ k,
                     const float* __restrict__ Wq, const float* __restrict__ Wk,
                     const float* __restrict__ bq, const float* __restrict__ bk)
{
    __shared__ float Ws[16][512];
    __shared__ float bs[16];
    const int z = blockIdx.y;
    const float* A = z ? k : q;
    const float* W = z ? Wk : Wq;
    const float* bias = z ? bk : bq;
    float* out = z ? g_Ck : g_Cq;

    for (int i = threadIdx.x; i < 16 * 512; i += 256) {
        int j = i >> 9, kk = i & 511;
        int wrow = (j >> 1) * 64 + (j & 1);
        Ws[j][kk] = W[(size_t)wrow * 512 + kk];
    }
    if (threadIdx.x < 16) {
        int j = threadIdx.x;
        bs[j] = bias[(j >> 1) * 64 + (j & 1)];
    }
    __syncthreads();

    const int tl = threadIdx.x >> 2;          // token within block (0..63)
    const int jg = (threadIdx.x & 3) * 4;     // output group base (0,4,8,12)
    const int token = blockIdx.x * 64 + tl;
    float acc[4] = { 0.f, 0.f, 0.f, 0.f };
    const float4* Ar = (const float4*)(A + (size_t)token * 512);
    for (int kk = 0; kk < 128; kk++) {
        float4 a = Ar[kk];
#pragma unroll
        for (int j = 0; j < 4; j++) {
            acc[j] = fmaf(a.x, Ws[jg + j][4 * kk + 0], acc[j]);
            acc[j] = fmaf(a.y, Ws[jg + j][4 * kk + 1], acc[j]);
            acc[j] = fmaf(a.z, Ws[jg + j][4 * kk + 2], acc[j]);
            acc[j] = fmaf(a.w, Ws[jg + j][4 * kk + 3], acc[j]);
        }
    }
#pragma unroll
    for (int j = 0; j < 4; j++)
        out[(size_t)token * 16 + jg + j] = acc[j] + bs[jg + j];
}

// ---------------- GEMM: C = A*W^T + bias (3-term bf16 split) ----------------
// tcgen05 + TMA, depth-3 pipeline (M=128, N=128, K chunks of 64).
// MODE 0 fuses the Poincare projection + binning + query bucketing into the
// epilogue (the 128x128 tile covers 128 tokens x 2 complete heads).
template <int MODE>
__global__ __launch_bounds__(256)
void tc_gemm(const __grid_constant__ CUtensorMap tAhi,
             const __grid_constant__ CUtensorMap tAlo,
             const __grid_constant__ CUtensorMap tWhi,
             const __grid_constant__ CUtensorMap tWlo,
             const float* __restrict__ b0, const float* __restrict__ b1,
             const float* __restrict__ b2, float* __restrict__ outp)
{
    extern __shared__ __align__(1024) char smem[];
    const int tid = threadIdx.x;
    const int wid = tid >> 5;
    const int lid = tid & 31;

    const int z = blockIdx.z;
    const float* bias;
    float* outQ;
    if (MODE == 0) {
        bias = (z == 0) ? b0 : (z == 1) ? b1 : b2;
        outQ = (z == 0) ? g_Q : (z == 1) ? g_K : g_V;
    } else {
        bias = b0;
        outQ = outp;
    }
    const int m0 = blockIdx.x * 128;
    const int n0 = blockIdx.y * 128;

#if HAS_TCGEN05
    const int zA = (MODE == 0) ? z : 0;
    const int zW = (MODE == 0) ? z : 3;
    const uint32_t sb = smem_u32(smem);
    const uint32_t bufB = sb + 1024;

    if (wid == 0) {
        asm volatile("tcgen05.alloc.cta_group::1.sync.aligned.shared::cta.b32 [%0], %1;"
                     :: "r"(sb), "r"(128u) : "memory");
        asm volatile("tcgen05.relinquish_alloc_permit.cta_group::1.sync.aligned;");
    }
    if (tid == 0) {
        MBAR_INIT(sb + 8, 1);  MBAR_INIT(sb + 16, 1); MBAR_INIT(sb + 24, 1); // data
        MBAR_INIT(sb + 32, 1); MBAR_INIT(sb + 40, 1); MBAR_INIT(sb + 48, 1); // mma
    }
    __syncthreads();
    uint32_t tmem;
    asm volatile("ld.shared.b32 %0, [%1];" : "=r"(tmem) : "r"(sb));

    if (wid == 0 && elect_one()) {
        const uint32_t dmb[3] = { sb + 8, sb + 16, sb + 24 };
        const uint32_t mmb[3] = { sb + 32, sb + 40, sb + 48 };

        auto stage = [&](int b, int chunk) {
            const uint32_t bb = bufB + (uint32_t)b * 65536;
            MBAR_EXPECT_TX(dmb[b], 65536u);
            TMA3(bb,         tAhi, chunk * 64, m0, zA, dmb[b]);
            TMA3(bb + 16384, tAlo, chunk * 64, m0, zA, dmb[b]);
            TMA3(bb + 32768, tWhi, chunk * 64, n0, zW, dmb[b]);
            TMA3(bb + 49152, tWlo, chunk * 64, n0, zW, dmb[b]);
        };

        stage(0, 0);
        stage(1, 1);
        stage(2, 2);
        int dph[3] = {0, 0, 0}, mph[3] = {0, 0, 0};

        for (int c = 0; c < 8; c++) {
            const int b = c % 3;
            MBAR_WAIT(dmb[b], dph[b]); dph[b] ^= 1;
            const uint32_t bb = bufB + (uint32_t)b * 65536;
            const uint64_t dAh = mk_desc(bb);
            const uint64_t dAl = mk_desc(bb + 16384);
            const uint64_t dBh = mk_desc(bb + 32768);
            const uint64_t dBl = mk_desc(bb + 49152);
#pragma unroll
            for (int k16 = 0; k16 < 4; k16++) {
                const uint64_t o = k16 * 2;
                mma_f16_ss(tmem, dAh + o, dBh + o, IDESC_F16_128x128,
                           (c == 0 && k16 == 0) ? 0u : 1u);
                mma_f16_ss(tmem, dAh + o, dBl + o, IDESC_F16_128x128, 1u);
                mma_f16_ss(tmem, dAl + o, dBh + o, IDESC_F16_128x128, 1u);
            }
            asm volatile(
                "tcgen05.commit.cta_group::1.mbarrier::arrive::one.shared::cluster.b64 [%0];"
                :: "r"(mmb[b]) : "memory");
            if (c >= 1 && c + 2 < 8) {
                const int pb = (c - 1) % 3;
                MBAR_WAIT(mmb[pb], mph[pb]); mph[pb] ^= 1;
                stage(pb, c + 2);
            }
        }
        MBAR_WAIT(mmb[2], mph[2]); mph[2] ^= 1;
        MBAR_WAIT(mmb[0], mph[0]); mph[0] ^= 1;
        MBAR_WAIT(mmb[1], mph[1]); mph[1] ^= 1;
    }
    __syncthreads();
    asm volatile("tcgen05.fence::after_thread_sync;" ::: "memory");

    // ---- pass 1: TMEM -> smem tile (raw accumulators) ----
    float* sT = (float*)(smem + 1024);
    {
        const int trow = (wid & 3) * 32 + lid;
        const int cbase = (wid >> 2) * 64;
#pragma unroll
        for (int cb = 0; cb < 64; cb += 32) {
            uint32_t r[32];
            asm volatile(
                "tcgen05.ld.sync.aligned.32x32b.x32.b32 "
                "{%0,%1,%2,%3,%4,%5,%6,%7,%8,%9,%10,%11,%12,%13,%14,%15,"
                "%16,%17,%18,%19,%20,%21,%22,%23,%24,%25,%26,%27,%28,%29,%30,%31}, [%32];"
                : "=r"(r[0]), "=r"(r[1]), "=r"(r[2]), "=r"(r[3]),
                  "=r"(r[4]), "=r"(r[5]), "=r"(r[6]), "=r"(r[7]),
                  "=r"(r[8]), "=r"(r[9]), "=r"(r[10]), "=r"(r[11]),
                  "=r"(r[12]), "=r"(r[13]), "=r"(r[14]), "=r"(r[15]),
                  "=r"(r[16]), "=r"(r[17]), "=r"(r[18]), "=r"(r[19]),
                  "=r"(r[20]), "=r"(r[21]), "=r"(r[22]), "=r"(r[23]),
                  "=r"(r[24]), "=r"(r[25]), "=r"(r[26]), "=r"(r[27]),
                  "=r"(r[28]), "=r"(r[29]), "=r"(r[30]), "=r"(r[31])
                : "r"(tmem + cbase + cb));
            asm volatile("tcgen05.wait::ld.sync.aligned;" ::: "memory");
#pragma unroll
            for (int j = 0; j < 32; j++)
                sT[trow * EPI_STRIDE + cbase + cb + j] = __uint_as_float(r[j]);
        }
    }
    __syncthreads();

    // ---- pass 2 (MODE 0): bias + Poincare scale + bin + bucket, in smem ----
    if (MODE == 0) {
        const int r = tid >> 1;            // token row within tile
        const int hh = tid & 1;            // which head half of the tile
        const int gh = (n0 >> 6) + hh;     // global head
        const int token = m0 + r;
        float* rowp = &sT[r * EPI_STRIDE + hh * 64];
        const float* bp = &bias[hh * 64];

        float ss = 0.f;
#pragma unroll
        for (int j4 = 0; j4 < 16; j4++) {
            float4 v = *(float4*)&rowp[j4 * 4];
            const float4 b4 = *(const float4*)&bp[n0 + j4 * 4];
            v.x += b4.x; v.y += b4.y; v.z += b4.z; v.w += b4.w;
            if (z < 2) {
                ss = fmaf(v.x, v.x, ss); ss = fmaf(v.y, v.y, ss);
                ss = fmaf(v.z, v.z, ss); ss = fmaf(v.w, v.w, ss);
            }
            *(float4*)&rowp[j4 * 4] = v;
        }
        if (z < 2) {
            const float nrm = sqrtf(ss);
            const float s = fminf(1.0f, 0.99999f / fmaxf(nrm, 1e-12f));
#pragma unroll
            for (int j4 = 0; j4 < 16; j4++) {
                float4 v = *(float4*)&rowp[j4 * 4];
                v.x *= s; v.y *= s; v.z *= s; v.w *= s;
                *(float4*)&rowp[j4 * 4] = v;
            }
            const float* C = (z == 0) ? g_Cq : g_Ck;
            const float c0 = C[(size_t)token * 16 + 2 * gh];
            const float c1 = C[(size_t)token * 16 + 2 * gh + 1];
            float ang = atan2f(c1, c0);
            float t = (ang / 6.28318530717958647692f + 0.5f) * 512.0f;
            if (fabsf(t - rintf(t)) < 4e-3f) {
                ang = (float)atan2((double)c1, (double)c0);
                t = (ang / 6.28318530717958647692f + 0.5f) * 512.0f;
            }
            int b = (int)floorf(t);
            b = (b < 0) ? 0 : ((b > NBINS_C - 1) ? NBINS_C - 1 : b);
            if (z == 0) {
                const int hb = (gh << 9) + b;
                const int idx = atomicAdd(&g_qcnt[hb], 1);
                if (idx < QCAP) g_qlist[(size_t)hb * QCAP + idx] = (short)token;
            } else {
                g_kb[gh * N_TOK + token] = b;
            }
        }
    }
    __syncthreads();

    // ---- pass 3: coalesced float4 stores (bias already applied for MODE 0) --
    for (int i = tid; i < 128 * 32; i += 256) {
        const int row = i >> 5;
        const int col = (i & 31) * 4;
        float4 v = *(float4*)&sT[row * EPI_STRIDE + col];
        const int gcol = n0 + col;
        if (MODE == 1) {
            const float4 bb4 = *(const float4*)&bias[gcol];
            v.x += bb4.x; v.y += bb4.y; v.z += bb4.z; v.w += bb4.w;
            *(float4*)&outQ[(size_t)(m0 + row) * 512 + gcol] = v;
        } else {
            const int h = gcol >> 6, dd = gcol & 63;
            *(float4*)&outQ[((size_t)((h << 12) + m0 + row)) * 64 + dd] = v;
        }
    }
    __syncthreads();
    if (wid == 0) {
        asm volatile("tcgen05.dealloc.cta_group::1.sync.aligned.b32 %0, %1;"
                     :: "r"(tmem), "r"(128u));
    }
#else
    // ---- fallback: mma.sync path (compile-completeness only) ----
    const __nv_bfloat16 *Ahi, *Alo, *Whi, *Wlo;
    if (MODE == 0) {
        Ahi = g_INhi + (size_t)z * IN_ELEMS;
        Alo = g_INlo + (size_t)z * IN_ELEMS;
        Whi = g_Whi + (size_t)z * W_ELEMS;
        Wlo = g_Wlo + (size_t)z * W_ELEMS;
    } else {
        Ahi = g_AOhi; Alo = g_AOlo;
        Whi = g_Whi + (size_t)3 * W_ELEMS;
        Wlo = g_Wlo + (size_t)3 * W_ELEMS;
    }
    unsigned short* As = (unsigned short*)smem;
    unsigned short* Bs = (unsigned short*)(smem + 16384);
    const int wm = wid >> 1;
    const int wn = wid & 1;

    float acc[2][8][4];
#pragma unroll
    for (int a = 0; a < 2; a++)
#pragma unroll
        for (int b = 0; b < 8; b++)
#pragma unroll
            for (int c = 0; c < 4; c++) acc[a][b][c] = 0.f;

    for (int kt = 0; kt < D_MODEL; kt += 32) {
#pragma unroll
        for (int i = 0; i < 8; i++) {
            const int cid = tid + i * 256;
            const int which = cid >> 9;
            const int r = (cid >> 2) & 127;
            const int kc = cid & 3;
            const __nv_bfloat16* base =
                (which == 0) ? Ahi : (which == 1) ? Alo : (which == 2) ? Whi : Wlo;
            const int grow = ((which < 2) ? m0 : n0) + r;
            uint4 v = *(const uint4*)(base + (size_t)grow * 512 + kt + kc * 8);
            unsigned short* db = (which < 2) ? As : Bs;
            const int sc = (kc + ((which & 1) << 2)) ^ (r & 7);
            *(uint4*)(db + r * 64 + sc * 8) = v;
        }
        __syncthreads();

#pragma unroll
        for (int k16 = 0; k16 < 2; k16++) {
            unsigned ah[2][4], al[2][4], bh[4][4], bl[4][4];
#pragma unroll
            for (int mi = 0; mi < 2; mi++) {
                const int r = wm * 32 + mi * 16 + (lid & 15);
                const int kc = 2 * k16 + (lid >> 4);
                LDSM4(ah[mi], As + r * 64 + ((kc) ^ (r & 7)) * 8);
                LDSM4(al[mi], As + r * 64 + ((kc + 4) ^ (r & 7)) * 8);
            }
#pragma unroll
            for (int p = 0; p < 4; p++) {
                const int r = wn * 64 + p * 16 + ((lid >> 4) << 3) + (lid & 7);
                const int kc = 2 * k16 + ((lid >> 3) & 1);
                LDSM4(bh[p], Bs + r * 64 + ((kc) ^ (r & 7)) * 8);
                LDSM4(bl[p], Bs + r * 64 + ((kc + 4) ^ (r & 7)) * 8);
            }
#pragma unroll
            for (int mi = 0; mi < 2; mi++)
#pragma unroll
                for (int nj = 0; nj < 8; nj++) {
                    const int p = nj >> 1, o = (nj & 1) * 2;
                    MMA16816(acc[mi][nj], ah[mi], bh[p][o], bh[p][o + 1]);
                    MMA16816(acc[mi][nj], ah[mi], bl[p][o], bl[p][o + 1]);
                    MMA16816(acc[mi][nj], al[mi], bh[p][o], bh[p][o + 1]);
                }
        }
        __syncthreads();
    }

#pragma unroll
    for (int mi = 0; mi < 2; mi++)
#pragma unroll
        for (int nj = 0; nj < 8; nj++) {
            const int row = m0 + wm * 32 + mi * 16 + (lid >> 2);
            const int col = n0 + wn * 64 + nj * 8 + (lid & 3) * 2;
            const float bx = bias[col], by = bias[col + 1];
            float2 v0 = make_float2(acc[mi][nj][0] + bx, acc[mi][nj][1] + by);
            float2 v1 = make_float2(acc[mi][nj][2] + bx, acc[mi][nj][3] + by);
            if (MODE == 0) {
                const int h = col >> 6, d = col & 63;
                *(float2*)&outQ[((size_t)((h << 12) + row)) * 64 + d] = v0;
                *(float2*)&outQ[((size_t)((h << 12) + row + 8)) * 64 + d] = v1;
            } else {
                *(float2*)&outQ[(size_t)row * 512 + col] = v0;
                *(float2*)&outQ[(size_t)(row + 8) * 512 + col] = v1;
            }
        }
#endif
}

// ---------------- candidate lists per (head, bin) ---------------------------
// 512 threads / 16 bins per block; vectorized kb load; two-phase ballot +
// scan + bit-extract (identical output to the R13 version).
__global__ __launch_bounds__(512)
void cand_kernel()
{
    __shared__ short kbs[N_TOK];
    __shared__ unsigned words[16][128];
    const int h    = blockIdx.x >> 5;          // 32 blocks per head
    const int bin0 = (blockIdx.x & 31) * 16;
    for (int i = threadIdx.x; i < N_TOK / 4; i += 512) {
        const int4 v = ((const int4*)(g_kb + h * N_TOK))[i];
        kbs[i * 4 + 0] = (short)v.x;
        kbs[i * 4 + 1] = (short)v.y;
        kbs[i * 4 + 2] = (short)v.z;
        kbs[i * 4 + 3] = (short)v.w;
    }
    __syncthreads();

    const int warp = threadIdx.x >> 5;   // 0..15
    const int lane = threadIdx.x & 31;
    const int b = bin0 + warp;
    short* dst = g_cand + ((size_t)h * NBINS_C + b) * CAND_C;

    // phase 1: 128 independent ballots
#pragma unroll 4
    for (int w = 0; w < 128; w++) {
        const int kv = (int)kbs[w * 32 + lane];
        const int d = kv - b;
        const unsigned bal = __ballot_sync(0xffffffffu, (d >= -1) && (d <= 1));
        if (lane == (w & 31)) words[warp][w] = bal;
    }
    __syncwarp();

    // phase 2: per-lane counts over 4 words, warp exclusive scan
    unsigned w0 = words[warp][lane * 4 + 0];
    unsigned w1 = words[warp][lane * 4 + 1];
    unsigned w2 = words[warp][lane * 4 + 2];
    unsigned w3 = words[warp][lane * 4 + 3];
    const int myc = __popc(w0) + __popc(w1) + __popc(w2) + __popc(w3);
    int ex = myc;
#pragma unroll
    for (int o = 1; o < 32; o <<= 1) {
        const int v = __shfl_up_sync(0xffffffffu, ex, o);
        if (lane >= o) ex += v;
    }
    const int total = __shfl_sync(0xffffffffu, ex, 31);
    ex -= myc;  // exclusive prefix

    if (ex < CAND_C && myc > 0) {
        int base = ex;
        const int k0 = lane * 128;
        unsigned ws[4] = { w0, w1, w2, w3 };
#pragma unroll
        for (int wi = 0; wi < 4; wi++) {
            unsigned word = ws[wi];
            while (word && base < CAND_C) {
                const int bit = __ffs(word) - 1;
                dst[base] = (short)(k0 + wi * 32 + bit);
                word &= word - 1;
                base++;
            }
        }
    }
    if (lane == 0)
        g_cnt[h * NBINS_C + b] = (total > CAND_C) ? CAND_C : total;
}

// ---------------- bucketed sparse attention ----------------------------------
__global__ __launch_bounds__(256)
void attn_kernel()
{
    __shared__ float Ks[CAND_C * 68];
    __shared__ float Vs[CAND_C * 68];
    __shared__ float qs[8][64];
    __shared__ float ws[8][64];
    __shared__ short cl[CAND_C];

    const int hb = blockIdx.x;
    int nq = g_qcnt[hb];
    if (nq == 0) return;
    if (nq > QCAP) nq = QCAP;

    const int h = hb >> 9;
    const int tid = threadIdx.x;
    const int wid = tid >> 5;
    const int lane = tid & 31;

    const int cnt = g_cnt[hb];
    const int c = (cnt == 0) ? CAND_C : cnt;
    if (tid < CAND_C) {
        short v = (short)tid;
        if (cnt > 0) v = (tid < cnt) ? g_cand[(size_t)hb * CAND_C + tid] : (short)0;
        cl[tid] = v;
    }
    __syncthreads();

    for (int i = tid; i < c * 16; i += 256) {
        const int r = i >> 4, seg = i & 15;
        const size_t gro = ((size_t)(h << 12) + cl[r]) * 64 + seg * 4;
        *(float4*)&Ks[r * 68 + seg * 4] = *(const float4*)&g_K[gro];
        *(float4*)&Vs[r * 68 + seg * 4] = *(const float4*)&g_V[gro];
    }
    __syncthreads();

    for (int qi = wid; qi < nq; qi += 8) {
        const int q = (int)g_qlist[(size_t)hb * QCAP + qi];
        const float* qrow = g_Q + ((size_t)(h << 12) + q) * 64;
        qs[wid][lane] = qrow[lane];
        qs[wid][lane + 32] = qrow[lane + 32];
        __syncwarp();

        float s0 = -INFINITY, s1 = -INFINITY;
        {
            float a0 = 0.f, a1 = 0.f;
            const bool v0 = (lane < c), v1 = (lane + 32 < c);
#pragma unroll
            for (int d4 = 0; d4 < 16; d4++) {
                const float4 qv = *(const float4*)&qs[wid][d4 * 4];
                if (v0) {
                    const float4 kv = *(const float4*)&Ks[lane * 68 + d4 * 4];
                    a0 = fmaf(qv.x, kv.x, a0); a0 = fmaf(qv.y, kv.y, a0);
                    a0 = fmaf(qv.z, kv.z, a0); a0 = fmaf(qv.w, kv.w, a0);
                }
                if (v1) {
                    const float4 kv = *(const float4*)&Ks[(lane + 32) * 68 + d4 * 4];
                    a1 = fmaf(qv.x, kv.x, a1); a1 = fmaf(qv.y, kv.y, a1);
                    a1 = fmaf(qv.z, kv.z, a1); a1 = fmaf(qv.w, kv.w, a1);
                }
            }
            if (v0) s0 = a0 * 0.125f;
            if (v1) s1 = a1 * 0.125f;
        }

        float m = fmaxf(s0, s1);
#pragma unroll
        for (int o = 16; o; o >>= 1) m = fmaxf(m, __shfl_xor_sync(0xffffffffu, m, o));
        const float e0 = expf(s0 - m);
        const float e1 = expf(s1 - m);
        float ssum = e0 + e1;
#pragma unroll
        for (int o = 16; o; o >>= 1) ssum += __shfl_xor_sync(0xffffffffu, ssum, o);
        const float inv = 1.0f / ssum;
        ws[wid][lane] = e0 * inv;
        ws[wid][lane + 32] = e1 * inv;
        __syncwarp();

        float a0 = 0.f, a1 = 0.f;
        for (int c2 = 0; c2 < c; c2++) {
            const float wv = ws[wid][c2];
            a0 = fmaf(wv, Vs[c2 * 68 + lane], a0);
            a1 = fmaf(wv, Vs[c2 * 68 + lane + 32], a1);
        }

        const int ch = (h << 6) + lane;
        __nv_bfloat16 h0 = __float2bfloat16(a0);
        __nv_bfloat16 h1 = __float2bfloat16(a1);
        g_AOhi[(size_t)q * 512 + ch]      = h0;
        g_AOhi[(size_t)q * 512 + ch + 32] = h1;
        g_AOlo[(size_t)q * 512 + ch]      = __float2bfloat16(a0 - __bfloat162float(h0));
        g_AOlo[(size_t)q * 512 + ch + 32] = __float2bfloat16(a1 - __bfloat162float(h1));
    }
}

// ---------------- host: tensor-map construction ------------------------------
typedef CUresult (*PFN_encodeTiled)(
    CUtensorMap*, CUtensorMapDataType, cuuint32_t, void*,
    const cuuint64_t*, const cuuint64_t*, const cuuint32_t*, const cuuint32_t*,
    CUtensorMapInterleave, CUtensorMapSwizzle, CUtensorMapL2promotion,
    CUtensorMapFloatOOBfill);

static PFN_encodeTiled get_encoder()
{
    static PFN_encodeTiled fn = nullptr;
    if (!fn) {
        void* p = nullptr;
        cudaDriverEntryPointQueryResult st;
        cudaGetDriverEntryPoint("cuTensorMapEncodeTiled", &p,
                                cudaEnableDefault, &st);
        fn = (PFN_encodeTiled)p;
    }
    return fn;
}

static void make_map(CUtensorMap* m, void* ptr, uint64_t d0, uint64_t d1,
                     uint64_t d2, uint32_t bx, uint32_t by)
{
    cuuint64_t dims[3] = { d0, d1, d2 };
    cuuint64_t strides[2] = { d0 * 2, d0 * d1 * 2 };
    cuuint32_t box[3] = { bx, by, 1 };
    cuuint32_t es[3] = { 1, 1, 1 };
    get_encoder()(m, CU_TENSOR_MAP_DATA_TYPE_BFLOAT16, 3, ptr,
                  dims, strides, box, es,
                  CU_TENSOR_MAP_INTERLEAVE_NONE, CU_TENSOR_MAP_SWIZZLE_128B,
                  CU_TENSOR_MAP_L2_PROMOTION_L2_128B,
                  CU_TENSOR_MAP_FLOAT_OOB_FILL_NONE);
}

// ---------------- launch -----------------------------------------------------
extern "C" void kernel_launch(void* const* d_in, const int* in_sizes, int n_in,
                              void* d_out, int out_size)
{
    const float* query = (const float*)d_in[0];
    const float* key   = (const float*)d_in[1];
    const float* value = (const float*)d_in[2];
    const float* Wq    = (const float*)d_in[3];
    const float* bq    = (const float*)d_in[4];
    const float* Wk    = (const float*)d_in[5];
    const float* bk    = (const float*)d_in[6];
    const float* Wv    = (const float*)d_in[7];
    const float* bv    = (const float*)d_in[8];
    const float* Wo    = (const float*)d_in[9];
    const float* bo    = (const float*)d_in[10];
    float* out = (float*)d_out;

    const int SMEM_GEMM = 1024 + 3 * 65536;   // 197632 bytes
    static int attr_done = 0;
    if (!attr_done) {
        cudaFuncSetAttribute(tc_gemm<0>, cudaFuncAttributeMaxDynamicSharedMemorySize, SMEM_GEMM);
        cudaFuncSetAttribute(tc_gemm<1>, cudaFuncAttributeMaxDynamicSharedMemorySize, SMEM_GEMM);
        attr_done = 1;
    }

    void *p_inhi, *p_inlo, *p_whi, *p_wlo, *p_aohi, *p_aolo;
    cudaGetSymbolAddress(&p_inhi, g_INhi);
    cudaGetSymbolAddress(&p_inlo, g_INlo);
    cudaGetSymbolAddress(&p_whi,  g_Whi);
    cudaGetSymbolAddress(&p_wlo,  g_Wlo);
    cudaGetSymbolAddress(&p_aohi, g_AOhi);
    cudaGetSymbolAddress(&p_aolo, g_AOlo);

    CUtensorMap tInHi, tInLo, tWHi, tWLo, tAoHi, tAoLo;
    make_map(&tInHi, p_inhi, 512, 4096, 3, 64, 128);
    make_map(&tInLo, p_inlo, 512, 4096, 3, 64, 128);
    make_map(&tWHi,  p_whi,  512, 512,  4, 64, 128);
    make_map(&tWLo,  p_wlo,  512, 512,  4, 64, 128);
    make_map(&tAoHi, p_aohi, 512, 4096, 1, 64, 128);
    make_map(&tAoLo, p_aolo, 512, 4096, 1, 64, 128);

    split_all<<<7168, 256>>>(query, key, value, Wq, Wk, Wv, Wo);
    bincoord_kernel<<<dim3(64, 2), 256>>>(query, key, Wq, Wk, bq, bk);
    tc_gemm<0><<<dim3(32, 4, 3), 256, SMEM_GEMM>>>(tInHi, tInLo, tWHi, tWLo,
                                                   bq, bk, bv, nullptr);
    cand_kernel<<<256, 512>>>();
    attn_kernel<<<4096, 256>>>();
    tc_gemm<1><<<dim3(32, 4, 1), 256, SMEM_GEMM>>>(tAoHi, tAoLo, tWHi, tWLo,
                                                   bo, nullptr, nullptr, out);
}

// round 15
// speedup vs baseline: 1.1969x; 1.0030x over previous
#include <cuda_runtime.h>
#include <cuda.h>
#include <cuda_bf16.h>
#include <math.h>
#include <stdint.h>

#define N_TOK   4096
#define D_MODEL 512
#define N_HEADS 8
#define HEAD_DIM 64
#define NBINS_C 512
#define CAND_C  64
#define QCAP    512
#define IN_ELEMS (N_TOK * D_MODEL)
#define W_ELEMS  (D_MODEL * D_MODEL)
#define EPI_STRIDE 132   // multiple of 4 -> float4-aligned rows

// Compile-time feature gate: tcgen05 is only legal in arch-specific passes.
#if defined(__CUDA_ARCH__)
#if defined(__CUDA_ARCH_FEAT_SM103_ALL) || defined(__CUDA_ARCH_FEAT_SM100_ALL)
#define HAS_TCGEN05 1
#elif defined(__CUDA_ARCH_SPECIFIC__) && (__CUDA_ARCH__ >= 1000)
#define HAS_TCGEN05 1
#elif defined(__CUDA_ARCH_FAMILY_SPECIFIC__) && (__CUDA_ARCH__ >= 1000)
#define HAS_TCGEN05 1
#else
#define HAS_TCGEN05 0
#endif
#else
#define HAS_TCGEN05 0
#endif

// ---------------- scratch (device globals: allocation-free) ----------------
static __device__ float g_Q[N_HEADS * N_TOK * HEAD_DIM];   // [h][n][d], projected
static __device__ float g_K[N_HEADS * N_TOK * HEAD_DIM];
static __device__ float g_V[N_HEADS * N_TOK * HEAD_DIM];
static __device__ int   g_kb[N_HEADS * N_TOK];
static __device__ short g_cand[N_HEADS * NBINS_C * CAND_C];
static __device__ int   g_cnt[N_HEADS * NBINS_C];

// query buckets per (head, bin)
static __device__ int   g_qcnt[N_HEADS * NBINS_C];
static __device__ short g_qlist[N_HEADS * NBINS_C * QCAP];

// bf16 split operands
static __device__ __align__(1024) __nv_bfloat16 g_INhi[3 * IN_ELEMS];
static __device__ __align__(1024) __nv_bfloat16 g_INlo[3 * IN_ELEMS];
static __device__ __align__(1024) __nv_bfloat16 g_Whi[4 * W_ELEMS];
static __device__ __align__(1024) __nv_bfloat16 g_Wlo[4 * W_ELEMS];
static __device__ __align__(1024) __nv_bfloat16 g_AOhi[IN_ELEMS];
static __device__ __align__(1024) __nv_bfloat16 g_AOlo[IN_ELEMS];

// exact fp32 bin coordinates: [token][2*h + {0,1}]
static __device__ float g_Cq[N_TOK * 16];
static __device__ float g_Ck[N_TOK * 16];

// ---------------- PTX helpers ------------------------------------------------
__device__ __forceinline__ uint32_t smem_u32(const void* p) {
    uint32_t a;
    asm("{ .reg .u64 t; cvta.to.shared.u64 t, %1; cvt.u32.u64 %0, t; }"
        : "=r"(a) : "l"(p));
    return a;
}

#define SW128(x) ((x) ^ (((x) >> 3) & 0x70))

#if HAS_TCGEN05
__device__ __forceinline__ uint32_t elect_one() {
    uint32_t pred;
    asm volatile("{\n\t.reg .pred p;\n\telect.sync _|p, 0xFFFFFFFF;\n\t"
                 "selp.b32 %0, 1, 0, p;\n\t}" : "=r"(pred));
    return pred;
}

#define MBAR_INIT(a, c) \
    asm volatile("mbarrier.init.shared.b64 [%0], %1;" :: "r"(a), "r"(c) : "memory")

#define MBAR_EXPECT_TX(a, bytes) \
    asm volatile("mbarrier.arrive.expect_tx.shared.b64 _, [%0], %1;" \
                 :: "r"(a), "r"(bytes) : "memory")

#define MBAR_WAIT(a, ph) do {                                                   \
    asm volatile("{\n\t.reg .pred P1;\n\t"                                      \
        "WL_%=:\n\t"                                                            \
        "mbarrier.try_wait.parity.acquire.cta.shared::cta.b64 P1, [%0], %1, 0x989680;\n\t" \
        "@P1 bra.uni WD_%=;\n\t"                                                \
        "bra.uni WL_%=;\n\t"                                                    \
        "WD_%=:\n\t}"                                                           \
        :: "r"(a), "r"(ph) : "memory");                                         \
} while (0)

#define TMA3(smem, mapref, x, y, z, mb) \
    asm volatile("cp.async.bulk.tensor.3d.shared::cta.global.tile.mbarrier::complete_tx::bytes " \
        "[%0], [%1, {%2, %3, %4}], [%5];" \
        :: "r"(smem), "l"(&(mapref)), "r"(x), "r"(y), "r"(z), "r"(mb) : "memory")

__device__ __forceinline__ void mma_f16_ss(uint32_t d, uint64_t a, uint64_t b,
                                           uint32_t idesc, uint32_t en) {
    asm volatile("{\n\t.reg .pred p;\n\tsetp.ne.u32 p, %5, 0;\n\t"
        "tcgen05.mma.cta_group::1.kind::f16 [%0], %1, %2, %3, {%4,%4,%4,%4}, p;\n\t}"
        :: "r"(d), "l"(a), "l"(b), "r"(idesc), "r"(0u), "r"(en) : "memory");
}

// SW128 K-major smem descriptor (layout=2, version=1, SBO=64, LBO=1)
__device__ __forceinline__ uint64_t mk_desc(uint32_t addr) {
    const uint64_t base = (uint64_t(2) << 61) | (uint64_t(1) << 46)
                        | (uint64_t(64) << 32) | (uint64_t(1) << 16);
    return base | ((uint64_t)(addr >> 4) & 0x3FFF);
}

// idesc: f32 accum, bf16 a/b, M=128, N=128
#define IDESC_F16_128x128 0x8200490u
#else
// ---- legacy mma.sync helpers (fallback path) ----
#define LDSM4(R, ptr) do {                                                     \
    unsigned _a = (unsigned)__cvta_generic_to_shared(ptr);                     \
    asm volatile("ldmatrix.sync.aligned.m8n8.x4.shared.b16 {%0,%1,%2,%3}, [%4];" \
        : "=r"((R)[0]), "=r"((R)[1]), "=r"((R)[2]), "=r"((R)[3]) : "r"(_a));   \
} while (0)

#define MMA16816(C, A, B0, B1)                                                 \
    asm volatile("mma.sync.aligned.m16n8k16.row.col.f32.bf16.bf16.f32 "       \
        "{%0,%1,%2,%3},{%4,%5,%6,%7},{%8,%9},{%0,%1,%2,%3};"                  \
        : "+f"((C)[0]), "+f"((C)[1]), "+f"((C)[2]), "+f"((C)[3])              \
        : "r"((A)[0]), "r"((A)[1]), "r"((A)[2]), "r"((A)[3]),                 \
          "r"(B0), "r"(B1))
#endif

// ---------------- merged split fp32 -> bf16 hi/lo (+ qcnt zeroing) -----------
__global__ __launch_bounds__(256)
void split_all(const float* __restrict__ q, const float* __restrict__ k,
               const float* __restrict__ v, const float* __restrict__ wq,
               const float* __restrict__ wk, const float* __restrict__ wv,
               const float* __restrict__ wo)
{
    const int bid = blockIdx.x;
    if (bid < 16) g_qcnt[bid * 256 + threadIdx.x] = 0;   // fused zero_qcnt
    const float* src;
    __nv_bfloat16 *hi, *lo;
    int i4;
    if (bid < 6144) {
        const int z = bid >> 11;
        src = (z == 0) ? q : (z == 1) ? k : v;
        hi = g_INhi + (size_t)z * IN_ELEMS;
        lo = g_INlo + (size_t)z * IN_ELEMS;
        i4 = (bid & 2047) * 256 + threadIdx.x;
    } else {
        const int z = (bid - 6144) >> 8;
        src = (z == 0) ? wq : (z == 1) ? wk : (z == 2) ? wv : wo;
        hi = g_Whi + (size_t)z * W_ELEMS;
        lo = g_Wlo + (size_t)z * W_ELEMS;
        i4 = ((bid - 6144) & 255) * 256 + threadIdx.x;
    }
    float4 val = ((const float4*)src)[i4];
    __nv_bfloat16 h0 = __float2bfloat16(val.x);
    __nv_bfloat16 h1 = __float2bfloat16(val.y);
    __nv_bfloat16 h2 = __float2bfloat16(val.z);
    __nv_bfloat16 h3 = __float2bfloat16(val.w);
    __nv_bfloat16 l0 = __float2bfloat16(val.x - __bfloat162float(h0));
    __nv_bfloat16 l1 = __float2bfloat16(val.y - __bfloat162float(h1));
    __nv_bfloat16 l2 = __float2bfloat16(val.z - __bfloat162float(h2));
    __nv_bfloat16 l3 = __float2bfloat16(val.w - __bfloat162float(h3));
    uint2 hp, lp;
    hp.x = (unsigned)__bfloat16_as_ushort(h0) | ((unsigned)__bfloat16_as_ushort(h1) << 16);
    hp.y = (unsigned)__bfloat16_as_ushort(h2) | ((unsigned)__bfloat16_as_ushort(h3) << 16);
    lp.x = (unsigned)__bfloat16_as_ushort(l0) | ((unsigned)__bfloat16_as_ushort(l1) << 16);
    lp.y = (unsigned)__bfloat16_as_ushort(l2) | ((unsigned)__bfloat16_as_ushort(l3) << 16);
    *(uint2*)(hi + 4 * (size_t)i4) = hp;
    *(uint2*)(lo + 4 * (size_t)i4) = lp;
}

// ---------------- exact fp32 bin-coordinate GEMM -----------------------------
__global__ __launch_bounds__(256)
void bincoord_kernel(const float* __restrict__ q, const float* __restrict__ k,
                     const float* __restrict__ Wq, const float* __restrict__ Wk,
                     const float* __restrict__ bq, const float* __restrict__ bk)
{
    __shared__ float Ws[16][512];
    __shared__ float bs[16];
    const int z = blockIdx.y;
    const float* A = z ? k : q;
    const float* W = z ? Wk : Wq;
    const float* bias = z ? bk : bq;
    float* out = z ? g_Ck : g_Cq;

    for (int i = threadIdx.x; i < 16 * 512; i += 256) {
        int j = i >> 9, kk = i & 511;
        int wrow = (j >> 1) * 64 + (j & 1);
        Ws[j][kk] = W[(size_t)wrow * 512 + kk];
    }
    if (threadIdx.x < 16) {
        int j = threadIdx.x;
        bs[j] = bias[(j >> 1) * 64 + (j & 1)];
    }
    __syncthreads();

    const int tl = threadIdx.x >> 2;
    const int jg = (threadIdx.x & 3) * 4;
    const int token = blockIdx.x * 64 + tl;
    float acc[4] = { 0.f, 0.f, 0.f, 0.f };
    const float4* Ar = (const float4*)(A + (size_t)token * 512);
    for (int kk = 0; kk < 128; kk++) {
        float4 a = Ar[kk];
#pragma unroll
        for (int j = 0; j < 4; j++) {
            acc[j] = fmaf(a.x, Ws[jg + j][4 * kk + 0], acc[j]);
            acc[j] = fmaf(a.y, Ws[jg + j][4 * kk + 1], acc[j]);
            acc[j] = fmaf(a.z, Ws[jg + j][4 * kk + 2], acc[j]);
            acc[j] = fmaf(a.w, Ws[jg + j][4 * kk + 3], acc[j]);
        }
    }
#pragma unroll
    for (int j = 0; j < 4; j++)
        out[(size_t)token * 16 + jg + j] = acc[j] + bs[jg + j];
}

// ---------------- GEMM: C = A*W^T + bias (3-term bf16 split) ----------------
// tcgen05 + TMA, depth-3 pipeline (M=128, N=128, K chunks of 64).
// MODE 0 fuses the Poincare projection + binning + query bucketing into the
// epilogue (the 128x128 tile covers 128 tokens x 2 complete heads).
template <int MODE>
__global__ __launch_bounds__(256)
void tc_gemm(const __grid_constant__ CUtensorMap tAhi,
             const __grid_constant__ CUtensorMap tAlo,
             const __grid_constant__ CUtensorMap tWhi,
             const __grid_constant__ CUtensorMap tWlo,
             const float* __restrict__ b0, const float* __restrict__ b1,
             const float* __restrict__ b2, float* __restrict__ outp)
{
    extern __shared__ __align__(1024) char smem[];
    const int tid = threadIdx.x;
    const int wid = tid >> 5;
    const int lid = tid & 31;

    const int z = blockIdx.z;
    const float* bias;
    float* outQ;
    if (MODE == 0) {
        bias = (z == 0) ? b0 : (z == 1) ? b1 : b2;
        outQ = (z == 0) ? g_Q : (z == 1) ? g_K : g_V;
    } else {
        bias = b0;
        outQ = outp;
    }
    const int m0 = blockIdx.x * 128;
    const int n0 = blockIdx.y * 128;

#if HAS_TCGEN05
    const int zA = (MODE == 0) ? z : 0;
    const int zW = (MODE == 0) ? z : 3;
    const uint32_t sb = smem_u32(smem);
    const uint32_t bufB = sb + 1024;

    if (wid == 0) {
        asm volatile("tcgen05.alloc.cta_group::1.sync.aligned.shared::cta.b32 [%0], %1;"
                     :: "r"(sb), "r"(128u) : "memory");
        asm volatile("tcgen05.relinquish_alloc_permit.cta_group::1.sync.aligned;");
    }
    if (tid == 0) {
        MBAR_INIT(sb + 8, 1);  MBAR_INIT(sb + 16, 1); MBAR_INIT(sb + 24, 1); // data
        MBAR_INIT(sb + 32, 1); MBAR_INIT(sb + 40, 1); MBAR_INIT(sb + 48, 1); // mma
    }
    __syncthreads();
    uint32_t tmem;
    asm volatile("ld.shared.b32 %0, [%1];" : "=r"(tmem) : "r"(sb));

    if (wid == 0 && elect_one()) {
        const uint32_t dmb[3] = { sb + 8, sb + 16, sb + 24 };
        const uint32_t mmb[3] = { sb + 32, sb + 40, sb + 48 };

        auto stage = [&](int b, int chunk) {
            const uint32_t bb = bufB + (uint32_t)b * 65536;
            MBAR_EXPECT_TX(dmb[b], 65536u);
            TMA3(bb,         tAhi, chunk * 64, m0, zA, dmb[b]);
            TMA3(bb + 16384, tAlo, chunk * 64, m0, zA, dmb[b]);
            TMA3(bb + 32768, tWhi, chunk * 64, n0, zW, dmb[b]);
            TMA3(bb + 49152, tWlo, chunk * 64, n0, zW, dmb[b]);
        };

        stage(0, 0);
        stage(1, 1);
        stage(2, 2);
        int dph[3] = {0, 0, 0}, mph[3] = {0, 0, 0};

        for (int c = 0; c < 8; c++) {
            const int b = c % 3;
            MBAR_WAIT(dmb[b], dph[b]); dph[b] ^= 1;
            const uint32_t bb = bufB + (uint32_t)b * 65536;
            const uint64_t dAh = mk_desc(bb);
            const uint64_t dAl = mk_desc(bb + 16384);
            const uint64_t dBh = mk_desc(bb + 32768);
            const uint64_t dBl = mk_desc(bb + 49152);
#pragma unroll
            for (int k16 = 0; k16 < 4; k16++) {
                const uint64_t o = k16 * 2;
                mma_f16_ss(tmem, dAh + o, dBh + o, IDESC_F16_128x128,
                           (c == 0 && k16 == 0) ? 0u : 1u);
                mma_f16_ss(tmem, dAh + o, dBl + o, IDESC_F16_128x128, 1u);
                mma_f16_ss(tmem, dAl + o, dBh + o, IDESC_F16_128x128, 1u);
            }
            asm volatile(
                "tcgen05.commit.cta_group::1.mbarrier::arrive::one.shared::cluster.b64 [%0];"
                :: "r"(mmb[b]) : "memory");
            if (c >= 1 && c + 2 < 8) {
                const int pb = (c - 1) % 3;
                MBAR_WAIT(mmb[pb], mph[pb]); mph[pb] ^= 1;
                stage(pb, c + 2);
            }
        }
        MBAR_WAIT(mmb[2], mph[2]); mph[2] ^= 1;
        MBAR_WAIT(mmb[0], mph[0]); mph[0] ^= 1;
        MBAR_WAIT(mmb[1], mph[1]); mph[1] ^= 1;
    }
    __syncthreads();
    asm volatile("tcgen05.fence::after_thread_sync;" ::: "memory");

    // ---- pass 1: TMEM -> smem tile (raw accumulators) ----
    float* sT = (float*)(smem + 1024);
    {
        const int trow = (wid & 3) * 32 + lid;
        const int cbase = (wid >> 2) * 64;
#pragma unroll
        for (int cb = 0; cb < 64; cb += 32) {
            uint32_t r[32];
            asm volatile(
                "tcgen05.ld.sync.aligned.32x32b.x32.b32 "
                "{%0,%1,%2,%3,%4,%5,%6,%7,%8,%9,%10,%11,%12,%13,%14,%15,"
                "%16,%17,%18,%19,%20,%21,%22,%23,%24,%25,%26,%27,%28,%29,%30,%31}, [%32];"
                : "=r"(r[0]), "=r"(r[1]), "=r"(r[2]), "=r"(r[3]),
                  "=r"(r[4]), "=r"(r[5]), "=r"(r[6]), "=r"(r[7]),
                  "=r"(r[8]), "=r"(r[9]), "=r"(r[10]), "=r"(r[11]),
                  "=r"(r[12]), "=r"(r[13]), "=r"(r[14]), "=r"(r[15]),
                  "=r"(r[16]), "=r"(r[17]), "=r"(r[18]), "=r"(r[19]),
                  "=r"(r[20]), "=r"(r[21]), "=r"(r[22]), "=r"(r[23]),
                  "=r"(r[24]), "=r"(r[25]), "=r"(r[26]), "=r"(r[27]),
                  "=r"(r[28]), "=r"(r[29]), "=r"(r[30]), "=r"(r[31])
                : "r"(tmem + cbase + cb));
            asm volatile("tcgen05.wait::ld.sync.aligned;" ::: "memory");
#pragma unroll
            for (int j = 0; j < 32; j++)
                sT[trow * EPI_STRIDE + cbase + cb + j] = __uint_as_float(r[j]);
        }
    }
    __syncthreads();

    // ---- pass 2 (MODE 0): bias + Poincare scale + bin + bucket, in smem ----
    if (MODE == 0) {
        const int r = tid >> 1;
        const int hh = tid & 1;
        const int gh = (n0 >> 6) + hh;
        const int token = m0 + r;
        float* rowp = &sT[r * EPI_STRIDE + hh * 64];
        const float* bp = &bias[hh * 64];

        float ss = 0.f;
#pragma unroll
        for (int j4 = 0; j4 < 16; j4++) {
            float4 v = *(float4*)&rowp[j4 * 4];
            const float4 b4 = *(const float4*)&bp[n0 + j4 * 4];
            v.x += b4.x; v.y += b4.y; v.z += b4.z; v.w += b4.w;
            if (z < 2) {
                ss = fmaf(v.x, v.x, ss); ss = fmaf(v.y, v.y, ss);
                ss = fmaf(v.z, v.z, ss); ss = fmaf(v.w, v.w, ss);
            }
            *(float4*)&rowp[j4 * 4] = v;
        }
        if (z < 2) {
            const float nrm = sqrtf(ss);
            const float s = fminf(1.0f, 0.99999f / fmaxf(nrm, 1e-12f));
#pragma unroll
            for (int j4 = 0; j4 < 16; j4++) {
                float4 v = *(float4*)&rowp[j4 * 4];
                v.x *= s; v.y *= s; v.z *= s; v.w *= s;
                *(float4*)&rowp[j4 * 4] = v;
            }
            const float* C = (z == 0) ? g_Cq : g_Ck;
            const float c0 = C[(size_t)token * 16 + 2 * gh];
            const float c1 = C[(size_t)token * 16 + 2 * gh + 1];
            float ang = atan2f(c1, c0);
            float t = (ang / 6.28318530717958647692f + 0.5f) * 512.0f;
            if (fabsf(t - rintf(t)) < 4e-3f) {
                ang = (float)atan2((double)c1, (double)c0);
                t = (ang / 6.28318530717958647692f + 0.5f) * 512.0f;
            }
            int b = (int)floorf(t);
            b = (b < 0) ? 0 : ((b > NBINS_C - 1) ? NBINS_C - 1 : b);
            if (z == 0) {
                const int hb = (gh << 9) + b;
                const int idx = atomicAdd(&g_qcnt[hb], 1);
                if (idx < QCAP) g_qlist[(size_t)hb * QCAP + idx] = (short)token;
            } else {
                g_kb[gh * N_TOK + token] = b;
            }
        }
    }
    __syncthreads();

    // ---- pass 3: coalesced float4 stores (bias already applied for MODE 0) --
    for (int i = tid; i < 128 * 32; i += 256) {
        const int row = i >> 5;
        const int col = (i & 31) * 4;
        float4 v = *(float4*)&sT[row * EPI_STRIDE + col];
        const int gcol = n0 + col;
        if (MODE == 1) {
            const float4 bb4 = *(const float4*)&bias[gcol];
            v.x += bb4.x; v.y += bb4.y; v.z += bb4.z; v.w += bb4.w;
            *(float4*)&outQ[(size_t)(m0 + row) * 512 + gcol] = v;
        } else {
            const int h = gcol >> 6, dd = gcol & 63;
            *(float4*)&outQ[((size_t)((h << 12) + m0 + row)) * 64 + dd] = v;
        }
    }
    __syncthreads();
    if (wid == 0) {
        asm volatile("tcgen05.dealloc.cta_group::1.sync.aligned.b32 %0, %1;"
                     :: "r"(tmem), "r"(128u));
    }
#else
    // ---- fallback: mma.sync path (compile-completeness only) ----
    const __nv_bfloat16 *Ahi, *Alo, *Whi, *Wlo;
    if (MODE == 0) {
        Ahi = g_INhi + (size_t)z * IN_ELEMS;
        Alo = g_INlo + (size_t)z * IN_ELEMS;
        Whi = g_Whi + (size_t)z * W_ELEMS;
        Wlo = g_Wlo + (size_t)z * W_ELEMS;
    } else {
        Ahi = g_AOhi; Alo = g_AOlo;
        Whi = g_Whi + (size_t)3 * W_ELEMS;
        Wlo = g_Wlo + (size_t)3 * W_ELEMS;
    }
    unsigned short* As = (unsigned short*)smem;
    unsigned short* Bs = (unsigned short*)(smem + 16384);
    const int wm = wid >> 1;
    const int wn = wid & 1;

    float acc[2][8][4];
#pragma unroll
    for (int a = 0; a < 2; a++)
#pragma unroll
        for (int b = 0; b < 8; b++)
#pragma unroll
            for (int c = 0; c < 4; c++) acc[a][b][c] = 0.f;

    for (int kt = 0; kt < D_MODEL; kt += 32) {
#pragma unroll
        for (int i = 0; i < 8; i++) {
            const int cid = tid + i * 256;
            const int which = cid >> 9;
            const int r = (cid >> 2) & 127;
            const int kc = cid & 3;
            const __nv_bfloat16* base =
                (which == 0) ? Ahi : (which == 1) ? Alo : (which == 2) ? Whi : Wlo;
            const int grow = ((which < 2) ? m0 : n0) + r;
            uint4 v = *(const uint4*)(base + (size_t)grow * 512 + kt + kc * 8);
            unsigned short* db = (which < 2) ? As : Bs;
            const int sc = (kc + ((which & 1) << 2)) ^ (r & 7);
            *(uint4*)(db + r * 64 + sc * 8) = v;
        }
        __syncthreads();

#pragma unroll
        for (int k16 = 0; k16 < 2; k16++) {
            unsigned ah[2][4], al[2][4], bh[4][4], bl[4][4];
#pragma unroll
            for (int mi = 0; mi < 2; mi++) {
                const int r = wm * 32 + mi * 16 + (lid & 15);
                const int kc = 2 * k16 + (lid >> 4);
                LDSM4(ah[mi], As + r * 64 + ((kc) ^ (r & 7)) * 8);
                LDSM4(al[mi], As + r * 64 + ((kc + 4) ^ (r & 7)) * 8);
            }
#pragma unroll
            for (int p = 0; p < 4; p++) {
                const int r = wn * 64 + p * 16 + ((lid >> 4) << 3) + (lid & 7);
                const int kc = 2 * k16 + ((lid >> 3) & 1);
                LDSM4(bh[p], Bs + r * 64 + ((kc) ^ (r & 7)) * 8);
                LDSM4(bl[p], Bs + r * 64 + ((kc + 4) ^ (r & 7)) * 8);
            }
#pragma unroll
            for (int mi = 0; mi < 2; mi++)
#pragma unroll
                for (int nj = 0; nj < 8; nj++) {
                    const int p = nj >> 1, o = (nj & 1) * 2;
                    MMA16816(acc[mi][nj], ah[mi], bh[p][o], bh[p][o + 1]);
                    MMA16816(acc[mi][nj], ah[mi], bl[p][o], bl[p][o + 1]);
                    MMA16816(acc[mi][nj], al[mi], bh[p][o], bh[p][o + 1]);
                }
        }
        __syncthreads();
    }

#pragma unroll
    for (int mi = 0; mi < 2; mi++)
#pragma unroll
        for (int nj = 0; nj < 8; nj++) {
            const int row = m0 + wm * 32 + mi * 16 + (lid >> 2);
            const int col = n0 + wn * 64 + nj * 8 + (lid & 3) * 2;
            const float bx = bias[col], by = bias[col + 1];
            float2 v0 = make_float2(acc[mi][nj][0] + bx, acc[mi][nj][1] + by);
            float2 v1 = make_float2(acc[mi][nj][2] + bx, acc[mi][nj][3] + by);
            if (MODE == 0) {
                const int h = col >> 6, d = col & 63;
                *(float2*)&outQ[((size_t)((h << 12) + row)) * 64 + d] = v0;
                *(float2*)&outQ[((size_t)((h << 12) + row + 8)) * 64 + d] = v1;
            } else {
                *(float2*)&outQ[(size_t)row * 512 + col] = v0;
                *(float2*)&outQ[(size_t)(row + 8) * 512 + col] = v1;
            }
        }
#endif
}

// ---------------- candidate lists per (head, bin) ---------------------------
// 256 threads / 8 bins per block (512 blocks, good wave balance); int4 kb
// loads; register-resident ballot words (lane j keeps words 4j..4j+3);
// warp scan + bit-extract. Output identical to prior rounds.
__global__ __launch_bounds__(256)
void cand_kernel()
{
    __shared__ short kbs[N_TOK];
    const int h    = blockIdx.x >> 6;          // 64 blocks per head
    const int bin0 = (blockIdx.x & 63) * 8;
    for (int i = threadIdx.x; i < N_TOK / 4; i += 256) {
        const int4 v = ((const int4*)(g_kb + h * N_TOK))[i];
        kbs[i * 4 + 0] = (short)v.x;
        kbs[i * 4 + 1] = (short)v.y;
        kbs[i * 4 + 2] = (short)v.z;
        kbs[i * 4 + 3] = (short)v.w;
    }
    __syncthreads();

    const int warp = threadIdx.x >> 5;   // 0..7
    const int lane = threadIdx.x & 31;
    const int b = bin0 + warp;
    short* dst = g_cand + ((size_t)h * NBINS_C + b) * CAND_C;

    // phase 1: 128 independent ballots; lane j captures words w = 4j+i
    unsigned ws[4];
#pragma unroll
    for (int i = 0; i < 4; i++) {
        unsigned cap = 0;
#pragma unroll 8
        for (int j = 0; j < 32; j++) {
            const int w = j * 4 + i;
            const int kv = (int)kbs[w * 32 + lane];
            const int d = kv - b;
            const unsigned bal = __ballot_sync(0xffffffffu, (d >= -1) && (d <= 1));
            if (j == lane) cap = bal;
        }
        ws[i] = cap;
    }

    // phase 2: per-lane counts over 4 words, warp exclusive scan
    const int myc = __popc(ws[0]) + __popc(ws[1]) + __popc(ws[2]) + __popc(ws[3]);
    int ex = myc;
#pragma unroll
    for (int o = 1; o < 32; o <<= 1) {
        const int v = __shfl_up_sync(0xffffffffu, ex, o);
        if (lane >= o) ex += v;
    }
    const int total = __shfl_sync(0xffffffffu, ex, 31);
    ex -= myc;  // exclusive prefix

    // lane j owns keys [j*128, (j+1)*128): word i covers keys j*128+i*... NO:
    // word w = j*4+i covers keys [w*32, w*32+32) = [(4j+i)*32, ...).
    if (ex < CAND_C && myc > 0) {
        int base = ex;
#pragma unroll
        for (int i = 0; i < 4; i++) {
            unsigned word = ws[i];
            const int k0 = (lane * 4 + i) * 32;
            while (word && base < CAND_C) {
                const int bit = __ffs(word) - 1;
                dst[base] = (short)(k0 + bit);
                word &= word - 1;
                base++;
            }
        }
    }
    if (lane == 0)
        g_cnt[h * NBINS_C + b] = (total > CAND_C) ? CAND_C : total;
}

// ---------------- bucketed sparse attention ----------------------------------
__global__ __launch_bounds__(256)
void attn_kernel()
{
    __shared__ float Ks[CAND_C * 68];
    __shared__ float Vs[CAND_C * 68];
    __shared__ float qs[8][64];
    __shared__ float ws[8][64];
    __shared__ short cl[CAND_C];

    const int hb = blockIdx.x;
    int nq = g_qcnt[hb];
    if (nq == 0) return;
    if (nq > QCAP) nq = QCAP;

    const int h = hb >> 9;
    const int tid = threadIdx.x;
    const int wid = tid >> 5;
    const int lane = tid & 31;

    const int cnt = g_cnt[hb];
    const int c = (cnt == 0) ? CAND_C : cnt;
    if (tid < CAND_C) {
        short v = (short)tid;
        if (cnt > 0) v = (tid < cnt) ? g_cand[(size_t)hb * CAND_C + tid] : (short)0;
        cl[tid] = v;
    }
    __syncthreads();

    for (int i = tid; i < c * 16; i += 256) {
        const int r = i >> 4, seg = i & 15;
        const size_t gro = ((size_t)(h << 12) + cl[r]) * 64 + seg * 4;
        *(float4*)&Ks[r * 68 + seg * 4] = *(const float4*)&g_K[gro];
        *(float4*)&Vs[r * 68 + seg * 4] = *(const float4*)&g_V[gro];
    }
    __syncthreads();

    for (int qi = wid; qi < nq; qi += 8) {
        const int q = (int)g_qlist[(size_t)hb * QCAP + qi];
        const float* qrow = g_Q + ((size_t)(h << 12) + q) * 64;
        qs[wid][lane] = qrow[lane];
        qs[wid][lane + 32] = qrow[lane + 32];
        __syncwarp();

        float s0 = -INFINITY, s1 = -INFINITY;
        {
            float a0 = 0.f, a1 = 0.f;
            const bool v0 = (lane < c), v1 = (lane + 32 < c);
#pragma unroll
            for (int d4 = 0; d4 < 16; d4++) {
                const float4 qv = *(const float4*)&qs[wid][d4 * 4];
                if (v0) {
                    const float4 kv = *(const float4*)&Ks[lane * 68 + d4 * 4];
                    a0 = fmaf(qv.x, kv.x, a0); a0 = fmaf(qv.y, kv.y, a0);
                    a0 = fmaf(qv.z, kv.z, a0); a0 = fmaf(qv.w, kv.w, a0);
                }
                if (v1) {
                    const float4 kv = *(const float4*)&Ks[(lane + 32) * 68 + d4 * 4];
                    a1 = fmaf(qv.x, kv.x, a1); a1 = fmaf(qv.y, kv.y, a1);
                    a1 = fmaf(qv.z, kv.z, a1); a1 = fmaf(qv.w, kv.w, a1);
                }
            }
            if (v0) s0 = a0 * 0.125f;
            if (v1) s1 = a1 * 0.125f;
        }

        float m = fmaxf(s0, s1);
#pragma unroll
        for (int o = 16; o; o >>= 1) m = fmaxf(m, __shfl_xor_sync(0xffffffffu, m, o));
        const float e0 = expf(s0 - m);
        const float e1 = expf(s1 - m);
        float ssum = e0 + e1;
#pragma unroll
        for (int o = 16; o; o >>= 1) ssum += __shfl_xor_sync(0xffffffffu, ssum, o);
        const float inv = 1.0f / ssum;
        ws[wid][lane] = e0 * inv;
        ws[wid][lane + 32] = e1 * inv;
        __syncwarp();

        float a0 = 0.f, a1 = 0.f;
        for (int c2 = 0; c2 < c; c2++) {
            const float wv = ws[wid][c2];
            a0 = fmaf(wv, Vs[c2 * 68 + lane], a0);
            a1 = fmaf(wv, Vs[c2 * 68 + lane + 32], a1);
        }

        const int ch = (h << 6) + lane;
        __nv_bfloat16 h0 = __float2bfloat16(a0);
        __nv_bfloat16 h1 = __float2bfloat16(a1);
        g_AOhi[(size_t)q * 512 + ch]      = h0;
        g_AOhi[(size_t)q * 512 + ch + 32] = h1;
        g_AOlo[(size_t)q * 512 + ch]      = __float2bfloat16(a0 - __bfloat162float(h0));
        g_AOlo[(size_t)q * 512 + ch + 32] = __float2bfloat16(a1 - __bfloat162float(h1));
    }
}

// ---------------- host: tensor-map construction ------------------------------
typedef CUresult (*PFN_encodeTiled)(
    CUtensorMap*, CUtensorMapDataType, cuuint32_t, void*,
    const cuuint64_t*, const cuuint64_t*, const cuuint32_t*, const cuuint32_t*,
    CUtensorMapInterleave, CUtensorMapSwizzle, CUtensorMapL2promotion,
    CUtensorMapFloatOOBfill);

static PFN_encodeTiled get_encoder()
{
    static PFN_encodeTiled fn = nullptr;
    if (!fn) {
        void* p = nullptr;
        cudaDriverEntryPointQueryResult st;
        cudaGetDriverEntryPoint("cuTensorMapEncodeTiled", &p,
                                cudaEnableDefault, &st);
        fn = (PFN_encodeTiled)p;
    }
    return fn;
}

static void make_map(CUtensorMap* m, void* ptr, uint64_t d0, uint64_t d1,
                     uint64_t d2, uint32_t bx, uint32_t by)
{
    cuuint64_t dims[3] = { d0, d1, d2 };
    cuuint64_t strides[2] = { d0 * 2, d0 * d1 * 2 };
    cuuint32_t box[3] = { bx, by, 1 };
    cuuint32_t es[3] = { 1, 1, 1 };
    get_encoder()(m, CU_TENSOR_MAP_DATA_TYPE_BFLOAT16, 3, ptr,
                  dims, strides, box, es,
                  CU_TENSOR_MAP_INTERLEAVE_NONE, CU_TENSOR_MAP_SWIZZLE_128B,
                  CU_TENSOR_MAP_L2_PROMOTION_L2_128B,
                  CU_TENSOR_MAP_FLOAT_OOB_FILL_NONE);
}

// ---------------- launch -----------------------------------------------------
extern "C" void kernel_launch(void* const* d_in, const int* in_sizes, int n_in,
                              void* d_out, int out_size)
{
    const float* query = (const float*)d_in[0];
    const float* key   = (const float*)d_in[1];
    const float* value = (const float*)d_in[2];
    const float* Wq    = (const float*)d_in[3];
    const float* bq    = (const float*)d_in[4];
    const float* Wk    = (const float*)d_in[5];
    const float* bk    = (const float*)d_in[6];
    const float* Wv    = (const float*)d_in[7];
    const float* bv    = (const float*)d_in[8];
    const float* Wo    = (const float*)d_in[9];
    const float* bo    = (const float*)d_in[10];
    float* out = (float*)d_out;

    const int SMEM_GEMM = 1024 + 3 * 65536;   // 197632 bytes
    static int attr_done = 0;
    if (!attr_done) {
        cudaFuncSetAttribute(tc_gemm<0>, cudaFuncAttributeMaxDynamicSharedMemorySize, SMEM_GEMM);
        cudaFuncSetAttribute(tc_gemm<1>, cudaFuncAttributeMaxDynamicSharedMemorySize, SMEM_GEMM);
        attr_done = 1;
    }

    void *p_inhi, *p_inlo, *p_whi, *p_wlo, *p_aohi, *p_aolo;
    cudaGetSymbolAddress(&p_inhi, g_INhi);
    cudaGetSymbolAddress(&p_inlo, g_INlo);
    cudaGetSymbolAddress(&p_whi,  g_Whi);
    cudaGetSymbolAddress(&p_wlo,  g_Wlo);
    cudaGetSymbolAddress(&p_aohi, g_AOhi);
    cudaGetSymbolAddress(&p_aolo, g_AOlo);

    CUtensorMap tInHi, tInLo, tWHi, tWLo, tAoHi, tAoLo;
    make_map(&tInHi, p_inhi, 512, 4096, 3, 64, 128);
    make_map(&tInLo, p_inlo, 512, 4096, 3, 64, 128);
    make_map(&tWHi,  p_whi,  512, 512,  4, 64, 128);
    make_map(&tWLo,  p_wlo,  512, 512,  4, 64, 128);
    make_map(&tAoHi, p_aohi, 512, 4096, 1, 64, 128);
    make_map(&tAoLo, p_aolo, 512, 4096, 1, 64, 128);

    split_all<<<7168, 256>>>(query, key, value, Wq, Wk, Wv, Wo);
    bincoord_kernel<<<dim3(64, 2), 256>>>(query, key, Wq, Wk, bq, bk);
    tc_gemm<0><<<dim3(32, 4, 3), 256, SMEM_GEMM>>>(tInHi, tInLo, tWHi, tWLo,
                                                   bq, bk, bv, nullptr);
    cand_kernel<<<512, 256>>>();
    attn_kernel<<<4096, 256>>>();
    tc_gemm<1><<<dim3(32, 4, 1), 256, SMEM_GEMM>>>(tAoHi, tAoLo, tWHi, tWLo,
                                                   bo, nullptr, nullptr, out);
}

// round 16
// speedup vs baseline: 1.2284x; 1.0263x over previous
#include <cuda_runtime.h>
#include <cuda.h>
#include <cuda_bf16.h>
#include <math.h>
#include <stdint.h>

#define N_TOK   4096
#define D_MODEL 512
#define N_HEADS 8
#define HEAD_DIM 64
#define NBINS_C 512
#define CAND_C  64
#define QCAP    512
#define IN_ELEMS (N_TOK * D_MODEL)
#define W_ELEMS  (D_MODEL * D_MODEL)
#define EPI_STRIDE 132   // multiple of 4 -> float4-aligned rows

// Compile-time feature gate: tcgen05 is only legal in arch-specific passes.
#if defined(__CUDA_ARCH__)
#if defined(__CUDA_ARCH_FEAT_SM103_ALL) || defined(__CUDA_ARCH_FEAT_SM100_ALL)
#define HAS_TCGEN05 1
#elif defined(__CUDA_ARCH_SPECIFIC__) && (__CUDA_ARCH__ >= 1000)
#define HAS_TCGEN05 1
#elif defined(__CUDA_ARCH_FAMILY_SPECIFIC__) && (__CUDA_ARCH__ >= 1000)
#define HAS_TCGEN05 1
#else
#define HAS_TCGEN05 0
#endif
#else
#define HAS_TCGEN05 0
#endif

// ---------------- scratch (device globals: allocation-free) ----------------
static __device__ float g_Q[N_HEADS * N_TOK * HEAD_DIM];   // [h][n][d], projected
static __device__ float g_K[N_HEADS * N_TOK * HEAD_DIM];
static __device__ float g_V[N_HEADS * N_TOK * HEAD_DIM];
static __device__ int   g_kb[N_HEADS * N_TOK];
static __device__ short g_cand[N_HEADS * NBINS_C * CAND_C];
static __device__ int   g_cnt[N_HEADS * NBINS_C];

// query buckets per (head, bin)
static __device__ int   g_qcnt[N_HEADS * NBINS_C];
static __device__ short g_qlist[N_HEADS * NBINS_C * QCAP];

// bf16 split operands
static __device__ __align__(1024) __nv_bfloat16 g_INhi[3 * IN_ELEMS];
static __device__ __align__(1024) __nv_bfloat16 g_INlo[3 * IN_ELEMS];
static __device__ __align__(1024) __nv_bfloat16 g_Whi[4 * W_ELEMS];
static __device__ __align__(1024) __nv_bfloat16 g_Wlo[4 * W_ELEMS];
static __device__ __align__(1024) __nv_bfloat16 g_AOhi[IN_ELEMS];
static __device__ __align__(1024) __nv_bfloat16 g_AOlo[IN_ELEMS];

// exact fp32 bin coordinates: [token][2*h + {0,1}]
static __device__ float g_Cq[N_TOK * 16];
static __device__ float g_Ck[N_TOK * 16];

// ---------------- PTX helpers ------------------------------------------------
__device__ __forceinline__ uint32_t smem_u32(const void* p) {
    uint32_t a;
    asm("{ .reg .u64 t; cvta.to.shared.u64 t, %1; cvt.u32.u64 %0, t; }"
        : "=r"(a) : "l"(p));
    return a;
}

#define SW128(x) ((x) ^ (((x) >> 3) & 0x70))

#if HAS_TCGEN05
__device__ __forceinline__ uint32_t elect_one() {
    uint32_t pred;
    asm volatile("{\n\t.reg .pred p;\n\telect.sync _|p, 0xFFFFFFFF;\n\t"
                 "selp.b32 %0, 1, 0, p;\n\t}" : "=r"(pred));
    return pred;
}

#define MBAR_INIT(a, c) \
    asm volatile("mbarrier.init.shared.b64 [%0], %1;" :: "r"(a), "r"(c) : "memory")

#define MBAR_EXPECT_TX(a, bytes) \
    asm volatile("mbarrier.arrive.expect_tx.shared.b64 _, [%0], %1;" \
                 :: "r"(a), "r"(bytes) : "memory")

#define MBAR_WAIT(a, ph) do {                                                   \
    asm volatile("{\n\t.reg .pred P1;\n\t"                                      \
        "WL_%=:\n\t"                                                            \
        "mbarrier.try_wait.parity.acquire.cta.shared::cta.b64 P1, [%0], %1, 0x989680;\n\t" \
        "@P1 bra.uni WD_%=;\n\t"                                                \
        "bra.uni WL_%=;\n\t"                                                    \
        "WD_%=:\n\t}"                                                           \
        :: "r"(a), "r"(ph) : "memory");                                         \
} while (0)

#define TMA3(smem, mapref, x, y, z, mb) \
    asm volatile("cp.async.bulk.tensor.3d.shared::cta.global.tile.mbarrier::complete_tx::bytes " \
        "[%0], [%1, {%2, %3, %4}], [%5];" \
        :: "r"(smem), "l"(&(mapref)), "r"(x), "r"(y), "r"(z), "r"(mb) : "memory")

__device__ __forceinline__ void mma_f16_ss(uint32_t d, uint64_t a, uint64_t b,
                                           uint32_t idesc, uint32_t en) {
    asm volatile("{\n\t.reg .pred p;\n\tsetp.ne.u32 p, %5, 0;\n\t"
        "tcgen05.mma.cta_group::1.kind::f16 [%0], %1, %2, %3, {%4,%4,%4,%4}, p;\n\t}"
        :: "r"(d), "l"(a), "l"(b), "r"(idesc), "r"(0u), "r"(en) : "memory");
}

// SW128 K-major smem descriptor (layout=2, version=1, SBO=64, LBO=1)
__device__ __forceinline__ uint64_t mk_desc(uint32_t addr) {
    const uint64_t base = (uint64_t(2) << 61) | (uint64_t(1) << 46)
                        | (uint64_t(64) << 32) | (uint64_t(1) << 16);
    return base | ((uint64_t)(addr >> 4) & 0x3FFF);
}

// idesc: f32 accum, bf16 a/b, M=128, N=128
#define IDESC_F16_128x128 0x8200490u

#define LDTM32(R, addr)                                                        \
    do {                                                                       \
        asm volatile(                                                          \
            "tcgen05.ld.sync.aligned.32x32b.x32.b32 "                          \
            "{%0,%1,%2,%3,%4,%5,%6,%7,%8,%9,%10,%11,%12,%13,%14,%15,"          \
            "%16,%17,%18,%19,%20,%21,%22,%23,%24,%25,%26,%27,%28,%29,%30,%31}, [%32];" \
            : "=r"((R)[0]), "=r"((R)[1]), "=r"((R)[2]), "=r"((R)[3]),          \
              "=r"((R)[4]), "=r"((R)[5]), "=r"((R)[6]), "=r"((R)[7]),          \
              "=r"((R)[8]), "=r"((R)[9]), "=r"((R)[10]), "=r"((R)[11]),        \
              "=r"((R)[12]), "=r"((R)[13]), "=r"((R)[14]), "=r"((R)[15]),      \
              "=r"((R)[16]), "=r"((R)[17]), "=r"((R)[18]), "=r"((R)[19]),      \
              "=r"((R)[20]), "=r"((R)[21]), "=r"((R)[22]), "=r"((R)[23]),      \
              "=r"((R)[24]), "=r"((R)[25]), "=r"((R)[26]), "=r"((R)[27]),      \
              "=r"((R)[28]), "=r"((R)[29]), "=r"((R)[30]), "=r"((R)[31])       \
            : "r"(addr));                                                      \
        asm volatile("tcgen05.wait::ld.sync.aligned;" ::: "memory");           \
    } while (0)
#else
// ---- legacy mma.sync helpers (fallback path) ----
#define LDSM4(R, ptr) do {                                                     \
    unsigned _a = (unsigned)__cvta_generic_to_shared(ptr);                     \
    asm volatile("ldmatrix.sync.aligned.m8n8.x4.shared.b16 {%0,%1,%2,%3}, [%4];" \
        : "=r"((R)[0]), "=r"((R)[1]), "=r"((R)[2]), "=r"((R)[3]) : "r"(_a));   \
} while (0)

#define MMA16816(C, A, B0, B1)                                                 \
    asm volatile("mma.sync.aligned.m16n8k16.row.col.f32.bf16.bf16.f32 "       \
        "{%0,%1,%2,%3},{%4,%5,%6,%7},{%8,%9},{%0,%1,%2,%3};"                  \
        : "+f"((C)[0]), "+f"((C)[1]), "+f"((C)[2]), "+f"((C)[3])              \
        : "r"((A)[0]), "r"((A)[1]), "r"((A)[2]), "r"((A)[3]),                 \
          "r"(B0), "r"(B1))
#endif

// ---------------- merged split fp32 -> bf16 hi/lo (+ qcnt zeroing) -----------
__global__ __launch_bounds__(256)
void split_all(const float* __restrict__ q, const float* __restrict__ k,
               const float* __restrict__ v, const float* __restrict__ wq,
               const float* __restrict__ wk, const float* __restrict__ wv,
               const float* __restrict__ wo)
{
    const int bid = blockIdx.x;
    if (bid < 16) g_qcnt[bid * 256 + threadIdx.x] = 0;   // fused zero_qcnt
    const float* src;
    __nv_bfloat16 *hi, *lo;
    int i4;
    if (bid < 6144) {
        const int z = bid >> 11;
        src = (z == 0) ? q : (z == 1) ? k : v;
        hi = g_INhi + (size_t)z * IN_ELEMS;
        lo = g_INlo + (size_t)z * IN_ELEMS;
        i4 = (bid & 2047) * 256 + threadIdx.x;
    } else {
        const int z = (bid - 6144) >> 8;
        src = (z == 0) ? wq : (z == 1) ? wk : (z == 2) ? wv : wo;
        hi = g_Whi + (size_t)z * W_ELEMS;
        lo = g_Wlo + (size_t)z * W_ELEMS;
        i4 = ((bid - 6144) & 255) * 256 + threadIdx.x;
    }
    float4 val = ((const float4*)src)[i4];
    __nv_bfloat16 h0 = __float2bfloat16(val.x);
    __nv_bfloat16 h1 = __float2bfloat16(val.y);
    __nv_bfloat16 h2 = __float2bfloat16(val.z);
    __nv_bfloat16 h3 = __float2bfloat16(val.w);
    __nv_bfloat16 l0 = __float2bfloat16(val.x - __bfloat162float(h0));
    __nv_bfloat16 l1 = __float2bfloat16(val.y - __bfloat162float(h1));
    __nv_bfloat16 l2 = __float2bfloat16(val.z - __bfloat162float(h2));
    __nv_bfloat16 l3 = __float2bfloat16(val.w - __bfloat162float(h3));
    uint2 hp, lp;
    hp.x = (unsigned)__bfloat16_as_ushort(h0) | ((unsigned)__bfloat16_as_ushort(h1) << 16);
    hp.y = (unsigned)__bfloat16_as_ushort(h2) | ((unsigned)__bfloat16_as_ushort(h3) << 16);
    lp.x = (unsigned)__bfloat16_as_ushort(l0) | ((unsigned)__bfloat16_as_ushort(l1) << 16);
    lp.y = (unsigned)__bfloat16_as_ushort(l2) | ((unsigned)__bfloat16_as_ushort(l3) << 16);
    *(uint2*)(hi + 4 * (size_t)i4) = hp;
    *(uint2*)(lo + 4 * (size_t)i4) = lp;
}

// ---------------- exact fp32 bin-coordinate GEMM -----------------------------
__global__ __launch_bounds__(256)
void bincoord_kernel(const float* __restrict__ q, const float* __restrict__ k,
                     const float* __restrict__ Wq, const float* __restrict__ Wk,
                     const float* __restrict__ bq, const float* __restrict__ bk)
{
    __shared__ float Ws[16][512];
    __shared__ float bs[16];
    const int z = blockIdx.y;
    const float* A = z ? k : q;
    const float* W = z ? Wk : Wq;
    const float* bias = z ? bk : bq;
    float* out = z ? g_Ck : g_Cq;

    for (int i = threadIdx.x; i < 16 * 512; i += 256) {
        int j = i >> 9, kk = i & 511;
        int wrow = (j >> 1) * 64 + (j & 1);
        Ws[j][kk] = W[(size_t)wrow * 512 + kk];
    }
    if (threadIdx.x < 16) {
        int j = threadIdx.x;
        bs[j] = bias[(j >> 1) * 64 + (j & 1)];
    }
    __syncthreads();

    const int tl = threadIdx.x >> 2;
    const int jg = (threadIdx.x & 3) * 4;
    const int token = blockIdx.x * 64 + tl;
    float acc[4] = { 0.f, 0.f, 0.f, 0.f };
    const float4* Ar = (const float4*)(A + (size_t)token * 512);
    for (int kk = 0; kk < 128; kk++) {
        float4 a = Ar[kk];
#pragma unroll
        for (int j = 0; j < 4; j++) {
            acc[j] = fmaf(a.x, Ws[jg + j][4 * kk + 0], acc[j]);
            acc[j] = fmaf(a.y, Ws[jg + j][4 * kk + 1], acc[j]);
            acc[j] = fmaf(a.z, Ws[jg + j][4 * kk + 2], acc[j]);
            acc[j] = fmaf(a.w, Ws[jg + j][4 * kk + 3], acc[j]);
        }
    }
#pragma unroll
    for (int j = 0; j < 4; j++)
        out[(size_t)token * 16 + jg + j] = acc[j] + bs[jg + j];
}

// ---------------- GEMM: C = A*W^T + bias (3-term bf16 split) ----------------
// tcgen05 + TMA, depth-3 pipeline (M=128, N=128, K chunks of 64).
// MODE 0: the epilogue applies bias + Poincare scale + binning + bucketing
// ENTIRELY IN REGISTERS during the TMEM drain (each thread owns one full
// (token, head) row), then stores the final values once. No smem re-read.
template <int MODE>
__global__ __launch_bounds__(256)
void tc_gemm(const __grid_constant__ CUtensorMap tAhi,
             const __grid_constant__ CUtensorMap tAlo,
             const __grid_constant__ CUtensorMap tWhi,
             const __grid_constant__ CUtensorMap tWlo,
             const float* __restrict__ b0, const float* __restrict__ b1,
             const float* __restrict__ b2, float* __restrict__ outp)
{
    extern __shared__ __align__(1024) char smem[];
    const int tid = threadIdx.x;
    const int wid = tid >> 5;
    const int lid = tid & 31;

    const int z = blockIdx.z;
    const float* bias;
    float* outQ;
    if (MODE == 0) {
        bias = (z == 0) ? b0 : (z == 1) ? b1 : b2;
        outQ = (z == 0) ? g_Q : (z == 1) ? g_K : g_V;
    } else {
        bias = b0;
        outQ = outp;
    }
    const int m0 = blockIdx.x * 128;
    const int n0 = blockIdx.y * 128;

#if HAS_TCGEN05
    const int zA = (MODE == 0) ? z : 0;
    const int zW = (MODE == 0) ? z : 3;
    const uint32_t sb = smem_u32(smem);
    const uint32_t bufB = sb + 1024;

    if (wid == 0) {
        asm volatile("tcgen05.alloc.cta_group::1.sync.aligned.shared::cta.b32 [%0], %1;"
                     :: "r"(sb), "r"(128u) : "memory");
        asm volatile("tcgen05.relinquish_alloc_permit.cta_group::1.sync.aligned;");
    }
    if (tid == 0) {
        MBAR_INIT(sb + 8, 1);  MBAR_INIT(sb + 16, 1); MBAR_INIT(sb + 24, 1); // data
        MBAR_INIT(sb + 32, 1); MBAR_INIT(sb + 40, 1); MBAR_INIT(sb + 48, 1); // mma
    }
    __syncthreads();
    uint32_t tmem;
    asm volatile("ld.shared.b32 %0, [%1];" : "=r"(tmem) : "r"(sb));

    if (wid == 0 && elect_one()) {
        const uint32_t dmb[3] = { sb + 8, sb + 16, sb + 24 };
        const uint32_t mmb[3] = { sb + 32, sb + 40, sb + 48 };

        auto stage = [&](int b, int chunk) {
            const uint32_t bb = bufB + (uint32_t)b * 65536;
            MBAR_EXPECT_TX(dmb[b], 65536u);
            TMA3(bb,         tAhi, chunk * 64, m0, zA, dmb[b]);
            TMA3(bb + 16384, tAlo, chunk * 64, m0, zA, dmb[b]);
            TMA3(bb + 32768, tWhi, chunk * 64, n0, zW, dmb[b]);
            TMA3(bb + 49152, tWlo, chunk * 64, n0, zW, dmb[b]);
        };

        stage(0, 0);
        stage(1, 1);
        stage(2, 2);
        int dph[3] = {0, 0, 0}, mph[3] = {0, 0, 0};

        for (int c = 0; c < 8; c++) {
            const int b = c % 3;
            MBAR_WAIT(dmb[b], dph[b]); dph[b] ^= 1;
            const uint32_t bb = bufB + (uint32_t)b * 65536;
            const uint64_t dAh = mk_desc(bb);
            const uint64_t dAl = mk_desc(bb + 16384);
            const uint64_t dBh = mk_desc(bb + 32768);
            const uint64_t dBl = mk_desc(bb + 49152);
#pragma unroll
            for (int k16 = 0; k16 < 4; k16++) {
                const uint64_t o = k16 * 2;
                mma_f16_ss(tmem, dAh + o, dBh + o, IDESC_F16_128x128,
                           (c == 0 && k16 == 0) ? 0u : 1u);
                mma_f16_ss(tmem, dAh + o, dBl + o, IDESC_F16_128x128, 1u);
                mma_f16_ss(tmem, dAl + o, dBh + o, IDESC_F16_128x128, 1u);
            }
            asm volatile(
                "tcgen05.commit.cta_group::1.mbarrier::arrive::one.shared::cluster.b64 [%0];"
                :: "r"(mmb[b]) : "memory");
            if (c >= 1 && c + 2 < 8) {
                const int pb = (c - 1) % 3;
                MBAR_WAIT(mmb[pb], mph[pb]); mph[pb] ^= 1;
                stage(pb, c + 2);
            }
        }
        MBAR_WAIT(mmb[2], mph[2]); mph[2] ^= 1;
        MBAR_WAIT(mmb[0], mph[0]); mph[0] ^= 1;
        MBAR_WAIT(mmb[1], mph[1]); mph[1] ^= 1;
    }
    __syncthreads();
    asm volatile("tcgen05.fence::after_thread_sync;" ::: "memory");

    // ---- epilogue pass 1: TMEM drain + (MODE 0) fused bias/scale/bin -------
    float* sT = (float*)(smem + 1024);
    {
        const int trow = (wid & 3) * 32 + lid;        // tile row (token)
        const int hh = wid >> 2;                      // head half of tile
        const int cbase = hh * 64;

        if (MODE == 0) {
            // each thread owns the full 64-dim row of (token m0+trow, head gh)
            float va[64];
            float ss = 0.f;
#pragma unroll
            for (int cb = 0; cb < 64; cb += 32) {
                uint32_t r[32];
                LDTM32(r, tmem + cbase + cb);
#pragma unroll
                for (int j4 = 0; j4 < 8; j4++) {
                    const float4 b4 =
                        *(const float4*)&bias[n0 + cbase + cb + j4 * 4];
                    float* vp = &va[cb + j4 * 4];
                    vp[0] = __uint_as_float(r[j4 * 4 + 0]) + b4.x;
                    vp[1] = __uint_as_float(r[j4 * 4 + 1]) + b4.y;
                    vp[2] = __uint_as_float(r[j4 * 4 + 2]) + b4.z;
                    vp[3] = __uint_as_float(r[j4 * 4 + 3]) + b4.w;
                    if (z < 2) {
                        ss = fmaf(vp[0], vp[0], ss); ss = fmaf(vp[1], vp[1], ss);
                        ss = fmaf(vp[2], vp[2], ss); ss = fmaf(vp[3], vp[3], ss);
                    }
                }
            }
            if (z < 2) {
                const float nrm = sqrtf(ss);
                const float s = fminf(1.0f, 0.99999f / fmaxf(nrm, 1e-12f));
#pragma unroll
                for (int j = 0; j < 64; j++) va[j] *= s;

                const int gh = (n0 >> 6) + hh;
                const int token = m0 + trow;
                const float* C = (z == 0) ? g_Cq : g_Ck;
                const float c0 = C[(size_t)token * 16 + 2 * gh];
                const float c1 = C[(size_t)token * 16 + 2 * gh + 1];
                float ang = atan2f(c1, c0);
                float t = (ang / 6.28318530717958647692f + 0.5f) * 512.0f;
                if (fabsf(t - rintf(t)) < 4e-3f) {
                    ang = (float)atan2((double)c1, (double)c0);
                    t = (ang / 6.28318530717958647692f + 0.5f) * 512.0f;
                }
                int b = (int)floorf(t);
                b = (b < 0) ? 0 : ((b > NBINS_C - 1) ? NBINS_C - 1 : b);
                if (z == 0) {
                    const int hb = (gh << 9) + b;
                    const int idx = atomicAdd(&g_qcnt[hb], 1);
                    if (idx < QCAP) g_qlist[(size_t)hb * QCAP + idx] = (short)token;
                } else {
                    g_kb[gh * N_TOK + token] = b;
                }
            }
#pragma unroll
            for (int j = 0; j < 64; j++)
                sT[trow * EPI_STRIDE + cbase + j] = va[j];
        } else {
#pragma unroll
            for (int cb = 0; cb < 64; cb += 32) {
                uint32_t r[32];
                LDTM32(r, tmem + cbase + cb);
#pragma unroll
                for (int j = 0; j < 32; j++)
                    sT[trow * EPI_STRIDE + cbase + cb + j] = __uint_as_float(r[j]);
            }
        }
    }
    __syncthreads();

    // ---- pass 3: coalesced float4 stores (bias already applied for MODE 0) --
    for (int i = tid; i < 128 * 32; i += 256) {
        const int row = i >> 5;
        const int col = (i & 31) * 4;
        float4 v = *(float4*)&sT[row * EPI_STRIDE + col];
        const int gcol = n0 + col;
        if (MODE == 1) {
            const float4 bb4 = *(const float4*)&bias[gcol];
            v.x += bb4.x; v.y += bb4.y; v.z += bb4.z; v.w += bb4.w;
            *(float4*)&outQ[(size_t)(m0 + row) * 512 + gcol] = v;
        } else {
            const int h = gcol >> 6, dd = gcol & 63;
            *(float4*)&outQ[((size_t)((h << 12) + m0 + row)) * 64 + dd] = v;
        }
    }
    __syncthreads();
    if (wid == 0) {
        asm volatile("tcgen05.dealloc.cta_group::1.sync.aligned.b32 %0, %1;"
                     :: "r"(tmem), "r"(128u));
    }
#else
    // ---- fallback: mma.sync path (compile-completeness only) ----
    const __nv_bfloat16 *Ahi, *Alo, *Whi, *Wlo;
    if (MODE == 0) {
        Ahi = g_INhi + (size_t)z * IN_ELEMS;
        Alo = g_INlo + (size_t)z * IN_ELEMS;
        Whi = g_Whi + (size_t)z * W_ELEMS;
        Wlo = g_Wlo + (size_t)z * W_ELEMS;
    } else {
        Ahi = g_AOhi; Alo = g_AOlo;
        Whi = g_Whi + (size_t)3 * W_ELEMS;
        Wlo = g_Wlo + (size_t)3 * W_ELEMS;
    }
    unsigned short* As = (unsigned short*)smem;
    unsigned short* Bs = (unsigned short*)(smem + 16384);
    const int wm = wid >> 1;
    const int wn = wid & 1;

    float acc[2][8][4];
#pragma unroll
    for (int a = 0; a < 2; a++)
#pragma unroll
        for (int b = 0; b < 8; b++)
#pragma unroll
            for (int c = 0; c < 4; c++) acc[a][b][c] = 0.f;

    for (int kt = 0; kt < D_MODEL; kt += 32) {
#pragma unroll
        for (int i = 0; i < 8; i++) {
            const int cid = tid + i * 256;
            const int which = cid >> 9;
            const int r = (cid >> 2) & 127;
            const int kc = cid & 3;
            const __nv_bfloat16* base =
                (which == 0) ? Ahi : (which == 1) ? Alo : (which == 2) ? Whi : Wlo;
            const int grow = ((which < 2) ? m0 : n0) + r;
            uint4 v = *(const uint4*)(base + (size_t)grow * 512 + kt + kc * 8);
            unsigned short* db = (which < 2) ? As : Bs;
            const int sc = (kc + ((which & 1) << 2)) ^ (r & 7);
            *(uint4*)(db + r * 64 + sc * 8) = v;
        }
        __syncthreads();

#pragma unroll
        for (int k16 = 0; k16 < 2; k16++) {
            unsigned ah[2][4], al[2][4], bh[4][4], bl[4][4];
#pragma unroll
            for (int mi = 0; mi < 2; mi++) {
                const int r = wm * 32 + mi * 16 + (lid & 15);
                const int kc = 2 * k16 + (lid >> 4);
                LDSM4(ah[mi], As + r * 64 + ((kc) ^ (r & 7)) * 8);
                LDSM4(al[mi], As + r * 64 + ((kc + 4) ^ (r & 7)) * 8);
            }
#pragma unroll
            for (int p = 0; p < 4; p++) {
                const int r = wn * 64 + p * 16 + ((lid >> 4) << 3) + (lid & 7);
                const int kc = 2 * k16 + ((lid >> 3) & 1);
                LDSM4(bh[p], Bs + r * 64 + ((kc) ^ (r & 7)) * 8);
                LDSM4(bl[p], Bs + r * 64 + ((kc + 4) ^ (r & 7)) * 8);
            }
#pragma unroll
            for (int mi = 0; mi < 2; mi++)
#pragma unroll
                for (int nj = 0; nj < 8; nj++) {
                    const int p = nj >> 1, o = (nj & 1) * 2;
                    MMA16816(acc[mi][nj], ah[mi], bh[p][o], bh[p][o + 1]);
                    MMA16816(acc[mi][nj], ah[mi], bl[p][o], bl[p][o + 1]);
                    MMA16816(acc[mi][nj], al[mi], bh[p][o], bh[p][o + 1]);
                }
        }
        __syncthreads();
    }

#pragma unroll
    for (int mi = 0; mi < 2; mi++)
#pragma unroll
        for (int nj = 0; nj < 8; nj++) {
            const int row = m0 + wm * 32 + mi * 16 + (lid >> 2);
            const int col = n0 + wn * 64 + nj * 8 + (lid & 3) * 2;
            const float bx = bias[col], by = bias[col + 1];
            float2 v0 = make_float2(acc[mi][nj][0] + bx, acc[mi][nj][1] + by);
            float2 v1 = make_float2(acc[mi][nj][2] + bx, acc[mi][nj][3] + by);
            if (MODE == 0) {
                const int h = col >> 6, d = col & 63;
                *(float2*)&outQ[((size_t)((h << 12) + row)) * 64 + d] = v0;
                *(float2*)&outQ[((size_t)((h << 12) + row + 8)) * 64 + d] = v1;
            } else {
                *(float2*)&outQ[(size_t)row * 512 + col] = v0;
                *(float2*)&outQ[(size_t)(row + 8) * 512 + col] = v1;
            }
        }
#endif
}

// ---------------- candidate lists per (head, bin) ---------------------------
// 256 threads / 8 bins per block; int4 kb loads; register-resident ballot
// words; warp scan + bit-extract. Output identical to prior rounds.
__global__ __launch_bounds__(256)
void cand_kernel()
{
    __shared__ short kbs[N_TOK];
    const int h    = blockIdx.x >> 6;          // 64 blocks per head
    const int bin0 = (blockIdx.x & 63) * 8;
    for (int i = threadIdx.x; i < N_TOK / 4; i += 256) {
        const int4 v = ((const int4*)(g_kb + h * N_TOK))[i];
        kbs[i * 4 + 0] = (short)v.x;
        kbs[i * 4 + 1] = (short)v.y;
        kbs[i * 4 + 2] = (short)v.z;
        kbs[i * 4 + 3] = (short)v.w;
    }
    __syncthreads();

    const int warp = threadIdx.x >> 5;   // 0..7
    const int lane = threadIdx.x & 31;
    const int b = bin0 + warp;
    short* dst = g_cand + ((size_t)h * NBINS_C + b) * CAND_C;

    // phase 1: 128 independent ballots; lane j captures words w = 4j+i
    unsigned ws[4];
#pragma unroll
    for (int i = 0; i < 4; i++) {
        unsigned cap = 0;
#pragma unroll 8
        for (int j = 0; j < 32; j++) {
            const int w = j * 4 + i;
            const int kv = (int)kbs[w * 32 + lane];
            const int d = kv - b;
            const unsigned bal = __ballot_sync(0xffffffffu, (d >= -1) && (d <= 1));
            if (j == lane) cap = bal;
        }
        ws[i] = cap;
    }

    // phase 2: per-lane counts over 4 words, warp exclusive scan
    const int myc = __popc(ws[0]) + __popc(ws[1]) + __popc(ws[2]) + __popc(ws[3]);
    int ex = myc;
#pragma unroll
    for (int o = 1; o < 32; o <<= 1) {
        const int v = __shfl_up_sync(0xffffffffu, ex, o);
        if (lane >= o) ex += v;
    }
    const int total = __shfl_sync(0xffffffffu, ex, 31);
    ex -= myc;  // exclusive prefix

    if (ex < CAND_C && myc > 0) {
        int base = ex;
#pragma unroll
        for (int i = 0; i < 4; i++) {
            unsigned word = ws[i];
            const int k0 = (lane * 4 + i) * 32;
            while (word && base < CAND_C) {
                const int bit = __ffs(word) - 1;
                dst[base] = (short)(k0 + bit);
                word &= word - 1;
                base++;
            }
        }
    }
    if (lane == 0)
        g_cnt[h * NBINS_C + b] = (total > CAND_C) ? CAND_C : total;
}

// ---------------- bucketed sparse attention ----------------------------------
__global__ __launch_bounds__(256)
void attn_kernel()
{
    __shared__ float Ks[CAND_C * 68];
    __shared__ float Vs[CAND_C * 68];
    __shared__ float qs[8][64];
    __shared__ float ws[8][64];
    __shared__ short cl[CAND_C];

    const int hb = blockIdx.x;
    int nq = g_qcnt[hb];
    if (nq == 0) return;
    if (nq > QCAP) nq = QCAP;

    const int h = hb >> 9;
    const int tid = threadIdx.x;
    const int wid = tid >> 5;
    const int lane = tid & 31;

    const int cnt = g_cnt[hb];
    const int c = (cnt == 0) ? CAND_C : cnt;
    if (tid < CAND_C) {
        short v = (short)tid;
        if (cnt > 0) v = (tid < cnt) ? g_cand[(size_t)hb * CAND_C + tid] : (short)0;
        cl[tid] = v;
    }
    __syncthreads();

    for (int i = tid; i < c * 16; i += 256) {
        const int r = i >> 4, seg = i & 15;
        const size_t gro = ((size_t)(h << 12) + cl[r]) * 64 + seg * 4;
        *(float4*)&Ks[r * 68 + seg * 4] = *(const float4*)&g_K[gro];
        *(float4*)&Vs[r * 68 + seg * 4] = *(const float4*)&g_V[gro];
    }
    __syncthreads();

    for (int qi = wid; qi < nq; qi += 8) {
        const int q = (int)g_qlist[(size_t)hb * QCAP + qi];
        const float* qrow = g_Q + ((size_t)(h << 12) + q) * 64;
        qs[wid][lane] = qrow[lane];
        qs[wid][lane + 32] = qrow[lane + 32];
        __syncwarp();

        float s0 = -INFINITY, s1 = -INFINITY;
        {
            float a0 = 0.f, a1 = 0.f;
            const bool v0 = (lane < c), v1 = (lane + 32 < c);
#pragma unroll
            for (int d4 = 0; d4 < 16; d4++) {
                const float4 qv = *(const float4*)&qs[wid][d4 * 4];
                if (v0) {
                    const float4 kv = *(const float4*)&Ks[lane * 68 + d4 * 4];
                    a0 = fmaf(qv.x, kv.x, a0); a0 = fmaf(qv.y, kv.y, a0);
                    a0 = fmaf(qv.z, kv.z, a0); a0 = fmaf(qv.w, kv.w, a0);
                }
                if (v1) {
                    const float4 kv = *(const float4*)&Ks[(lane + 32) * 68 + d4 * 4];
                    a1 = fmaf(qv.x, kv.x, a1); a1 = fmaf(qv.y, kv.y, a1);
                    a1 = fmaf(qv.z, kv.z, a1); a1 = fmaf(qv.w, kv.w, a1);
                }
            }
            if (v0) s0 = a0 * 0.125f;
            if (v1) s1 = a1 * 0.125f;
        }

        float m = fmaxf(s0, s1);
#pragma unroll
        for (int o = 16; o; o >>= 1) m = fmaxf(m, __shfl_xor_sync(0xffffffffu, m, o));
        const float e0 = expf(s0 - m);
        const float e1 = expf(s1 - m);
        float ssum = e0 + e1;
#pragma unroll
        for (int o = 16; o; o >>= 1) ssum += __shfl_xor_sync(0xffffffffu, ssum, o);
        const float inv = 1.0f / ssum;
        ws[wid][lane] = e0 * inv;
        ws[wid][lane + 32] = e1 * inv;
        __syncwarp();

        float a0 = 0.f, a1 = 0.f;
        for (int c2 = 0; c2 < c; c2++) {
            const float wv = ws[wid][c2];
            a0 = fmaf(wv, Vs[c2 * 68 + lane], a0);
            a1 = fmaf(wv, Vs[c2 * 68 + lane + 32], a1);
        }

        const int ch = (h << 6) + lane;
        __nv_bfloat16 h0 = __float2bfloat16(a0);
        __nv_bfloat16 h1 = __float2bfloat16(a1);
        g_AOhi[(size_t)q * 512 + ch]      = h0;
        g_AOhi[(size_t)q * 512 + ch + 32] = h1;
        g_AOlo[(size_t)q * 512 + ch]      = __float2bfloat16(a0 - __bfloat162float(h0));
        g_AOlo[(size_t)q * 512 + ch + 32] = __float2bfloat16(a1 - __bfloat162float(h1));
    }
}

// ---------------- host: tensor-map construction ------------------------------
typedef CUresult (*PFN_encodeTiled)(
    CUtensorMap*, CUtensorMapDataType, cuuint32_t, void*,
    const cuuint64_t*, const cuuint64_t*, const cuuint32_t*, const cuuint32_t*,
    CUtensorMapInterleave, CUtensorMapSwizzle, CUtensorMapL2promotion,
    CUtensorMapFloatOOBfill);

static PFN_encodeTiled get_encoder()
{
    static PFN_encodeTiled fn = nullptr;
    if (!fn) {
        void* p = nullptr;
        cudaDriverEntryPointQueryResult st;
        cudaGetDriverEntryPoint("cuTensorMapEncodeTiled", &p,
                                cudaEnableDefault, &st);
        fn = (PFN_encodeTiled)p;
    }
    return fn;
}

static void make_map(CUtensorMap* m, void* ptr, uint64_t d0, uint64_t d1,
                     uint64_t d2, uint32_t bx, uint32_t by)
{
    cuuint64_t dims[3] = { d0, d1, d2 };
    cuuint64_t strides[2] = { d0 * 2, d0 * d1 * 2 };
    cuuint32_t box[3] = { bx, by, 1 };
    cuuint32_t es[3] = { 1, 1, 1 };
    get_encoder()(m, CU_TENSOR_MAP_DATA_TYPE_BFLOAT16, 3, ptr,
                  dims, strides, box, es,
                  CU_TENSOR_MAP_INTERLEAVE_NONE, CU_TENSOR_MAP_SWIZZLE_128B,
                  CU_TENSOR_MAP_L2_PROMOTION_L2_128B,
                  CU_TENSOR_MAP_FLOAT_OOB_FILL_NONE);
}

// ---------------- launch -----------------------------------------------------
extern "C" void kernel_launch(void* const* d_in, const int* in_sizes, int n_in,
                              void* d_out, int out_size)
{
    const float* query = (const float*)d_in[0];
    const float* key   = (const float*)d_in[1];
    const float* value = (const float*)d_in[2];
    const float* Wq    = (const float*)d_in[3];
    const float* bq    = (const float*)d_in[4];
    const float* Wk    = (const float*)d_in[5];
    const float* bk    = (const float*)d_in[6];
    const float* Wv    = (const float*)d_in[7];
    const float* bv    = (const float*)d_in[8];
    const float* Wo    = (const float*)d_in[9];
    const float* bo    = (const float*)d_in[10];
    float* out = (float*)d_out;

    const int SMEM_GEMM = 1024 + 3 * 65536;   // 197632 bytes
    static int attr_done = 0;
    if (!attr_done) {
        cudaFuncSetAttribute(tc_gemm<0>, cudaFuncAttributeMaxDynamicSharedMemorySize, SMEM_GEMM);
        cudaFuncSetAttribute(tc_gemm<1>, cudaFuncAttributeMaxDynamicSharedMemorySize, SMEM_GEMM);
        attr_done = 1;
    }

    void *p_inhi, *p_inlo, *p_whi, *p_wlo, *p_aohi, *p_aolo;
    cudaGetSymbolAddress(&p_inhi, g_INhi);
    cudaGetSymbolAddress(&p_inlo, g_INlo);
    cudaGetSymbolAddress(&p_whi,  g_Whi);
    cudaGetSymbolAddress(&p_wlo,  g_Wlo);
    cudaGetSymbolAddress(&p_aohi, g_AOhi);
    cudaGetSymbolAddress(&p_aolo, g_AOlo);

    CUtensorMap tInHi, tInLo, tWHi, tWLo, tAoHi, tAoLo;
    make_map(&tInHi, p_inhi, 512, 4096, 3, 64, 128);
    make_map(&tInLo, p_inlo, 512, 4096, 3, 64, 128);
    make_map(&tWHi,  p_whi,  512, 512,  4, 64, 128);
    make_map(&tWLo,  p_wlo,  512, 512,  4, 64, 128);
    make_map(&tAoHi, p_aohi, 512, 4096, 1, 64, 128);
    make_map(&tAoLo, p_aolo, 512, 4096, 1, 64, 128);

    split_all<<<7168, 256>>>(query, key, value, Wq, Wk, Wv, Wo);
    bincoord_kernel<<<dim3(64, 2), 256>>>(query, key, Wq, Wk, bq, bk);
    tc_gemm<0><<<dim3(32, 4, 3), 256, SMEM_GEMM>>>(tInHi, tInLo, tWHi, tWLo,
                                                   bq, bk, bv, nullptr);
    cand_kernel<<<512, 256>>>();
    attn_kernel<<<4096, 256>>>();
    tc_gemm<1><<<dim3(32, 4, 1), 256, SMEM_GEMM>>>(tAoHi, tAoLo, tWHi, tWLo,
                                                   bo, nullptr, nullptr, out);
}

// round 17
// speedup vs baseline: 1.2435x; 1.0123x over previous
#include <cuda_runtime.h>
#include <cuda.h>
#include <cuda_bf16.h>
#include <math.h>
#include <stdint.h>

#define N_TOK   4096
#define D_MODEL 512
#define N_HEADS 8
#define HEAD_DIM 64
#define NBINS_C 512
#define CAND_C  64
#define QCAP    512
#define IN_ELEMS (N_TOK * D_MODEL)
#define W_ELEMS  (D_MODEL * D_MODEL)
#define EPI_STRIDE 132   // multiple of 4 -> float4-aligned rows
#define MASK_WORDS 128   // 4096 keys / 32

// Compile-time feature gate: tcgen05 is only legal in arch-specific passes.
#if defined(__CUDA_ARCH__)
#if defined(__CUDA_ARCH_FEAT_SM103_ALL) || defined(__CUDA_ARCH_FEAT_SM100_ALL)
#define HAS_TCGEN05 1
#elif defined(__CUDA_ARCH_SPECIFIC__) && (__CUDA_ARCH__ >= 1000)
#define HAS_TCGEN05 1
#elif defined(__CUDA_ARCH_FAMILY_SPECIFIC__) && (__CUDA_ARCH__ >= 1000)
#define HAS_TCGEN05 1
#else
#define HAS_TCGEN05 0
#endif
#else
#define HAS_TCGEN05 0
#endif

// ---------------- scratch (device globals: allocation-free) ----------------
static __device__ float g_Q[N_HEADS * N_TOK * HEAD_DIM];   // [h][n][d], projected
static __device__ float g_K[N_HEADS * N_TOK * HEAD_DIM];
static __device__ float g_V[N_HEADS * N_TOK * HEAD_DIM];
static __device__ short g_cand[N_HEADS * NBINS_C * CAND_C];
static __device__ int   g_cnt[N_HEADS * NBINS_C];

// per-(head,bin) key bitmask: bit t of g_mask[(h*512+b)*128 + t/32] set iff
// key t of head h falls in bin b
static __device__ unsigned g_mask[N_HEADS * NBINS_C * MASK_WORDS];

// query buckets per (head, bin)
static __device__ int   g_qcnt[N_HEADS * NBINS_C];
static __device__ short g_qlist[N_HEADS * NBINS_C * QCAP];

// bf16 split operands
static __device__ __align__(1024) __nv_bfloat16 g_INhi[3 * IN_ELEMS];
static __device__ __align__(1024) __nv_bfloat16 g_INlo[3 * IN_ELEMS];
static __device__ __align__(1024) __nv_bfloat16 g_Whi[4 * W_ELEMS];
static __device__ __align__(1024) __nv_bfloat16 g_Wlo[4 * W_ELEMS];
static __device__ __align__(1024) __nv_bfloat16 g_AOhi[IN_ELEMS];
static __device__ __align__(1024) __nv_bfloat16 g_AOlo[IN_ELEMS];

// exact fp32 bin coordinates: [token][2*h + {0,1}]
static __device__ float g_Cq[N_TOK * 16];
static __device__ float g_Ck[N_TOK * 16];

// ---------------- PTX helpers ------------------------------------------------
__device__ __forceinline__ uint32_t smem_u32(const void* p) {
    uint32_t a;
    asm("{ .reg .u64 t; cvta.to.shared.u64 t, %1; cvt.u32.u64 %0, t; }"
        : "=r"(a) : "l"(p));
    return a;
}

#define SW128(x) ((x) ^ (((x) >> 3) & 0x70))

#if HAS_TCGEN05
__device__ __forceinline__ uint32_t elect_one() {
    uint32_t pred;
    asm volatile("{\n\t.reg .pred p;\n\telect.sync _|p, 0xFFFFFFFF;\n\t"
                 "selp.b32 %0, 1, 0, p;\n\t}" : "=r"(pred));
    return pred;
}

#define MBAR_INIT(a, c) \
    asm volatile("mbarrier.init.shared.b64 [%0], %1;" :: "r"(a), "r"(c) : "memory")

#define MBAR_EXPECT_TX(a, bytes) \
    asm volatile("mbarrier.arrive.expect_tx.shared.b64 _, [%0], %1;" \
                 :: "r"(a), "r"(bytes) : "memory")

#define MBAR_WAIT(a, ph) do {                                                   \
    asm volatile("{\n\t.reg .pred P1;\n\t"                                      \
        "WL_%=:\n\t"                                                            \
        "mbarrier.try_wait.parity.acquire.cta.shared::cta.b64 P1, [%0], %1, 0x989680;\n\t" \
        "@P1 bra.uni WD_%=;\n\t"                                                \
        "bra.uni WL_%=;\n\t"                                                    \
        "WD_%=:\n\t}"                                                           \
        :: "r"(a), "r"(ph) : "memory");                                         \
} while (0)

#define TMA3(smem, mapref, x, y, z, mb) \
    asm volatile("cp.async.bulk.tensor.3d.shared::cta.global.tile.mbarrier::complete_tx::bytes " \
        "[%0], [%1, {%2, %3, %4}], [%5];" \
        :: "r"(smem), "l"(&(mapref)), "r"(x), "r"(y), "r"(z), "r"(mb) : "memory")

__device__ __forceinline__ void mma_f16_ss(uint32_t d, uint64_t a, uint64_t b,
                                           uint32_t idesc, uint32_t en) {
    asm volatile("{\n\t.reg .pred p;\n\tsetp.ne.u32 p, %5, 0;\n\t"
        "tcgen05.mma.cta_group::1.kind::f16 [%0], %1, %2, %3, {%4,%4,%4,%4}, p;\n\t}"
        :: "r"(d), "l"(a), "l"(b), "r"(idesc), "r"(0u), "r"(en) : "memory");
}

// SW128 K-major smem descriptor (layout=2, version=1, SBO=64, LBO=1)
__device__ __forceinline__ uint64_t mk_desc(uint32_t addr) {
    const uint64_t base = (uint64_t(2) << 61) | (uint64_t(1) << 46)
                        | (uint64_t(64) << 32) | (uint64_t(1) << 16);
    return base | ((uint64_t)(addr >> 4) & 0x3FFF);
}

// idesc: f32 accum, bf16 a/b, M=128, N=128
#define IDESC_F16_128x128 0x8200490u

#define LDTM32(R, addr)                                                        \
    do {                                                                       \
        asm volatile(                                                          \
            "tcgen05.ld.sync.aligned.32x32b.x32.b32 "                          \
            "{%0,%1,%2,%3,%4,%5,%6,%7,%8,%9,%10,%11,%12,%13,%14,%15,"          \
            "%16,%17,%18,%19,%20,%21,%22,%23,%24,%25,%26,%27,%28,%29,%30,%31}, [%32];" \
            : "=r"((R)[0]), "=r"((R)[1]), "=r"((R)[2]), "=r"((R)[3]),          \
              "=r"((R)[4]), "=r"((R)[5]), "=r"((R)[6]), "=r"((R)[7]),          \
              "=r"((R)[8]), "=r"((R)[9]), "=r"((R)[10]), "=r"((R)[11]),        \
              "=r"((R)[12]), "=r"((R)[13]), "=r"((R)[14]), "=r"((R)[15]),      \
              "=r"((R)[16]), "=r"((R)[17]), "=r"((R)[18]), "=r"((R)[19]),      \
              "=r"((R)[20]), "=r"((R)[21]), "=r"((R)[22]), "=r"((R)[23]),      \
              "=r"((R)[24]), "=r"((R)[25]), "=r"((R)[26]), "=r"((R)[27]),      \
              "=r"((R)[28]), "=r"((R)[29]), "=r"((R)[30]), "=r"((R)[31])       \
            : "r"(addr));                                                      \
        asm volatile("tcgen05.wait::ld.sync.aligned;" ::: "memory");           \
    } while (0)
#else
// ---- legacy mma.sync helpers (fallback path) ----
#define LDSM4(R, ptr) do {                                                     \
    unsigned _a = (unsigned)__cvta_generic_to_shared(ptr);                     \
    asm volatile("ldmatrix.sync.aligned.m8n8.x4.shared.b16 {%0,%1,%2,%3}, [%4];" \
        : "=r"((R)[0]), "=r"((R)[1]), "=r"((R)[2]), "=r"((R)[3]) : "r"(_a));   \
} while (0)

#define MMA16816(C, A, B0, B1)                                                 \
    asm volatile("mma.sync.aligned.m16n8k16.row.col.f32.bf16.bf16.f32 "       \
        "{%0,%1,%2,%3},{%4,%5,%6,%7},{%8,%9},{%0,%1,%2,%3};"                  \
        : "+f"((C)[0]), "+f"((C)[1]), "+f"((C)[2]), "+f"((C)[3])              \
        : "r"((A)[0]), "r"((A)[1]), "r"((A)[2]), "r"((A)[3]),                 \
          "r"(B0), "r"(B1))
#endif

// ---------------- merged split fp32 -> bf16 hi/lo (+ scratch zeroing) --------
__global__ __launch_bounds__(256)
void split_all(const float* __restrict__ q, const float* __restrict__ k,
               const float* __restrict__ v, const float* __restrict__ wq,
               const float* __restrict__ wk, const float* __restrict__ wv,
               const float* __restrict__ wo)
{
    const int bid = blockIdx.x;
    if (bid < 16) g_qcnt[bid * 256 + threadIdx.x] = 0;   // fused zero_qcnt
    if (bid < 2048) g_mask[bid * 256 + threadIdx.x] = 0; // fused mask zeroing
    const float* src;
    __nv_bfloat16 *hi, *lo;
    int i4;
    if (bid < 6144) {
        const int z = bid >> 11;
        src = (z == 0) ? q : (z == 1) ? k : v;
        hi = g_INhi + (size_t)z * IN_ELEMS;
        lo = g_INlo + (size_t)z * IN_ELEMS;
        i4 = (bid & 2047) * 256 + threadIdx.x;
    } else {
        const int z = (bid - 6144) >> 8;
        src = (z == 0) ? wq : (z == 1) ? wk : (z == 2) ? wv : wo;
        hi = g_Whi + (size_t)z * W_ELEMS;
        lo = g_Wlo + (size_t)z * W_ELEMS;
        i4 = ((bid - 6144) & 255) * 256 + threadIdx.x;
    }
    float4 val = ((const float4*)src)[i4];
    __nv_bfloat16 h0 = __float2bfloat16(val.x);
    __nv_bfloat16 h1 = __float2bfloat16(val.y);
    __nv_bfloat16 h2 = __float2bfloat16(val.z);
    __nv_bfloat16 h3 = __float2bfloat16(val.w);
    __nv_bfloat16 l0 = __float2bfloat16(val.x - __bfloat162float(h0));
    __nv_bfloat16 l1 = __float2bfloat16(val.y - __bfloat162float(h1));
    __nv_bfloat16 l2 = __float2bfloat16(val.z - __bfloat162float(h2));
    __nv_bfloat16 l3 = __float2bfloat16(val.w - __bfloat162float(h3));
    uint2 hp, lp;
    hp.x = (unsigned)__bfloat16_as_ushort(h0) | ((unsigned)__bfloat16_as_ushort(h1) << 16);
    hp.y = (unsigned)__bfloat16_as_ushort(h2) | ((unsigned)__bfloat16_as_ushort(h3) << 16);
    lp.x = (unsigned)__bfloat16_as_ushort(l0) | ((unsigned)__bfloat16_as_ushort(l1) << 16);
    lp.y = (unsigned)__bfloat16_as_ushort(l2) | ((unsigned)__bfloat16_as_ushort(l3) << 16);
    *(uint2*)(hi + 4 * (size_t)i4) = hp;
    *(uint2*)(lo + 4 * (size_t)i4) = lp;
}

// ---------------- exact fp32 bin-coordinate GEMM -----------------------------
__global__ __launch_bounds__(256)
void bincoord_kernel(const float* __restrict__ q, const float* __restrict__ k,
                     const float* __restrict__ Wq, const float* __restrict__ Wk,
                     const float* __restrict__ bq, const float* __restrict__ bk)
{
    __shared__ float Ws[16][512];
    __shared__ float bs[16];
    const int z = blockIdx.y;
    const float* A = z ? k : q;
    const float* W = z ? Wk : Wq;
    const float* bias = z ? bk : bq;
    float* out = z ? g_Ck : g_Cq;

    for (int i = threadIdx.x; i < 16 * 512; i += 256) {
        int j = i >> 9, kk = i & 511;
        int wrow = (j >> 1) * 64 + (j & 1);
        Ws[j][kk] = W[(size_t)wrow * 512 + kk];
    }
    if (threadIdx.x < 16) {
        int j = threadIdx.x;
        bs[j] = bias[(j >> 1) * 64 + (j & 1)];
    }
    __syncthreads();

    const int tl = threadIdx.x >> 2;
    const int jg = (threadIdx.x & 3) * 4;
    const int token = blockIdx.x * 64 + tl;
    float acc[4] = { 0.f, 0.f, 0.f, 0.f };
    const float4* Ar = (const float4*)(A + (size_t)token * 512);
    for (int kk = 0; kk < 128; kk++) {
        float4 a = Ar[kk];
#pragma unroll
        for (int j = 0; j < 4; j++) {
            acc[j] = fmaf(a.x, Ws[jg + j][4 * kk + 0], acc[j]);
            acc[j] = fmaf(a.y, Ws[jg + j][4 * kk + 1], acc[j]);
            acc[j] = fmaf(a.z, Ws[jg + j][4 * kk + 2], acc[j]);
            acc[j] = fmaf(a.w, Ws[jg + j][4 * kk + 3], acc[j]);
        }
    }
#pragma unroll
    for (int j = 0; j < 4; j++)
        out[(size_t)token * 16 + jg + j] = acc[j] + bs[jg + j];
}

// ---------------- GEMM: C = A*W^T + bias (3-term bf16 split) ----------------
// tcgen05 + TMA, depth-3 pipeline (M=128, N=128, K chunks of 64).
// MODE 0 fuses bias + Poincare scale + binning in registers during the TMEM
// drain; z==0 buckets queries, z==1 sets the per-(head,bin) key bitmask.
template <int MODE>
__global__ __launch_bounds__(256)
void tc_gemm(const __grid_constant__ CUtensorMap tAhi,
             const __grid_constant__ CUtensorMap tAlo,
             const __grid_constant__ CUtensorMap tWhi,
             const __grid_constant__ CUtensorMap tWlo,
             const float* __restrict__ b0, const float* __restrict__ b1,
             const float* __restrict__ b2, float* __restrict__ outp)
{
    extern __shared__ __align__(1024) char smem[];
    const int tid = threadIdx.x;
    const int wid = tid >> 5;
    const int lid = tid & 31;

    const int z = blockIdx.z;
    const float* bias;
    float* outQ;
    if (MODE == 0) {
        bias = (z == 0) ? b0 : (z == 1) ? b1 : b2;
        outQ = (z == 0) ? g_Q : (z == 1) ? g_K : g_V;
    } else {
        bias = b0;
        outQ = outp;
    }
    const int m0 = blockIdx.x * 128;
    const int n0 = blockIdx.y * 128;

#if HAS_TCGEN05
    const int zA = (MODE == 0) ? z : 0;
    const int zW = (MODE == 0) ? z : 3;
    const uint32_t sb = smem_u32(smem);
    const uint32_t bufB = sb + 1024;

    if (wid == 0) {
        asm volatile("tcgen05.alloc.cta_group::1.sync.aligned.shared::cta.b32 [%0], %1;"
                     :: "r"(sb), "r"(128u) : "memory");
        asm volatile("tcgen05.relinquish_alloc_permit.cta_group::1.sync.aligned;");
    }
    if (tid == 0) {
        MBAR_INIT(sb + 8, 1);  MBAR_INIT(sb + 16, 1); MBAR_INIT(sb + 24, 1); // data
        MBAR_INIT(sb + 32, 1); MBAR_INIT(sb + 40, 1); MBAR_INIT(sb + 48, 1); // mma
    }
    __syncthreads();
    uint32_t tmem;
    asm volatile("ld.shared.b32 %0, [%1];" : "=r"(tmem) : "r"(sb));

    if (wid == 0 && elect_one()) {
        const uint32_t dmb[3] = { sb + 8, sb + 16, sb + 24 };
        const uint32_t mmb[3] = { sb + 32, sb + 40, sb + 48 };

        auto stage = [&](int b, int chunk) {
            const uint32_t bb = bufB + (uint32_t)b * 65536;
            MBAR_EXPECT_TX(dmb[b], 65536u);
            TMA3(bb,         tAhi, chunk * 64, m0, zA, dmb[b]);
            TMA3(bb + 16384, tAlo, chunk * 64, m0, zA, dmb[b]);
            TMA3(bb + 32768, tWhi, chunk * 64, n0, zW, dmb[b]);
            TMA3(bb + 49152, tWlo, chunk * 64, n0, zW, dmb[b]);
        };

        stage(0, 0);
        stage(1, 1);
        stage(2, 2);
        int dph[3] = {0, 0, 0}, mph[3] = {0, 0, 0};

        for (int c = 0; c < 8; c++) {
            const int b = c % 3;
            MBAR_WAIT(dmb[b], dph[b]); dph[b] ^= 1;
            const uint32_t bb = bufB + (uint32_t)b * 65536;
            const uint64_t dAh = mk_desc(bb);
            const uint64_t dAl = mk_desc(bb + 16384);
            const uint64_t dBh = mk_desc(bb + 32768);
            const uint64_t dBl = mk_desc(bb + 49152);
#pragma unroll
            for (int k16 = 0; k16 < 4; k16++) {
                const uint64_t o = k16 * 2;
                mma_f16_ss(tmem, dAh + o, dBh + o, IDESC_F16_128x128,
                           (c == 0 && k16 == 0) ? 0u : 1u);
                mma_f16_ss(tmem, dAh + o, dBl + o, IDESC_F16_128x128, 1u);
                mma_f16_ss(tmem, dAl + o, dBh + o, IDESC_F16_128x128, 1u);
            }
            asm volatile(
                "tcgen05.commit.cta_group::1.mbarrier::arrive::one.shared::cluster.b64 [%0];"
                :: "r"(mmb[b]) : "memory");
            if (c >= 1 && c + 2 < 8) {
                const int pb = (c - 1) % 3;
                MBAR_WAIT(mmb[pb], mph[pb]); mph[pb] ^= 1;
                stage(pb, c + 2);
            }
        }
        MBAR_WAIT(mmb[2], mph[2]); mph[2] ^= 1;
        MBAR_WAIT(mmb[0], mph[0]); mph[0] ^= 1;
        MBAR_WAIT(mmb[1], mph[1]); mph[1] ^= 1;
    }
    __syncthreads();
    asm volatile("tcgen05.fence::after_thread_sync;" ::: "memory");

    // ---- epilogue pass 1: TMEM drain + (MODE 0) fused bias/scale/bin -------
    float* sT = (float*)(smem + 1024);
    {
        const int trow = (wid & 3) * 32 + lid;        // tile row (token)
        const int hh = wid >> 2;                      // head half of tile
        const int cbase = hh * 64;

        if (MODE == 0) {
            float va[64];
            float ss = 0.f;
#pragma unroll
            for (int cb = 0; cb < 64; cb += 32) {
                uint32_t r[32];
                LDTM32(r, tmem + cbase + cb);
#pragma unroll
                for (int j4 = 0; j4 < 8; j4++) {
                    const float4 b4 =
                        *(const float4*)&bias[n0 + cbase + cb + j4 * 4];
                    float* vp = &va[cb + j4 * 4];
                    vp[0] = __uint_as_float(r[j4 * 4 + 0]) + b4.x;
                    vp[1] = __uint_as_float(r[j4 * 4 + 1]) + b4.y;
                    vp[2] = __uint_as_float(r[j4 * 4 + 2]) + b4.z;
                    vp[3] = __uint_as_float(r[j4 * 4 + 3]) + b4.w;
                    if (z < 2) {
                        ss = fmaf(vp[0], vp[0], ss); ss = fmaf(vp[1], vp[1], ss);
                        ss = fmaf(vp[2], vp[2], ss); ss = fmaf(vp[3], vp[3], ss);
                    }
                }
            }
            if (z < 2) {
                const float nrm = sqrtf(ss);
                const float s = fminf(1.0f, 0.99999f / fmaxf(nrm, 1e-12f));
#pragma unroll
                for (int j = 0; j < 64; j++) va[j] *= s;

                const int gh = (n0 >> 6) + hh;
                const int token = m0 + trow;
                const float* C = (z == 0) ? g_Cq : g_Ck;
                const float c0 = C[(size_t)token * 16 + 2 * gh];
                const float c1 = C[(size_t)token * 16 + 2 * gh + 1];
                float ang = atan2f(c1, c0);
                float t = (ang / 6.28318530717958647692f + 0.5f) * 512.0f;
                if (fabsf(t - rintf(t)) < 4e-3f) {
                    ang = (float)atan2((double)c1, (double)c0);
                    t = (ang / 6.28318530717958647692f + 0.5f) * 512.0f;
                }
                int b = (int)floorf(t);
                b = (b < 0) ? 0 : ((b > NBINS_C - 1) ? NBINS_C - 1 : b);
                if (z == 0) {
                    const int hb = (gh << 9) + b;
                    const int idx = atomicAdd(&g_qcnt[hb], 1);
                    if (idx < QCAP) g_qlist[(size_t)hb * QCAP + idx] = (short)token;
                } else {
                    atomicOr(&g_mask[((size_t)((gh << 9) + b)) * MASK_WORDS
                                     + (token >> 5)], 1u << (token & 31));
                }
            }
#pragma unroll
            for (int j = 0; j < 64; j++)
                sT[trow * EPI_STRIDE + cbase + j] = va[j];
        } else {
#pragma unroll
            for (int cb = 0; cb < 64; cb += 32) {
                uint32_t r[32];
                LDTM32(r, tmem + cbase + cb);
#pragma unroll
                for (int j = 0; j < 32; j++)
                    sT[trow * EPI_STRIDE + cbase + cb + j] = __uint_as_float(r[j]);
            }
        }
    }
    __syncthreads();

    // ---- pass 3: coalesced float4 stores (bias already applied for MODE 0) --
    for (int i = tid; i < 128 * 32; i += 256) {
        const int row = i >> 5;
        const int col = (i & 31) * 4;
        float4 v = *(float4*)&sT[row * EPI_STRIDE + col];
        const int gcol = n0 + col;
        if (MODE == 1) {
            const float4 bb4 = *(const float4*)&bias[gcol];
            v.x += bb4.x; v.y += bb4.y; v.z += bb4.z; v.w += bb4.w;
            *(float4*)&outQ[(size_t)(m0 + row) * 512 + gcol] = v;
        } else {
            const int h = gcol >> 6, dd = gcol & 63;
            *(float4*)&outQ[((size_t)((h << 12) + m0 + row)) * 64 + dd] = v;
        }
    }
    __syncthreads();
    if (wid == 0) {
        asm volatile("tcgen05.dealloc.cta_group::1.sync.aligned.b32 %0, %1;"
                     :: "r"(tmem), "r"(128u));
    }
#else
    // ---- fallback: mma.sync path (compile-completeness only) ----
    const __nv_bfloat16 *Ahi, *Alo, *Whi, *Wlo;
    if (MODE == 0) {
        Ahi = g_INhi + (size_t)z * IN_ELEMS;
        Alo = g_INlo + (size_t)z * IN_ELEMS;
        Whi = g_Whi + (size_t)z * W_ELEMS;
        Wlo = g_Wlo + (size_t)z * W_ELEMS;
    } else {
        Ahi = g_AOhi; Alo = g_AOlo;
        Whi = g_Whi + (size_t)3 * W_ELEMS;
        Wlo = g_Wlo + (size_t)3 * W_ELEMS;
    }
    unsigned short* As = (unsigned short*)smem;
    unsigned short* Bs = (unsigned short*)(smem + 16384);
    const int wm = wid >> 1;
    const int wn = wid & 1;

    float acc[2][8][4];
#pragma unroll
    for (int a = 0; a < 2; a++)
#pragma unroll
        for (int b = 0; b < 8; b++)
#pragma unroll
            for (int c = 0; c < 4; c++) acc[a][b][c] = 0.f;

    for (int kt = 0; kt < D_MODEL; kt += 32) {
#pragma unroll
        for (int i = 0; i < 8; i++) {
            const int cid = tid + i * 256;
            const int which = cid >> 9;
            const int r = (cid >> 2) & 127;
            const int kc = cid & 3;
            const __nv_bfloat16* base =
                (which == 0) ? Ahi : (which == 1) ? Alo : (which == 2) ? Whi : Wlo;
            const int grow = ((which < 2) ? m0 : n0) + r;
            uint4 v = *(const uint4*)(base + (size_t)grow * 512 + kt + kc * 8);
            unsigned short* db = (which < 2) ? As : Bs;
            const int sc = (kc + ((which & 1) << 2)) ^ (r & 7);
            *(uint4*)(db + r * 64 + sc * 8) = v;
        }
        __syncthreads();

#pragma unroll
        for (int k16 = 0; k16 < 2; k16++) {
            unsigned ah[2][4], al[2][4], bh[4][4], bl[4][4];
#pragma unroll
            for (int mi = 0; mi < 2; mi++) {
                const int r = wm * 32 + mi * 16 + (lid & 15);
                const int kc = 2 * k16 + (lid >> 4);
                LDSM4(ah[mi], As + r * 64 + ((kc) ^ (r & 7)) * 8);
                LDSM4(al[mi], As + r * 64 + ((kc + 4) ^ (r & 7)) * 8);
            }
#pragma unroll
            for (int p = 0; p < 4; p++) {
                const int r = wn * 64 + p * 16 + ((lid >> 4) << 3) + (lid & 7);
                const int kc = 2 * k16 + ((lid >> 3) & 1);
                LDSM4(bh[p], Bs + r * 64 + ((kc) ^ (r & 7)) * 8);
                LDSM4(bl[p], Bs + r * 64 + ((kc + 4) ^ (r & 7)) * 8);
            }
#pragma unroll
            for (int mi = 0; mi < 2; mi++)
#pragma unroll
                for (int nj = 0; nj < 8; nj++) {
                    const int p = nj >> 1, o = (nj & 1) * 2;
                    MMA16816(acc[mi][nj], ah[mi], bh[p][o], bh[p][o + 1]);
                    MMA16816(acc[mi][nj], ah[mi], bl[p][o], bl[p][o + 1]);
                    MMA16816(acc[mi][nj], al[mi], bh[p][o], bh[p][o + 1]);
                }
        }
        __syncthreads();
    }

#pragma unroll
    for (int mi = 0; mi < 2; mi++)
#pragma unroll
        for (int nj = 0; nj < 8; nj++) {
            const int row = m0 + wm * 32 + mi * 16 + (lid >> 2);
            const int col = n0 + wn * 64 + nj * 8 + (lid & 3) * 2;
            const float bx = bias[col], by = bias[col + 1];
            float2 v0 = make_float2(acc[mi][nj][0] + bx, acc[mi][nj][1] + by);
            float2 v1 = make_float2(acc[mi][nj][2] + bx, acc[mi][nj][3] + by);
            if (MODE == 0) {
                const int h = col >> 6, d = col & 63;
                *(float2*)&outQ[((size_t)((h << 12) + row)) * 64 + d] = v0;
                *(float2*)&outQ[((size_t)((h << 12) + row + 8)) * 64 + d] = v1;
            } else {
                *(float2*)&outQ[(size_t)row * 512 + col] = v0;
                *(float2*)&outQ[(size_t)(row + 8) * 512 + col] = v1;
            }
        }
#endif
}

// ---------------- candidate lists per (head, bin) ---------------------------
// Mask-based: candidate set of bin b = mask[b-1] | mask[b] | mask[b+1].
// Each warp: 3 coalesced uint4 loads, OR, popc + warp scan + bit-extract.
// Output identical to the ballot-based versions.
__global__ __launch_bounds__(256)
void cand_kernel()
{
    const int h    = blockIdx.x >> 6;          // 64 blocks per head
    const int bin0 = (blockIdx.x & 63) * 8;
    const int warp = threadIdx.x >> 5;         // 0..7
    const int lane = threadIdx.x & 31;
    const int b = bin0 + warp;
    short* dst = g_cand + ((size_t)h * NBINS_C + b) * CAND_C;

    const unsigned* mb = g_mask + (size_t)(h << 9) * MASK_WORDS;
    uint4 m1 = ((const uint4*)(mb + (size_t)b * MASK_WORDS))[lane];
    if (b > 0) {
        const uint4 m0v = ((const uint4*)(mb + (size_t)(b - 1) * MASK_WORDS))[lane];
        m1.x |= m0v.x; m1.y |= m0v.y; m1.z |= m0v.z; m1.w |= m0v.w;
    }
    if (b < NBINS_C - 1) {
        const uint4 m2 = ((const uint4*)(mb + (size_t)(b + 1) * MASK_WORDS))[lane];
        m1.x |= m2.x; m1.y |= m2.y; m1.z |= m2.z; m1.w |= m2.w;
    }
    unsigned ws[4] = { m1.x, m1.y, m1.z, m1.w };

    const int myc = __popc(ws[0]) + __popc(ws[1]) + __popc(ws[2]) + __popc(ws[3]);
    int ex = myc;
#pragma unroll
    for (int o = 1; o < 32; o <<= 1) {
        const int v = __shfl_up_sync(0xffffffffu, ex, o);
        if (lane >= o) ex += v;
    }
    const int total = __shfl_sync(0xffffffffu, ex, 31);
    ex -= myc;  // exclusive prefix

    if (ex < CAND_C && myc > 0) {
        int base = ex;
#pragma unroll
        for (int i = 0; i < 4; i++) {
            unsigned word = ws[i];
            const int k0 = (lane * 4 + i) * 32;
            while (word && base < CAND_C) {
                const int bit = __ffs(word) - 1;
                dst[base] = (short)(k0 + bit);
                word &= word - 1;
                base++;
            }
        }
    }
    if (lane == 0)
        g_cnt[h * NBINS_C + b] = (total > CAND_C) ? CAND_C : total;
}

// ---------------- bucketed sparse attention ----------------------------------
__global__ __launch_bounds__(256)
void attn_kernel()
{
    __shared__ float Ks[CAND_C * 68];
    __shared__ float Vs[CAND_C * 68];
    __shared__ float qs[8][64];
    __shared__ float ws[8][64];
    __shared__ short cl[CAND_C];

    const int hb = blockIdx.x;
    int nq = g_qcnt[hb];
    if (nq == 0) return;
    if (nq > QCAP) nq = QCAP;

    const int h = hb >> 9;
    const int tid = threadIdx.x;
    const int wid = tid >> 5;
    const int lane = tid & 31;

    const int cnt = g_cnt[hb];
    const int c = (cnt == 0) ? CAND_C : cnt;
    if (tid < CAND_C) {
        short v = (short)tid;
        if (cnt > 0) v = (tid < cnt) ? g_cand[(size_t)hb * CAND_C + tid] : (short)0;
        cl[tid] = v;
    }
    __syncthreads();

    for (int i = tid; i < c * 16; i += 256) {
        const int r = i >> 4, seg = i & 15;
        const size_t gro = ((size_t)(h << 12) + cl[r]) * 64 + seg * 4;
        *(float4*)&Ks[r * 68 + seg * 4] = *(const float4*)&g_K[gro];
        *(float4*)&Vs[r * 68 + seg * 4] = *(const float4*)&g_V[gro];
    }
    __syncthreads();

    for (int qi = wid; qi < nq; qi += 8) {
        const int q = (int)g_qlist[(size_t)hb * QCAP + qi];
        const float* qrow = g_Q + ((size_t)(h << 12) + q) * 64;
        qs[wid][lane] = qrow[lane];
        qs[wid][lane + 32] = qrow[lane + 32];
        __syncwarp();

        float s0 = -INFINITY, s1 = -INFINITY;
        {
            float a0 = 0.f, a1 = 0.f;
            const bool v0 = (lane < c), v1 = (lane + 32 < c);
#pragma unroll
            for (int d4 = 0; d4 < 16; d4++) {
                const float4 qv = *(const float4*)&qs[wid][d4 * 4];
                if (v0) {
                    const float4 kv = *(const float4*)&Ks[lane * 68 + d4 * 4];
                    a0 = fmaf(qv.x, kv.x, a0); a0 = fmaf(qv.y, kv.y, a0);
                    a0 = fmaf(qv.z, kv.z, a0); a0 = fmaf(qv.w, kv.w, a0);
                }
                if (v1) {
                    const float4 kv = *(const float4*)&Ks[(lane + 32) * 68 + d4 * 4];
                    a1 = fmaf(qv.x, kv.x, a1); a1 = fmaf(qv.y, kv.y, a1);
                    a1 = fmaf(qv.z, kv.z, a1); a1 = fmaf(qv.w, kv.w, a1);
                }
            }
            if (v0) s0 = a0 * 0.125f;
            if (v1) s1 = a1 * 0.125f;
        }

        float m = fmaxf(s0, s1);
#pragma unroll
        for (int o = 16; o; o >>= 1) m = fmaxf(m, __shfl_xor_sync(0xffffffffu, m, o));
        const float e0 = expf(s0 - m);
        const float e1 = expf(s1 - m);
        float ssum = e0 + e1;
#pragma unroll
        for (int o = 16; o; o >>= 1) ssum += __shfl_xor_sync(0xffffffffu, ssum, o);
        const float inv = 1.0f / ssum;
        ws[wid][lane] = e0 * inv;
        ws[wid][lane + 32] = e1 * inv;
        __syncwarp();

        float a0 = 0.f, a1 = 0.f;
        for (int c2 = 0; c2 < c; c2++) {
            const float wv = ws[wid][c2];
            a0 = fmaf(wv, Vs[c2 * 68 + lane], a0);
            a1 = fmaf(wv, Vs[c2 * 68 + lane + 32], a1);
        }

        const int ch = (h << 6) + lane;
        __nv_bfloat16 h0 = __float2bfloat16(a0);
        __nv_bfloat16 h1 = __float2bfloat16(a1);
        g_AOhi[(size_t)q * 512 + ch]      = h0;
        g_AOhi[(size_t)q * 512 + ch + 32] = h1;
        g_AOlo[(size_t)q * 512 + ch]      = __float2bfloat16(a0 - __bfloat162float(h0));
        g_AOlo[(size_t)q * 512 + ch + 32] = __float2bfloat16(a1 - __bfloat162float(h1));
    }
}

// ---------------- host: tensor-map construction ------------------------------
typedef CUresult (*PFN_encodeTiled)(
    CUtensorMap*, CUtensorMapDataType, cuuint32_t, void*,
    const cuuint64_t*, const cuuint64_t*, const cuuint32_t*, const cuuint32_t*,
    CUtensorMapInterleave, CUtensorMapSwizzle, CUtensorMapL2promotion,
    CUtensorMapFloatOOBfill);

static PFN_encodeTiled get_encoder()
{
    static PFN_encodeTiled fn = nullptr;
    if (!fn) {
        void* p = nullptr;
        cudaDriverEntryPointQueryResult st;
        cudaGetDriverEntryPoint("cuTensorMapEncodeTiled", &p,
                                cudaEnableDefault, &st);
        fn = (PFN_encodeTiled)p;
    }
    return fn;
}

static void make_map(CUtensorMap* m, void* ptr, uint64_t d0, uint64_t d1,
                     uint64_t d2, uint32_t bx, uint32_t by)
{
    cuuint64_t dims[3] = { d0, d1, d2 };
    cuuint64_t strides[2] = { d0 * 2, d0 * d1 * 2 };
    cuuint32_t box[3] = { bx, by, 1 };
    cuuint32_t es[3] = { 1, 1, 1 };
    get_encoder()(m, CU_TENSOR_MAP_DATA_TYPE_BFLOAT16, 3, ptr,
                  dims, strides, box, es,
                  CU_TENSOR_MAP_INTERLEAVE_NONE, CU_TENSOR_MAP_SWIZZLE_128B,
                  CU_TENSOR_MAP_L2_PROMOTION_L2_128B,
                  CU_TENSOR_MAP_FLOAT_OOB_FILL_NONE);
}

// ---------------- launch -----------------------------------------------------
extern "C" void kernel_launch(void* const* d_in, const int* in_sizes, int n_in,
                              void* d_out, int out_size)
{
    const float* query = (const float*)d_in[0];
    const float* key   = (const float*)d_in[1];
    const float* value = (const float*)d_in[2];
    const float* Wq    = (const float*)d_in[3];
    const float* bq    = (const float*)d_in[4];
    const float* Wk    = (const float*)d_in[5];
    const float* bk    = (const float*)d_in[6];
    const float* Wv    = (const float*)d_in[7];
    const float* bv    = (const float*)d_in[8];
    const float* Wo    = (const float*)d_in[9];
    const float* bo    = (const float*)d_in[10];
    float* out = (float*)d_out;

    const int SMEM_GEMM = 1024 + 3 * 65536;   // 197632 bytes
    static int attr_done = 0;
    if (!attr_done) {
        cudaFuncSetAttribute(tc_gemm<0>, cudaFuncAttributeMaxDynamicSharedMemorySize, SMEM_GEMM);
        cudaFuncSetAttribute(tc_gemm<1>, cudaFuncAttributeMaxDynamicSharedMemorySize, SMEM_GEMM);
        attr_done = 1;
    }

    void *p_inhi, *p_inlo, *p_whi, *p_wlo, *p_aohi, *p_aolo;
    cudaGetSymbolAddress(&p_inhi, g_INhi);
    cudaGetSymbolAddress(&p_inlo, g_INlo);
    cudaGetSymbolAddress(&p_whi,  g_Whi);
    cudaGetSymbolAddress(&p_wlo,  g_Wlo);
    cudaGetSymbolAddress(&p_aohi, g_AOhi);
    cudaGetSymbolAddress(&p_aolo, g_AOlo);

    CUtensorMap tInHi, tInLo, tWHi, tWLo, tAoHi, tAoLo;
    make_map(&tInHi, p_inhi, 512, 4096, 3, 64, 128);
    make_map(&tInLo, p_inlo, 512, 4096, 3, 64, 128);
    make_map(&tWHi,  p_whi,  512, 512,  4, 64, 128);
    make_map(&tWLo,  p_wlo,  512, 512,  4, 64, 128);
    make_map(&tAoHi, p_aohi, 512, 4096, 1, 64, 128);
    make_map(&tAoLo, p_aolo, 512, 4096, 1, 64, 128);

    split_all<<<7168, 256>>>(query, key, value, Wq, Wk, Wv, Wo);
    bincoord_kernel<<<dim3(64, 2), 256>>>(query, key, Wq, Wk, bq, bk);
    tc_gemm<0><<<dim3(32, 4, 3), 256, SMEM_GEMM>>>(tInHi, tInLo, tWHi, tWLo,
                                                   bq, bk, bv, nullptr);
    cand_kernel<<<512, 256>>>();
    attn_kernel<<<4096, 256>>>();
    tc_gemm<1><<<dim3(32, 4, 1), 256, SMEM_GEMM>>>(tAoHi, tAoLo, tWHi, tWLo,
                                                   bo, nullptr, nullptr, out);
}